// round 1
// baseline (speedup 1.0000x reference)
#include <cuda_runtime.h>
#include <math.h>

#define EN 384
#define HIDN 128
#define NHEAD 8
#define DHEAD 16
#define NRBF 64

static constexpr int SW = 132;     // smem row stride (floats), 16B-aligned, conflict-mitigating
static constexpr int SMEM_BYTES = (3 * 128 * SW + 256) * 4;

// ---------------- device scratch (no runtime allocation allowed) ----------------
__device__ float g_q[EN * HIDN];
__device__ float g_k[EN * HIDN];
__device__ float g_v[EN * HIDN];
__device__ float g_Aq[NHEAD * EN * HIDN];
__device__ float g_Ak[NHEAD * EN * HIDN];
__device__ float g_gates[NHEAD * EN];
__device__ float g_scores[NHEAD * EN * EN];
__device__ float g_upd[EN * HIDN];
__device__ float g_delta[NHEAD * EN * 3];

__device__ __forceinline__ float siluf(float x) { return x / (1.0f + __expf(-x)); }

// ---------------- K0: q,k,v projections ----------------
__global__ void k_qkv(const float* __restrict__ ef, const float* __restrict__ wq,
                      const float* __restrict__ wk, const float* __restrict__ wv) {
    __shared__ float row[HIDN];
    int i = blockIdx.x;
    int n = threadIdx.x;
    row[n] = ef[i * HIDN + n];
    __syncthreads();
    const float* W = (blockIdx.y == 0) ? wq : ((blockIdx.y == 1) ? wk : wv);
    float* O = (blockIdx.y == 0) ? g_q : ((blockIdx.y == 1) ? g_k : g_v);
    float acc = 0.f;
#pragma unroll 8
    for (int c = 0; c < HIDN; c++) acc += row[c] * W[c * HIDN + n];
    O[i * HIDN + n] = acc;
}

// ---------------- K0b: Aq[h,i,:] = q[i,h,:] @ W1_q ; Ak similarly ----------------
__global__ void k_aqak(const float* __restrict__ w1) {
    __shared__ float row[HIDN];
    int i = blockIdx.x;
    int n = threadIdx.x;
    int sel = blockIdx.y;                  // 0: q, 1: k
    const float* src = sel ? g_k : g_q;
    float* dst = sel ? g_Ak : g_Aq;
    int roff = sel ? DHEAD : 0;
    row[n] = src[i * HIDN + n];
    __syncthreads();
    for (int h = 0; h < NHEAD; h++) {
        float acc = 0.f;
#pragma unroll
        for (int d = 0; d < DHEAD; d++)
            acc += row[h * DHEAD + d] * w1[(roff + d) * HIDN + n];
        dst[(h * EN + i) * HIDN + n] = acc;
    }
}

// ---------------- K0c: gates[h,j] = sigmoid(silu(v[j,h]@g_w1+b1)@g_w2+b2) ----------------
__global__ void k_gates(const float* __restrict__ gw1, const float* __restrict__ gb1,
                        const float* __restrict__ gw2, const float* __restrict__ gb2) {
    __shared__ float vrow[DHEAD];
    __shared__ float red[HIDN];
    int j = blockIdx.x, h = blockIdx.y, n = threadIdx.x;
    if (n < DHEAD) vrow[n] = g_v[j * HIDN + h * DHEAD + n];
    __syncthreads();
    float acc = gb1[n];
#pragma unroll
    for (int d = 0; d < DHEAD; d++) acc += vrow[d] * gw1[d * HIDN + n];
    red[n] = siluf(acc) * gw2[n];
    __syncthreads();
    for (int s = 64; s > 0; s >>= 1) {
        if (n < s) red[n] += red[n + s];
        __syncthreads();
    }
    if (n == 0) g_gates[h * EN + j] = 1.0f / (1.0f + __expf(-(red[0] + gb2[0])));
}

// ---------------- K1: fused pair-MLP -> attention scores ----------------
// CTA tile: 16 i's x 8 j's = 128 pairs. Thread grid 16(tx: hidden n) x 16(ty: pair group).
// Register tile: 8 pairs x 8 n per thread.
__device__ __forceinline__ void gemm_tile(const float* __restrict__ A,
                                          const float* __restrict__ B, int K, int ty,
                                          int tx, float acc[8][8]) {
#pragma unroll 1
    for (int c = 0; c < K; c++) {
        const float* ar = A + c * SW + ty * 8;
        const float* br = B + c * SW + tx * 8;
        float4 a0 = *(const float4*)(ar);
        float4 a1 = *(const float4*)(ar + 4);
        float4 b0 = *(const float4*)(br);
        float4 b1 = *(const float4*)(br + 4);
        float av[8] = {a0.x, a0.y, a0.z, a0.w, a1.x, a1.y, a1.z, a1.w};
        float bv[8] = {b0.x, b0.y, b0.z, b0.w, b1.x, b1.y, b1.z, b1.w};
#pragma unroll
        for (int ii = 0; ii < 8; ii++)
#pragma unroll
            for (int jj = 0; jj < 8; jj++) acc[ii][jj] += av[ii] * bv[jj];
    }
}

__global__ void __launch_bounds__(256, 1)
k_scores(const float* __restrict__ ec, const float* __restrict__ mask,
         const float* __restrict__ centers, const float* __restrict__ widths,
         const float* __restrict__ w1, const float* __restrict__ b1,
         const float* __restrict__ w2, const float* __restrict__ b2,
         const float* __restrict__ w3, const float* __restrict__ b3) {
    extern __shared__ float smem[];
    float* Ws = smem;                 // 128*SW : W1_rbf rows, then W2
    float* As = Ws + 128 * SW;        // 128*SW : rbf^T, then X1^T [c][p]
    float* Hs = As + 128 * SW;        // 128*SW : hpre [p][c]
    float* dists = Hs + 128 * SW;     // 128
    float* dots = dists + 128;        // 128

    int tid = threadIdx.x;
    int tx = tid & 15, ty = tid >> 4;
    int bi = blockIdx.x, bj = blockIdx.y;

    // pair geometry
    if (tid < 128) {
        int p = tid;
        int i = bi * 16 + (p >> 3);
        int j = bj * 8 + (p & 7);
        float ix = ec[i * 3], iy = ec[i * 3 + 1], iz = ec[i * 3 + 2];
        float jx = ec[j * 3], jy = ec[j * 3 + 1], jz = ec[j * 3 + 2];
        float dx = ix - jx, dy = iy - jy, dz = iz - jz;
        float d = sqrtf(dx * dx + dy * dy + dz * dz) + 1e-8f;
        d = fminf(fmaxf(d, 1e-8f), 1e8f);
        dists[p] = d;
        float dt = ix * jx + iy * jy + iz * jz;
        dots[p] = fminf(fmaxf(dt, -1e8f), 1e8f);
    }
    // load W1 rbf block (rows 32..95) into Ws
    for (int idx = tid; idx < NRBF * HIDN; idx += 256) {
        int r = idx >> 7, n = idx & 127;
        Ws[r * SW + n] = w1[(2 * DHEAD + r) * HIDN + n];
    }
    __syncthreads();
    // rbf features, transposed [r][p]
    for (int idx = tid; idx < NRBF * 128; idx += 256) {
        int p = idx & 127, r = idx >> 7;
        float d = dists[p];
        float t = d - centers[r];
        As[r * SW + p] = (d <= 10.0f) ? __expf(-widths[r] * t * t) : 0.0f;
    }
    __syncthreads();

    float acc[8][8];
    // hpre = rbf @ W1_rbf  (K = 64)
#pragma unroll
    for (int ii = 0; ii < 8; ii++)
#pragma unroll
        for (int jj = 0; jj < 8; jj++) acc[ii][jj] = 0.f;
    gemm_tile(As, Ws, NRBF, ty, tx, acc);
#pragma unroll
    for (int ii = 0; ii < 8; ii++) {
        int p = ty * 8 + ii;
        float dtp = dots[p];
#pragma unroll
        for (int jj = 0; jj < 8; jj++) {
            int n = tx * 8 + jj;
            Hs[p * SW + n] = acc[ii][jj] + dtp * w1[96 * HIDN + n];
        }
    }
    __syncthreads();
    // load W2 into Ws (overwrites W1_rbf)
    for (int idx = tid; idx < HIDN * HIDN; idx += 256) {
        Ws[(idx >> 7) * SW + (idx & 127)] = w2[idx];
    }
    float b2r[8];
#pragma unroll
    for (int jj = 0; jj < 8; jj++) b2r[jj] = b2[tx * 8 + jj];
    __syncthreads();

    for (int h = 0; h < NHEAD; h++) {
        // X1 = silu(hpre + Aq[h,i] + Ak[h,j] + b1), stored transposed [c][p]
        for (int idx = tid; idx < 128 * HIDN; idx += 256) {
            int p = idx >> 7, c = idx & 127;
            int i = bi * 16 + (p >> 3);
            int j = bj * 8 + (p & 7);
            float vv = Hs[p * SW + c] + g_Aq[(h * EN + i) * HIDN + c] +
                       g_Ak[(h * EN + j) * HIDN + c] + b1[c];
            As[c * SW + p] = siluf(vv);
        }
        __syncthreads();
#pragma unroll
        for (int ii = 0; ii < 8; ii++)
#pragma unroll
            for (int jj = 0; jj < 8; jj++) acc[ii][jj] = 0.f;
        gemm_tile(As, Ws, HIDN, ty, tx, acc);

        // epilogue: silu + w3 column reduce
        float w3r[8];
#pragma unroll
        for (int jj = 0; jj < 8; jj++) w3r[jj] = w3[(tx * 8 + jj) * NHEAD + h];
        float ps[8];
#pragma unroll
        for (int ii = 0; ii < 8; ii++) {
            float s = 0.f;
#pragma unroll
            for (int jj = 0; jj < 8; jj++) {
                float x = acc[ii][jj] + b2r[jj];
                s += siluf(x) * w3r[jj];
            }
            ps[ii] = s;
        }
#pragma unroll
        for (int off = 1; off < 16; off <<= 1) {
#pragma unroll
            for (int ii = 0; ii < 8; ii++)
                ps[ii] += __shfl_xor_sync(0xffffffffu, ps[ii], off);
        }
        if (tx == 0) {
            int ig = bi * 16 + ty;
            float bb = b3[h];
#pragma unroll
            for (int ii = 0; ii < 8; ii++) {
                int jg = bj * 8 + ii;
                float s = ps[ii] + bb + mask[ig * EN + jg];
                s = fminf(fmaxf(s, -1e9f), 1e9f);
                g_scores[(h * EN + ig) * EN + jg] = s;
            }
        }
        __syncthreads();
    }
}

// ---------------- K2: softmax + attn@V + coord delta ----------------
__global__ void k_softmax(const float* __restrict__ ec) {
    __shared__ float expv[EN];
    __shared__ float red[128];
    __shared__ float wred[4][20];
    __shared__ float fin[4];
    int i = blockIdx.x, h = blockIdx.y, t = threadIdx.x;
    const float* srow = &g_scores[(h * EN + i) * EN];

    float mx = -1e30f;
    for (int j = t; j < EN; j += 128) mx = fmaxf(mx, srow[j]);
    red[t] = mx;
    __syncthreads();
    for (int s = 64; s > 0; s >>= 1) {
        if (t < s) red[t] = fmaxf(red[t], red[t + s]);
        __syncthreads();
    }
    mx = red[0];
    __syncthreads();
    float sum = 0.f;
    for (int j = t; j < EN; j += 128) {
        float e = __expf(srow[j] - mx);
        expv[j] = e;
        sum += e;
    }
    red[t] = sum;
    __syncthreads();
    for (int s = 64; s > 0; s >>= 1) {
        if (t < s) red[t] += red[t + s];
        __syncthreads();
    }
    float inv = 1.0f / red[0];

    float vals[20];
#pragma unroll
    for (int q = 0; q < 20; q++) vals[q] = 0.f;
    for (int j = t; j < EN; j += 128) {
        float a = expv[j] * inv;
        const float* vr = &g_v[j * HIDN + h * DHEAD];
#pragma unroll
        for (int d = 0; d < DHEAD; d++) vals[d] += a * vr[d];
        vals[16] += a;
        vals[17] += a * ec[j * 3];
        vals[18] += a * ec[j * 3 + 1];
        vals[19] += a * ec[j * 3 + 2];
    }
#pragma unroll
    for (int off = 16; off > 0; off >>= 1)
#pragma unroll
        for (int q = 0; q < 20; q++)
            vals[q] += __shfl_xor_sync(0xffffffffu, vals[q], off);
    int lane = t & 31, warp = t >> 5;
    if (lane == 0)
#pragma unroll
        for (int q = 0; q < 20; q++) wred[warp][q] = vals[q];
    __syncthreads();
    if (t < 20) {
        float s = wred[0][t] + wred[1][t] + wred[2][t] + wred[3][t];
        if (t < 16) g_upd[i * HIDN + h * DHEAD + t] = s;
        else fin[t - 16] = s;
    }
    __syncthreads();
    if (t < 3) {
        float gate = g_gates[h * EN + i];
        g_delta[(h * EN + i) * 3 + t] = gate * (fin[0] * ec[i * 3 + t] - fin[1 + t]);
    }
}

// ---------------- K3: output projection + layernorm + coords ----------------
__global__ void k_out(const float* __restrict__ ef, const float* __restrict__ ec,
                      const float* __restrict__ wo, const float* __restrict__ bo,
                      const float* __restrict__ lg, const float* __restrict__ lb,
                      float* __restrict__ out) {
    __shared__ float u[HIDN];
    __shared__ float red[128];
    int i = blockIdx.x, n = threadIdx.x;
    u[n] = g_upd[i * HIDN + n];
    __syncthreads();
    float y = ef[i * HIDN + n] + bo[n];
#pragma unroll 8
    for (int c = 0; c < HIDN; c++) y += u[c] * wo[c * HIDN + n];
    red[n] = y;
    __syncthreads();
    for (int s = 64; s > 0; s >>= 1) {
        if (n < s) red[n] += red[n + s];
        __syncthreads();
    }
    float mean = red[0] * (1.0f / HIDN);
    __syncthreads();
    float dy = y - mean;
    red[n] = dy * dy;
    __syncthreads();
    for (int s = 64; s > 0; s >>= 1) {
        if (n < s) red[n] += red[n + s];
        __syncthreads();
    }
    float var = red[0] * (1.0f / HIDN);
    float rstd = rsqrtf(var + 1e-5f);
    out[i * HIDN + n] = dy * rstd * lg[n] + lb[n];
    if (n < 3) {
        float dsum = 0.f;
#pragma unroll
        for (int h = 0; h < NHEAD; h++) dsum += g_delta[(h * EN + i) * 3 + n];
        out[EN * HIDN + i * 3 + n] = ec[i * 3 + n] + dsum * 0.125f;
    }
}

// ---------------- launcher ----------------
extern "C" void kernel_launch(void* const* d_in, const int* in_sizes, int n_in,
                              void* d_out, int out_size) {
    const float* ef      = (const float*)d_in[0];
    const float* ec      = (const float*)d_in[1];
    const float* mask    = (const float*)d_in[2];
    const float* wq      = (const float*)d_in[3];
    const float* wk      = (const float*)d_in[4];
    const float* wv      = (const float*)d_in[5];
    const float* centers = (const float*)d_in[6];
    const float* widths  = (const float*)d_in[7];
    const float* a_w1    = (const float*)d_in[8];
    const float* a_b1    = (const float*)d_in[9];
    const float* a_w2    = (const float*)d_in[10];
    const float* a_b2    = (const float*)d_in[11];
    const float* a_w3    = (const float*)d_in[12];
    const float* a_b3    = (const float*)d_in[13];
    const float* g_w1    = (const float*)d_in[14];
    const float* g_b1    = (const float*)d_in[15];
    const float* g_w2    = (const float*)d_in[16];
    const float* g_b2    = (const float*)d_in[17];
    const float* wo      = (const float*)d_in[18];
    const float* bo      = (const float*)d_in[19];
    const float* ln_g    = (const float*)d_in[20];
    const float* ln_b    = (const float*)d_in[21];
    float* out = (float*)d_out;

    cudaFuncSetAttribute(k_scores, cudaFuncAttributeMaxDynamicSharedMemorySize,
                         SMEM_BYTES);

    k_qkv<<<dim3(EN, 3), HIDN>>>(ef, wq, wk, wv);
    k_aqak<<<dim3(EN, 2), HIDN>>>(a_w1);
    k_gates<<<dim3(EN, NHEAD), HIDN>>>(g_w1, g_b1, g_w2, g_b2);
    k_scores<<<dim3(EN / 16, EN / 8), 256, SMEM_BYTES>>>(
        ec, mask, centers, widths, a_w1, a_b1, a_w2, a_b2, a_w3, a_b3);
    k_softmax<<<dim3(EN, NHEAD), HIDN>>>(ec);
    k_out<<<EN, HIDN>>>(ef, ec, wo, bo, ln_g, ln_b, out);
}

// round 2
// speedup vs baseline: 1.1334x; 1.1334x over previous
#include <cuda_runtime.h>
#include <math.h>

#define EN 384
#define HIDN 128
#define NHEAD 8
#define DHEAD 16
#define NRBF 64

static constexpr int SW = 132;     // smem row stride (floats), 16B-aligned
static constexpr int SMEM_BYTES = (3 * 128 * SW + 256) * 4;

// ---------------- device scratch ----------------
__device__ float g_q[EN * HIDN];
__device__ float g_k[EN * HIDN];
__device__ float g_v[EN * HIDN];
__device__ float g_Aq[NHEAD * EN * HIDN];
__device__ float g_Ak[NHEAD * EN * HIDN];
__device__ float g_gates[NHEAD * EN];
__device__ float g_scores[NHEAD * EN * EN];
__device__ float g_upd[EN * HIDN];
__device__ float g_delta[NHEAD * EN * 3];

__device__ __forceinline__ float siluf(float x) { return x / (1.0f + __expf(-x)); }

__device__ __forceinline__ unsigned long long pack2(float lo, float hi) {
    unsigned long long r;
    asm("mov.b64 %0, {%1, %2};" : "=l"(r) : "f"(lo), "f"(hi));
    return r;
}
__device__ __forceinline__ void unpack2(unsigned long long v, float& lo, float& hi) {
    asm("mov.b64 {%0, %1}, %2;" : "=f"(lo), "=f"(hi) : "l"(v));
}
__device__ __forceinline__ void ffma2(unsigned long long& d, unsigned long long a,
                                      unsigned long long b) {
    asm("fma.rn.f32x2 %0, %1, %2, %0;" : "+l"(d) : "l"(a), "l"(b));
}

// ---------------- K0: q,k,v projections ----------------
__global__ void k_qkv(const float* __restrict__ ef, const float* __restrict__ wq,
                      const float* __restrict__ wk, const float* __restrict__ wv) {
    __shared__ float row[HIDN];
    int i = blockIdx.x;
    int n = threadIdx.x;
    row[n] = ef[i * HIDN + n];
    __syncthreads();
    const float* W = (blockIdx.y == 0) ? wq : ((blockIdx.y == 1) ? wk : wv);
    float* O = (blockIdx.y == 0) ? g_q : ((blockIdx.y == 1) ? g_k : g_v);
    float acc = 0.f;
#pragma unroll 8
    for (int c = 0; c < HIDN; c++) acc += row[c] * W[c * HIDN + n];
    O[i * HIDN + n] = acc;
}

// ---------------- K0b: Aq/Ak precompute ----------------
__global__ void k_aqak(const float* __restrict__ w1) {
    __shared__ float row[HIDN];
    int i = blockIdx.x;
    int n = threadIdx.x;
    int sel = blockIdx.y;
    const float* src = sel ? g_k : g_q;
    float* dst = sel ? g_Ak : g_Aq;
    int roff = sel ? DHEAD : 0;
    row[n] = src[i * HIDN + n];
    __syncthreads();
    for (int h = 0; h < NHEAD; h++) {
        float acc = 0.f;
#pragma unroll
        for (int d = 0; d < DHEAD; d++)
            acc += row[h * DHEAD + d] * w1[(roff + d) * HIDN + n];
        dst[(h * EN + i) * HIDN + n] = acc;
    }
}

// ---------------- K0c: gates ----------------
__global__ void k_gates(const float* __restrict__ gw1, const float* __restrict__ gb1,
                        const float* __restrict__ gw2, const float* __restrict__ gb2) {
    __shared__ float vrow[DHEAD];
    __shared__ float red[HIDN];
    int j = blockIdx.x, h = blockIdx.y, n = threadIdx.x;
    if (n < DHEAD) vrow[n] = g_v[j * HIDN + h * DHEAD + n];
    __syncthreads();
    float acc = gb1[n];
#pragma unroll
    for (int d = 0; d < DHEAD; d++) acc += vrow[d] * gw1[d * HIDN + n];
    red[n] = siluf(acc) * gw2[n];
    __syncthreads();
    for (int s = 64; s > 0; s >>= 1) {
        if (n < s) red[n] += red[n + s];
        __syncthreads();
    }
    if (n == 0) g_gates[h * EN + j] = 1.0f / (1.0f + __expf(-(red[0] + gb2[0])));
}

// ---------------- K1: fused pair-MLP -> attention scores ----------------
// FFMA2 register-tile GEMM: 8 pairs x 8 cols (as 4 f32x2) per thread.
__device__ __forceinline__ void gemm_tile2(const float* __restrict__ A,
                                           const float* __restrict__ B, int K,
                                           int ty, int tx,
                                           unsigned long long acc[8][4]) {
#pragma unroll 1
    for (int c = 0; c < K; c++) {
        const float4* ar = (const float4*)(A + c * SW + ty * 8);
        float4 a0 = ar[0];
        float4 a1 = ar[1];
        const ulonglong2* br = (const ulonglong2*)(B + c * SW + tx * 8);
        ulonglong2 b0 = br[0];
        ulonglong2 b1 = br[1];
        unsigned long long bv[4] = {b0.x, b0.y, b1.x, b1.y};
        float av[8] = {a0.x, a0.y, a0.z, a0.w, a1.x, a1.y, a1.z, a1.w};
#pragma unroll
        for (int ii = 0; ii < 8; ii++) {
            unsigned long long ap = pack2(av[ii], av[ii]);
#pragma unroll
            for (int jj = 0; jj < 4; jj++) ffma2(acc[ii][jj], ap, bv[jj]);
        }
    }
}

__global__ void __launch_bounds__(256, 1)
k_scores(const float* __restrict__ ec, const float* __restrict__ mask,
         const float* __restrict__ centers, const float* __restrict__ widths,
         const float* __restrict__ w1, const float* __restrict__ b1,
         const float* __restrict__ w2, const float* __restrict__ b2,
         const float* __restrict__ w3, const float* __restrict__ b3) {
    extern __shared__ float smem[];
    float* Ws = smem;                 // W1_rbf rows, then W2
    float* As = Ws + 128 * SW;        // rbf^T, then X1^T [c][p]
    float* Hs = As + 128 * SW;        // hpre [p][c]
    float* dists = Hs + 128 * SW;
    float* dots = dists + 128;

    int tid = threadIdx.x;
    int tx = tid & 15, ty = tid >> 4;
    int bi = blockIdx.x, bj = blockIdx.y;

    if (tid < 128) {
        int p = tid;
        int i = bi * 16 + (p >> 3);
        int j = bj * 8 + (p & 7);
        float ix = ec[i * 3], iy = ec[i * 3 + 1], iz = ec[i * 3 + 2];
        float jx = ec[j * 3], jy = ec[j * 3 + 1], jz = ec[j * 3 + 2];
        float dx = ix - jx, dy = iy - jy, dz = iz - jz;
        float d = sqrtf(dx * dx + dy * dy + dz * dz) + 1e-8f;
        d = fminf(fmaxf(d, 1e-8f), 1e8f);
        dists[p] = d;
        float dt = ix * jx + iy * jy + iz * jz;
        dots[p] = fminf(fmaxf(dt, -1e8f), 1e8f);
    }
    for (int idx = tid; idx < NRBF * HIDN; idx += 256) {
        int r = idx >> 7, n = idx & 127;
        Ws[r * SW + n] = w1[(2 * DHEAD + r) * HIDN + n];
    }
    __syncthreads();
    for (int idx = tid; idx < NRBF * 128; idx += 256) {
        int p = idx & 127, r = idx >> 7;
        float d = dists[p];
        float t = d - centers[r];
        As[r * SW + p] = (d <= 10.0f) ? __expf(-widths[r] * t * t) : 0.0f;
    }
    __syncthreads();

    unsigned long long acc[8][4];
    // hpre = rbf @ W1_rbf  (K = 64)
#pragma unroll
    for (int ii = 0; ii < 8; ii++)
#pragma unroll
        for (int jj = 0; jj < 4; jj++) acc[ii][jj] = 0ull;
    gemm_tile2(As, Ws, NRBF, ty, tx, acc);
#pragma unroll
    for (int ii = 0; ii < 8; ii++) {
        int p = ty * 8 + ii;
        float dtp = dots[p];
#pragma unroll
        for (int jj = 0; jj < 4; jj++) {
            float lo, hi;
            unpack2(acc[ii][jj], lo, hi);
            int n = tx * 8 + 2 * jj;
            Hs[p * SW + n] = lo + dtp * w1[96 * HIDN + n];
            Hs[p * SW + n + 1] = hi + dtp * w1[96 * HIDN + n + 1];
        }
    }
    __syncthreads();
    for (int idx = tid; idx < HIDN * HIDN; idx += 256) {
        Ws[(idx >> 7) * SW + (idx & 127)] = w2[idx];
    }
    float b2r[8];
#pragma unroll
    for (int jj = 0; jj < 8; jj++) b2r[jj] = b2[tx * 8 + jj];
    __syncthreads();

    // per-thread fixed coordinates for the X1-build loop
    int cc = tid & 127;          // hidden channel
    int p0 = tid >> 7;           // pair parity (0/1)
    float b1c = b1[cc];

    for (int h = 0; h < NHEAD; h++) {
        // X1 = silu(hpre + Aq[h,i] + Ak[h,j] + b1), stored transposed [c][p]
        {
            const float* AqB = g_Aq + ((long)h * EN + bi * 16) * HIDN + cc;
            const float* AkB = g_Ak + ((long)h * EN + bj * 8) * HIDN + cc;
            float akr[4];
#pragma unroll
            for (int t = 0; t < 4; t++) akr[t] = AkB[(p0 + 2 * t) * HIDN] + b1c;
#pragma unroll
            for (int pi = 0; pi < 16; pi++) {
                float aq = AqB[pi * HIDN];
#pragma unroll
                for (int t = 0; t < 4; t++) {
                    int p = pi * 8 + p0 + 2 * t;
                    float vv = Hs[p * SW + cc] + akr[t] + aq;
                    As[cc * SW + p] = siluf(vv);
                }
            }
        }
        __syncthreads();
#pragma unroll
        for (int ii = 0; ii < 8; ii++)
#pragma unroll
            for (int jj = 0; jj < 4; jj++) acc[ii][jj] = 0ull;
        gemm_tile2(As, Ws, HIDN, ty, tx, acc);

        // epilogue: silu + w3 column reduce
        float w3r[8];
#pragma unroll
        for (int jj = 0; jj < 8; jj++) w3r[jj] = w3[(tx * 8 + jj) * NHEAD + h];
        float ps[8];
#pragma unroll
        for (int ii = 0; ii < 8; ii++) {
            float s = 0.f;
#pragma unroll
            for (int jj = 0; jj < 4; jj++) {
                float lo, hi;
                unpack2(acc[ii][jj], lo, hi);
                s += siluf(lo + b2r[2 * jj]) * w3r[2 * jj];
                s += siluf(hi + b2r[2 * jj + 1]) * w3r[2 * jj + 1];
            }
            ps[ii] = s;
        }
#pragma unroll
        for (int off = 1; off < 16; off <<= 1) {
#pragma unroll
            for (int ii = 0; ii < 8; ii++)
                ps[ii] += __shfl_xor_sync(0xffffffffu, ps[ii], off);
        }
        if (tx == 0) {
            int ig = bi * 16 + ty;
            float bb = b3[h];
#pragma unroll
            for (int ii = 0; ii < 8; ii++) {
                int jg = bj * 8 + ii;
                float s = ps[ii] + bb + mask[ig * EN + jg];
                s = fminf(fmaxf(s, -1e9f), 1e9f);
                g_scores[(h * EN + ig) * EN + jg] = s;
            }
        }
        __syncthreads();
    }
}

// ---------------- K2: softmax + attn@V + coord delta ----------------
__global__ void k_softmax(const float* __restrict__ ec) {
    __shared__ float expv[EN];
    __shared__ float red[128];
    __shared__ float wred[4][20];
    __shared__ float fin[4];
    int i = blockIdx.x, h = blockIdx.y, t = threadIdx.x;
    const float* srow = &g_scores[(h * EN + i) * EN];

    float mx = -1e30f;
    for (int j = t; j < EN; j += 128) mx = fmaxf(mx, srow[j]);
    red[t] = mx;
    __syncthreads();
    for (int s = 64; s > 0; s >>= 1) {
        if (t < s) red[t] = fmaxf(red[t], red[t + s]);
        __syncthreads();
    }
    mx = red[0];
    __syncthreads();
    float sum = 0.f;
    for (int j = t; j < EN; j += 128) {
        float e = __expf(srow[j] - mx);
        expv[j] = e;
        sum += e;
    }
    red[t] = sum;
    __syncthreads();
    for (int s = 64; s > 0; s >>= 1) {
        if (t < s) red[t] += red[t + s];
        __syncthreads();
    }
    float inv = 1.0f / red[0];

    float vals[20];
#pragma unroll
    for (int q = 0; q < 20; q++) vals[q] = 0.f;
    for (int j = t; j < EN; j += 128) {
        float a = expv[j] * inv;
        const float* vr = &g_v[j * HIDN + h * DHEAD];
#pragma unroll
        for (int d = 0; d < DHEAD; d++) vals[d] += a * vr[d];
        vals[16] += a;
        vals[17] += a * ec[j * 3];
        vals[18] += a * ec[j * 3 + 1];
        vals[19] += a * ec[j * 3 + 2];
    }
#pragma unroll
    for (int off = 16; off > 0; off >>= 1)
#pragma unroll
        for (int q = 0; q < 20; q++)
            vals[q] += __shfl_xor_sync(0xffffffffu, vals[q], off);
    int lane = t & 31, warp = t >> 5;
    if (lane == 0)
#pragma unroll
        for (int q = 0; q < 20; q++) wred[warp][q] = vals[q];
    __syncthreads();
    if (t < 20) {
        float s = wred[0][t] + wred[1][t] + wred[2][t] + wred[3][t];
        if (t < 16) g_upd[i * HIDN + h * DHEAD + t] = s;
        else fin[t - 16] = s;
    }
    __syncthreads();
    if (t < 3) {
        float gate = g_gates[h * EN + i];
        g_delta[(h * EN + i) * 3 + t] = gate * (fin[0] * ec[i * 3 + t] - fin[1 + t]);
    }
}

// ---------------- K3: output projection + layernorm + coords ----------------
__global__ void k_out(const float* __restrict__ ef, const float* __restrict__ ec,
                      const float* __restrict__ wo, const float* __restrict__ bo,
                      const float* __restrict__ lg, const float* __restrict__ lb,
                      float* __restrict__ out) {
    __shared__ float u[HIDN];
    __shared__ float red[128];
    int i = blockIdx.x, n = threadIdx.x;
    u[n] = g_upd[i * HIDN + n];
    __syncthreads();
    float y = ef[i * HIDN + n] + bo[n];
#pragma unroll 8
    for (int c = 0; c < HIDN; c++) y += u[c] * wo[c * HIDN + n];
    red[n] = y;
    __syncthreads();
    for (int s = 64; s > 0; s >>= 1) {
        if (n < s) red[n] += red[n + s];
        __syncthreads();
    }
    float mean = red[0] * (1.0f / HIDN);
    __syncthreads();
    float dy = y - mean;
    red[n] = dy * dy;
    __syncthreads();
    for (int s = 64; s > 0; s >>= 1) {
        if (n < s) red[n] += red[n + s];
        __syncthreads();
    }
    float var = red[0] * (1.0f / HIDN);
    float rstd = rsqrtf(var + 1e-5f);
    out[i * HIDN + n] = dy * rstd * lg[n] + lb[n];
    if (n < 3) {
        float dsum = 0.f;
#pragma unroll
        for (int h = 0; h < NHEAD; h++) dsum += g_delta[(h * EN + i) * 3 + n];
        out[EN * HIDN + i * 3 + n] = ec[i * 3 + n] + dsum * 0.125f;
    }
}

// ---------------- launcher ----------------
extern "C" void kernel_launch(void* const* d_in, const int* in_sizes, int n_in,
                              void* d_out, int out_size) {
    const float* ef      = (const float*)d_in[0];
    const float* ec      = (const float*)d_in[1];
    const float* mask    = (const float*)d_in[2];
    const float* wq      = (const float*)d_in[3];
    const float* wk      = (const float*)d_in[4];
    const float* wv      = (const float*)d_in[5];
    const float* centers = (const float*)d_in[6];
    const float* widths  = (const float*)d_in[7];
    const float* a_w1    = (const float*)d_in[8];
    const float* a_b1    = (const float*)d_in[9];
    const float* a_w2    = (const float*)d_in[10];
    const float* a_b2    = (const float*)d_in[11];
    const float* a_w3    = (const float*)d_in[12];
    const float* a_b3    = (const float*)d_in[13];
    const float* g_w1    = (const float*)d_in[14];
    const float* g_b1    = (const float*)d_in[15];
    const float* g_w2    = (const float*)d_in[16];
    const float* g_b2    = (const float*)d_in[17];
    const float* wo      = (const float*)d_in[18];
    const float* bo      = (const float*)d_in[19];
    const float* ln_g    = (const float*)d_in[20];
    const float* ln_b    = (const float*)d_in[21];
    float* out = (float*)d_out;

    cudaFuncSetAttribute(k_scores, cudaFuncAttributeMaxDynamicSharedMemorySize,
                         SMEM_BYTES);

    k_qkv<<<dim3(EN, 3), HIDN>>>(ef, wq, wk, wv);
    k_aqak<<<dim3(EN, 2), HIDN>>>(a_w1);
    k_gates<<<dim3(EN, NHEAD), HIDN>>>(g_w1, g_b1, g_w2, g_b2);
    k_scores<<<dim3(EN / 16, EN / 8), 256, SMEM_BYTES>>>(
        ec, mask, centers, widths, a_w1, a_b1, a_w2, a_b2, a_w3, a_b3);
    k_softmax<<<dim3(EN, NHEAD), HIDN>>>(ec);
    k_out<<<EN, HIDN>>>(ef, ec, wo, bo, ln_g, ln_b, out);
}

// round 3
// speedup vs baseline: 1.6768x; 1.4794x over previous
#include <cuda_runtime.h>
#include <math.h>

#define EN 384
#define HIDN 128
#define NHEAD 8
#define DHEAD 16
#define NRBF 64

static constexpr int SW = 132;     // smem row stride (floats)
static constexpr int SMEM_BYTES = (2 * 128 * SW + 256) * 4;   // ~133 KB

// ---------------- device scratch ----------------
__device__ float g_q[EN * HIDN];
__device__ float g_k[EN * HIDN];
__device__ float g_v[EN * HIDN];
__device__ float g_Aq[NHEAD * EN * HIDN];
__device__ float g_Ak[NHEAD * EN * HIDN];
__device__ float g_gates[NHEAD * EN];
__device__ float g_scores[NHEAD * EN * EN];
__device__ float g_upd[EN * HIDN];
__device__ float g_delta[NHEAD * EN * 3];

__device__ __forceinline__ float siluf(float x) {
    return __fdividef(x, 1.0f + __expf(-x));
}

__device__ __forceinline__ unsigned long long pack2(float lo, float hi) {
    unsigned long long r;
    asm("mov.b64 %0, {%1, %2};" : "=l"(r) : "f"(lo), "f"(hi));
    return r;
}
__device__ __forceinline__ void unpack2(unsigned long long v, float& lo, float& hi) {
    asm("mov.b64 {%0, %1}, %2;" : "=f"(lo), "=f"(hi) : "l"(v));
}
__device__ __forceinline__ void ffma2(unsigned long long& d, unsigned long long a,
                                      unsigned long long b) {
    asm("fma.rn.f32x2 %0, %1, %2, %0;" : "+l"(d) : "l"(a), "l"(b));
}

// ---------------- K0: q,k,v projections ----------------
__global__ void k_qkv(const float* __restrict__ ef, const float* __restrict__ wq,
                      const float* __restrict__ wk, const float* __restrict__ wv) {
    __shared__ float row[HIDN];
    int i = blockIdx.x;
    int n = threadIdx.x;
    row[n] = ef[i * HIDN + n];
    __syncthreads();
    const float* W = (blockIdx.y == 0) ? wq : ((blockIdx.y == 1) ? wk : wv);
    float* O = (blockIdx.y == 0) ? g_q : ((blockIdx.y == 1) ? g_k : g_v);
    float acc = 0.f;
#pragma unroll 8
    for (int c = 0; c < HIDN; c++) acc += row[c] * W[c * HIDN + n];
    O[i * HIDN + n] = acc;
}

// ---------------- K0b: Aq/Ak precompute ----------------
__global__ void k_aqak(const float* __restrict__ w1) {
    __shared__ float row[HIDN];
    int i = blockIdx.x;
    int n = threadIdx.x;
    int sel = blockIdx.y;
    const float* src = sel ? g_k : g_q;
    float* dst = sel ? g_Ak : g_Aq;
    int roff = sel ? DHEAD : 0;
    row[n] = src[i * HIDN + n];
    __syncthreads();
    for (int h = 0; h < NHEAD; h++) {
        float acc = 0.f;
#pragma unroll
        for (int d = 0; d < DHEAD; d++)
            acc += row[h * DHEAD + d] * w1[(roff + d) * HIDN + n];
        dst[(h * EN + i) * HIDN + n] = acc;
    }
}

// ---------------- K0c: gates ----------------
__global__ void k_gates(const float* __restrict__ gw1, const float* __restrict__ gb1,
                        const float* __restrict__ gw2, const float* __restrict__ gb2) {
    __shared__ float vrow[DHEAD];
    __shared__ float red[HIDN];
    int j = blockIdx.x, h = blockIdx.y, n = threadIdx.x;
    if (n < DHEAD) vrow[n] = g_v[j * HIDN + h * DHEAD + n];
    __syncthreads();
    float acc = gb1[n];
#pragma unroll
    for (int d = 0; d < DHEAD; d++) acc += vrow[d] * gw1[d * HIDN + n];
    red[n] = siluf(acc) * gw2[n];
    __syncthreads();
    for (int s = 64; s > 0; s >>= 1) {
        if (n < s) red[n] += red[n + s];
        __syncthreads();
    }
    if (n == 0) g_gates[h * EN + j] = 1.0f / (1.0f + __expf(-(red[0] + gb2[0])));
}

// ---------------- K1: fused pair-MLP -> attention scores ----------------
// 512 threads. tx = tid&31 (4 cols), ty = tid>>5 = warp (8 pairs, one i per warp).
// acc[pp][jj]: f32x2 over adjacent pairs (2pp,2pp+1), col tx*4+jj.
// A (X1^T [c][p]) naturally packed; B (W2 [c][n]) duplicated via pack.
__device__ __forceinline__ void gemm_run(const float* __restrict__ A,
                                         const float* __restrict__ B, int K,
                                         int ty, int tx,
                                         unsigned long long acc[4][4]) {
    const float* ap = A + ty * 8;
    const float* bp = B + tx * 4;
#pragma unroll 2
    for (int c = 0; c < K; c++, ap += SW, bp += SW) {
        ulonglong2 a01 = *(const ulonglong2*)ap;          // broadcast within warp
        ulonglong2 a23 = *(const ulonglong2*)(ap + 4);
        unsigned long long av[4] = {a01.x, a01.y, a23.x, a23.y};
        float4 w = *(const float4*)bp;
        unsigned long long bd[4] = {pack2(w.x, w.x), pack2(w.y, w.y),
                                    pack2(w.z, w.z), pack2(w.w, w.w)};
#pragma unroll
        for (int pp = 0; pp < 4; pp++)
#pragma unroll
            for (int jj = 0; jj < 4; jj++) ffma2(acc[pp][jj], av[pp], bd[jj]);
    }
}

__global__ void __launch_bounds__(512, 1)
k_scores(const float* __restrict__ ec, const float* __restrict__ mask,
         const float* __restrict__ centers, const float* __restrict__ widths,
         const float* __restrict__ w1, const float* __restrict__ b1,
         const float* __restrict__ w2, const float* __restrict__ b2,
         const float* __restrict__ w3, const float* __restrict__ b3) {
    extern __shared__ float smem[];
    float* Ws = smem;                 // [128][SW]: W1_rbf rows, then W2
    float* As = Ws + 128 * SW;        // [128][SW]: rbf^T, then X1^T  [c][p]
    float* dists = As + 128 * SW;     // 128
    float* dots = dists + 128;        // 128

    int tid = threadIdx.x;
    int tx = tid & 31, ty = tid >> 5;
    int bi = blockIdx.x, bj = blockIdx.y;

    // pair geometry
    if (tid < 128) {
        int p = tid;
        int i = bi * 16 + (p >> 3);
        int j = bj * 8 + (p & 7);
        float ix = ec[i * 3], iy = ec[i * 3 + 1], iz = ec[i * 3 + 2];
        float jx = ec[j * 3], jy = ec[j * 3 + 1], jz = ec[j * 3 + 2];
        float dx = ix - jx, dy = iy - jy, dz = iz - jz;
        float d = sqrtf(dx * dx + dy * dy + dz * dz) + 1e-8f;
        d = fminf(fmaxf(d, 1e-8f), 1e8f);
        dists[p] = d;
        float dt = ix * jx + iy * jy + iz * jz;
        dots[p] = fminf(fmaxf(dt, -1e8f), 1e8f);
    }
    // W1 rbf block (rows 32..95) -> Ws rows 0..63 (vectorized)
    for (int idx = tid; idx < NRBF * HIDN / 4; idx += 512) {
        int r = idx >> 5, col = (idx & 31) * 4;
        *(float4*)(Ws + r * SW + col) = *(const float4*)(w1 + (2 * DHEAD + r) * HIDN + col);
    }
    __syncthreads();
    // rbf features, transposed [r][p]
    for (int idx = tid; idx < NRBF * 128; idx += 512) {
        int p = idx & 127, r = idx >> 7;
        float d = dists[p];
        float t = d - centers[r];
        As[r * SW + p] = (d <= 10.0f) ? __expf(-widths[r] * t * t) : 0.0f;
    }
    __syncthreads();

    unsigned long long acc[4][4];
#pragma unroll
    for (int pp = 0; pp < 4; pp++)
#pragma unroll
        for (int jj = 0; jj < 4; jj++) acc[pp][jj] = 0ull;
    gemm_run(As, Ws, NRBF, ty, tx, acc);

    // hpre = rbf@W1_rbf + dot*w1_dot, kept in registers (scalar form)
    float hs[8][4];
    {
        float4 wdot = *(const float4*)(w1 + 96 * HIDN + tx * 4);
        float wd[4] = {wdot.x, wdot.y, wdot.z, wdot.w};
#pragma unroll
        for (int pp = 0; pp < 4; pp++) {
            float2 dp = *(const float2*)(dots + ty * 8 + 2 * pp);
#pragma unroll
            for (int jj = 0; jj < 4; jj++) {
                float lo, hi;
                unpack2(acc[pp][jj], lo, hi);
                hs[2 * pp][jj] = lo + dp.x * wd[jj];
                hs[2 * pp + 1][jj] = hi + dp.y * wd[jj];
            }
        }
    }
    __syncthreads();
    // W2 -> Ws (vectorized)
    for (int idx = tid; idx < HIDN * HIDN / 4; idx += 512) {
        int r = idx >> 5, col = (idx & 31) * 4;
        *(float4*)(Ws + r * SW + col) = *(const float4*)(w2 + r * HIDN + col);
    }

    float4 b1v = *(const float4*)(b1 + tx * 4);
    float b1r[4] = {b1v.x, b1v.y, b1v.z, b1v.w};
    float4 b2v = *(const float4*)(b2 + tx * 4);
    float b2r[4] = {b2v.x, b2v.y, b2v.z, b2v.w};
    int ig = bi * 16 + ty;
    __syncthreads();

    for (int h = 0; h < NHEAD; h++) {
        // X1 = silu(hpre + Aq[h,i] + Ak[h,j] + b1) -> As [c][p]
        {
            const float4* aq4 = (const float4*)(g_Aq + ((long)(h * EN + ig)) * HIDN + tx * 4);
            float4 aq = __ldg(aq4);
            float aqr[4] = {aq.x + b1r[0], aq.y + b1r[1], aq.z + b1r[2], aq.w + b1r[3]};
            float xs[4][8];
#pragma unroll
            for (int ii = 0; ii < 8; ii++) {
                float4 ak = __ldg((const float4*)(g_Ak + ((long)(h * EN + bj * 8 + ii)) * HIDN + tx * 4));
                float akr[4] = {ak.x, ak.y, ak.z, ak.w};
#pragma unroll
                for (int jj = 0; jj < 4; jj++)
                    xs[jj][ii] = siluf(hs[ii][jj] + aqr[jj] + akr[jj]);
            }
#pragma unroll
            for (int jj = 0; jj < 4; jj++) {
                float* dst = As + (tx * 4 + jj) * SW + ty * 8;
                *(float4*)dst = make_float4(xs[jj][0], xs[jj][1], xs[jj][2], xs[jj][3]);
                *(float4*)(dst + 4) = make_float4(xs[jj][4], xs[jj][5], xs[jj][6], xs[jj][7]);
            }
        }
        __syncthreads();
#pragma unroll
        for (int pp = 0; pp < 4; pp++)
#pragma unroll
            for (int jj = 0; jj < 4; jj++) acc[pp][jj] = 0ull;
        gemm_run(As, Ws, HIDN, ty, tx, acc);

        // epilogue: silu + w3 column reduce across warp
        float w3r[4];
#pragma unroll
        for (int jj = 0; jj < 4; jj++) w3r[jj] = __ldg(w3 + (tx * 4 + jj) * NHEAD + h);
        float ps[8];
#pragma unroll
        for (int pp = 0; pp < 4; pp++) {
            float slo = 0.f, shi = 0.f;
#pragma unroll
            for (int jj = 0; jj < 4; jj++) {
                float lo, hi;
                unpack2(acc[pp][jj], lo, hi);
                slo += siluf(lo + b2r[jj]) * w3r[jj];
                shi += siluf(hi + b2r[jj]) * w3r[jj];
            }
            ps[2 * pp] = slo;
            ps[2 * pp + 1] = shi;
        }
#pragma unroll
        for (int off = 1; off < 32; off <<= 1) {
#pragma unroll
            for (int ii = 0; ii < 8; ii++)
                ps[ii] += __shfl_xor_sync(0xffffffffu, ps[ii], off);
        }
        if (tx == 0) {
            float bb = b3[h];
            const float* mrow = mask + (long)ig * EN + bj * 8;
            float* srow = g_scores + ((long)(h * EN + ig)) * EN + bj * 8;
            float4 m0 = __ldg((const float4*)mrow);
            float4 m1 = __ldg((const float4*)(mrow + 4));
            float4 o0, o1;
            o0.x = fminf(fmaxf(ps[0] + bb + m0.x, -1e9f), 1e9f);
            o0.y = fminf(fmaxf(ps[1] + bb + m0.y, -1e9f), 1e9f);
            o0.z = fminf(fmaxf(ps[2] + bb + m0.z, -1e9f), 1e9f);
            o0.w = fminf(fmaxf(ps[3] + bb + m0.w, -1e9f), 1e9f);
            o1.x = fminf(fmaxf(ps[4] + bb + m1.x, -1e9f), 1e9f);
            o1.y = fminf(fmaxf(ps[5] + bb + m1.y, -1e9f), 1e9f);
            o1.z = fminf(fmaxf(ps[6] + bb + m1.z, -1e9f), 1e9f);
            o1.w = fminf(fmaxf(ps[7] + bb + m1.w, -1e9f), 1e9f);
            *(float4*)srow = o0;
            *(float4*)(srow + 4) = o1;
        }
        __syncthreads();
    }
}

// ---------------- K2: softmax + attn@V + coord delta ----------------
__global__ void k_softmax(const float* __restrict__ ec) {
    __shared__ float expv[EN];
    __shared__ float red[128];
    __shared__ float wred[4][20];
    __shared__ float fin[4];
    int i = blockIdx.x, h = blockIdx.y, t = threadIdx.x;
    const float* srow = &g_scores[(h * EN + i) * EN];

    float mx = -1e30f;
    for (int j = t; j < EN; j += 128) mx = fmaxf(mx, srow[j]);
    red[t] = mx;
    __syncthreads();
    for (int s = 64; s > 0; s >>= 1) {
        if (t < s) red[t] = fmaxf(red[t], red[t + s]);
        __syncthreads();
    }
    mx = red[0];
    __syncthreads();
    float sum = 0.f;
    for (int j = t; j < EN; j += 128) {
        float e = __expf(srow[j] - mx);
        expv[j] = e;
        sum += e;
    }
    red[t] = sum;
    __syncthreads();
    for (int s = 64; s > 0; s >>= 1) {
        if (t < s) red[t] += red[t + s];
        __syncthreads();
    }
    float inv = 1.0f / red[0];

    float vals[20];
#pragma unroll
    for (int q = 0; q < 20; q++) vals[q] = 0.f;
    for (int j = t; j < EN; j += 128) {
        float a = expv[j] * inv;
        const float* vr = &g_v[j * HIDN + h * DHEAD];
#pragma unroll
        for (int d = 0; d < DHEAD; d++) vals[d] += a * vr[d];
        vals[16] += a;
        vals[17] += a * ec[j * 3];
        vals[18] += a * ec[j * 3 + 1];
        vals[19] += a * ec[j * 3 + 2];
    }
#pragma unroll
    for (int off = 16; off > 0; off >>= 1)
#pragma unroll
        for (int q = 0; q < 20; q++)
            vals[q] += __shfl_xor_sync(0xffffffffu, vals[q], off);
    int lane = t & 31, warp = t >> 5;
    if (lane == 0)
#pragma unroll
        for (int q = 0; q < 20; q++) wred[warp][q] = vals[q];
    __syncthreads();
    if (t < 20) {
        float s = wred[0][t] + wred[1][t] + wred[2][t] + wred[3][t];
        if (t < 16) g_upd[i * HIDN + h * DHEAD + t] = s;
        else fin[t - 16] = s;
    }
    __syncthreads();
    if (t < 3) {
        float gate = g_gates[h * EN + i];
        g_delta[(h * EN + i) * 3 + t] = gate * (fin[0] * ec[i * 3 + t] - fin[1 + t]);
    }
}

// ---------------- K3: output projection + layernorm + coords ----------------
__global__ void k_out(const float* __restrict__ ef, const float* __restrict__ ec,
                      const float* __restrict__ wo, const float* __restrict__ bo,
                      const float* __restrict__ lg, const float* __restrict__ lb,
                      float* __restrict__ out) {
    __shared__ float u[HIDN];
    __shared__ float red[128];
    int i = blockIdx.x, n = threadIdx.x;
    u[n] = g_upd[i * HIDN + n];
    __syncthreads();
    float y = ef[i * HIDN + n] + bo[n];
#pragma unroll 8
    for (int c = 0; c < HIDN; c++) y += u[c] * wo[c * HIDN + n];
    red[n] = y;
    __syncthreads();
    for (int s = 64; s > 0; s >>= 1) {
        if (n < s) red[n] += red[n + s];
        __syncthreads();
    }
    float mean = red[0] * (1.0f / HIDN);
    __syncthreads();
    float dy = y - mean;
    red[n] = dy * dy;
    __syncthreads();
    for (int s = 64; s > 0; s >>= 1) {
        if (n < s) red[n] += red[n + s];
        __syncthreads();
    }
    float var = red[0] * (1.0f / HIDN);
    float rstd = rsqrtf(var + 1e-5f);
    out[i * HIDN + n] = dy * rstd * lg[n] + lb[n];
    if (n < 3) {
        float dsum = 0.f;
#pragma unroll
        for (int h = 0; h < NHEAD; h++) dsum += g_delta[(h * EN + i) * 3 + n];
        out[EN * HIDN + i * 3 + n] = ec[i * 3 + n] + dsum * 0.125f;
    }
}

// ---------------- launcher ----------------
extern "C" void kernel_launch(void* const* d_in, const int* in_sizes, int n_in,
                              void* d_out, int out_size) {
    const float* ef      = (const float*)d_in[0];
    const float* ec      = (const float*)d_in[1];
    const float* mask    = (const float*)d_in[2];
    const float* wq      = (const float*)d_in[3];
    const float* wk      = (const float*)d_in[4];
    const float* wv      = (const float*)d_in[5];
    const float* centers = (const float*)d_in[6];
    const float* widths  = (const float*)d_in[7];
    const float* a_w1    = (const float*)d_in[8];
    const float* a_b1    = (const float*)d_in[9];
    const float* a_w2    = (const float*)d_in[10];
    const float* a_b2    = (const float*)d_in[11];
    const float* a_w3    = (const float*)d_in[12];
    const float* a_b3    = (const float*)d_in[13];
    const float* g_w1    = (const float*)d_in[14];
    const float* g_b1    = (const float*)d_in[15];
    const float* g_w2    = (const float*)d_in[16];
    const float* g_b2    = (const float*)d_in[17];
    const float* wo      = (const float*)d_in[18];
    const float* bo      = (const float*)d_in[19];
    const float* ln_g    = (const float*)d_in[20];
    const float* ln_b    = (const float*)d_in[21];
    float* out = (float*)d_out;

    cudaFuncSetAttribute(k_scores, cudaFuncAttributeMaxDynamicSharedMemorySize,
                         SMEM_BYTES);

    k_qkv<<<dim3(EN, 3), HIDN>>>(ef, wq, wk, wv);
    k_aqak<<<dim3(EN, 2), HIDN>>>(a_w1);
    k_gates<<<dim3(EN, NHEAD), HIDN>>>(g_w1, g_b1, g_w2, g_b2);
    k_scores<<<dim3(EN / 16, EN / 8), 512, SMEM_BYTES>>>(
        ec, mask, centers, widths, a_w1, a_b1, a_w2, a_b2, a_w3, a_b3);
    k_softmax<<<dim3(EN, NHEAD), HIDN>>>(ec);
    k_out<<<EN, HIDN>>>(ef, ec, wo, bo, ln_g, ln_b, out);
}

// round 4
// speedup vs baseline: 1.7066x; 1.0178x over previous
#include <cuda_runtime.h>
#include <math.h>

#define EN 384
#define HIDN 128
#define NHEAD 8
#define DHEAD 16
#define NRBF 64

static constexpr int SW = 132;     // smem row stride (floats)
static constexpr int SMEM_BYTES = (3 * 128 * SW + 256) * 4;   // Ws + As0 + As1 ~204 KB

// ---------------- device scratch ----------------
__device__ float g_q[EN * HIDN];
__device__ float g_k[EN * HIDN];
__device__ float g_v[EN * HIDN];
__device__ float g_Aq[NHEAD * EN * HIDN];
__device__ float g_Ak[NHEAD * EN * HIDN];
__device__ float g_gates[NHEAD * EN];
__device__ float g_scores[NHEAD * EN * EN];
__device__ float g_upd[EN * HIDN];
__device__ float g_delta[NHEAD * EN * 3];

// exact-ish silu (ex2 + rcp) — used where precision matters most
__device__ __forceinline__ float siluf(float x) {
    return __fdividef(x, 1.0f + __expf(-x));
}
// fast silu via tanh.approx (1 MUFU) — used in layer-1 build only
__device__ __forceinline__ float silu_fast(float x) {
    float t;
    asm("tanh.approx.f32 %0, %1;" : "=f"(t) : "f"(x * 0.5f));
    return fmaf(x, 0.5f * t, 0.5f * x);
}

__device__ __forceinline__ unsigned long long pack2(float lo, float hi) {
    unsigned long long r;
    asm("mov.b64 %0, {%1, %2};" : "=l"(r) : "f"(lo), "f"(hi));
    return r;
}
__device__ __forceinline__ void unpack2(unsigned long long v, float& lo, float& hi) {
    asm("mov.b64 {%0, %1}, %2;" : "=f"(lo), "=f"(hi) : "l"(v));
}
__device__ __forceinline__ void ffma2(unsigned long long& d, unsigned long long a,
                                      unsigned long long b) {
    asm("fma.rn.f32x2 %0, %1, %2, %0;" : "+l"(d) : "l"(a), "l"(b));
}

// ---------------- K0: q,k,v projections ----------------
__global__ void k_qkv(const float* __restrict__ ef, const float* __restrict__ wq,
                      const float* __restrict__ wk, const float* __restrict__ wv) {
    __shared__ float row[HIDN];
    int i = blockIdx.x;
    int n = threadIdx.x;
    row[n] = ef[i * HIDN + n];
    __syncthreads();
    const float* W = (blockIdx.y == 0) ? wq : ((blockIdx.y == 1) ? wk : wv);
    float* O = (blockIdx.y == 0) ? g_q : ((blockIdx.y == 1) ? g_k : g_v);
    float acc = 0.f;
#pragma unroll 8
    for (int c = 0; c < HIDN; c++) acc += row[c] * W[c * HIDN + n];
    O[i * HIDN + n] = acc;
}

// ---------------- K0b: Aq/Ak precompute ----------------
__global__ void k_aqak(const float* __restrict__ w1) {
    __shared__ float row[HIDN];
    int i = blockIdx.x;
    int n = threadIdx.x;
    int sel = blockIdx.y;
    const float* src = sel ? g_k : g_q;
    float* dst = sel ? g_Ak : g_Aq;
    int roff = sel ? DHEAD : 0;
    row[n] = src[i * HIDN + n];
    __syncthreads();
    for (int h = 0; h < NHEAD; h++) {
        float acc = 0.f;
#pragma unroll
        for (int d = 0; d < DHEAD; d++)
            acc += row[h * DHEAD + d] * w1[(roff + d) * HIDN + n];
        dst[(h * EN + i) * HIDN + n] = acc;
    }
}

// ---------------- K0c: gates ----------------
__global__ void k_gates(const float* __restrict__ gw1, const float* __restrict__ gb1,
                        const float* __restrict__ gw2, const float* __restrict__ gb2) {
    __shared__ float vrow[DHEAD];
    __shared__ float red[HIDN];
    int j = blockIdx.x, h = blockIdx.y, n = threadIdx.x;
    if (n < DHEAD) vrow[n] = g_v[j * HIDN + h * DHEAD + n];
    __syncthreads();
    float acc = gb1[n];
#pragma unroll
    for (int d = 0; d < DHEAD; d++) acc += vrow[d] * gw1[d * HIDN + n];
    red[n] = siluf(acc) * gw2[n];
    __syncthreads();
    for (int s = 64; s > 0; s >>= 1) {
        if (n < s) red[n] += red[n + s];
        __syncthreads();
    }
    if (n == 0) g_gates[h * EN + j] = 1.0f / (1.0f + __expf(-(red[0] + gb2[0])));
}

// ---------------- K1: fused pair-MLP -> attention scores ----------------
// 512 threads. tx = tid&31 (4 cols), ty = tid>>5 = warp (8 pairs, one i per warp).
__device__ __forceinline__ void gemm_run(const float* __restrict__ A,
                                         const float* __restrict__ B, int K,
                                         int ty, int tx,
                                         unsigned long long acc[4][4]) {
    const float* ap = A + ty * 8;
    const float* bp = B + tx * 4;
#pragma unroll 2
    for (int c = 0; c < K; c++, ap += SW, bp += SW) {
        ulonglong2 a01 = *(const ulonglong2*)ap;          // broadcast within warp
        ulonglong2 a23 = *(const ulonglong2*)(ap + 4);
        unsigned long long av[4] = {a01.x, a01.y, a23.x, a23.y};
        float4 w = *(const float4*)bp;
        unsigned long long bd[4] = {pack2(w.x, w.x), pack2(w.y, w.y),
                                    pack2(w.z, w.z), pack2(w.w, w.w)};
#pragma unroll
        for (int pp = 0; pp < 4; pp++)
#pragma unroll
            for (int jj = 0; jj < 4; jj++) ffma2(acc[pp][jj], av[pp], bd[jj]);
    }
}

__global__ void __launch_bounds__(512, 1)
k_scores(const float* __restrict__ ec, const float* __restrict__ mask,
         const float* __restrict__ centers, const float* __restrict__ widths,
         const float* __restrict__ w1, const float* __restrict__ b1,
         const float* __restrict__ w2, const float* __restrict__ b2,
         const float* __restrict__ w3, const float* __restrict__ b3) {
    extern __shared__ float smem[];
    float* Ws = smem;                  // [128][SW]: W1_rbf rows, then W2
    float* As0 = Ws + 128 * SW;        // [128][SW]: rbf^T, then X1^T (even heads)
    float* As1 = As0 + 128 * SW;       // [128][SW]: X1^T (odd heads)
    float* dists = As1 + 128 * SW;     // 128
    float* dots = dists + 128;         // 128

    int tid = threadIdx.x;
    int tx = tid & 31, ty = tid >> 5;
    int bi = blockIdx.x, bj = blockIdx.y;
    int ig = bi * 16 + ty;

    // pair geometry
    if (tid < 128) {
        int p = tid;
        int i = bi * 16 + (p >> 3);
        int j = bj * 8 + (p & 7);
        float ix = ec[i * 3], iy = ec[i * 3 + 1], iz = ec[i * 3 + 2];
        float jx = ec[j * 3], jy = ec[j * 3 + 1], jz = ec[j * 3 + 2];
        float dx = ix - jx, dy = iy - jy, dz = iz - jz;
        float d = sqrtf(dx * dx + dy * dy + dz * dz) + 1e-8f;
        d = fminf(fmaxf(d, 1e-8f), 1e8f);
        dists[p] = d;
        float dt = ix * jx + iy * jy + iz * jz;
        dots[p] = fminf(fmaxf(dt, -1e8f), 1e8f);
    }
    // W1 rbf block (rows 32..95) -> Ws rows 0..63
    for (int idx = tid; idx < NRBF * HIDN / 4; idx += 512) {
        int r = idx >> 5, col = (idx & 31) * 4;
        *(float4*)(Ws + r * SW + col) = *(const float4*)(w1 + (2 * DHEAD + r) * HIDN + col);
    }
    __syncthreads();
    // rbf features, transposed [r][p] -> As0
    for (int idx = tid; idx < NRBF * 128; idx += 512) {
        int p = idx & 127, r = idx >> 7;
        float d = dists[p];
        float t = d - centers[r];
        As0[r * SW + p] = (d <= 10.0f) ? __expf(-widths[r] * t * t) : 0.0f;
    }
    __syncthreads();

    unsigned long long acc[4][4];
#pragma unroll
    for (int pp = 0; pp < 4; pp++)
#pragma unroll
        for (int jj = 0; jj < 4; jj++) acc[pp][jj] = 0ull;
    gemm_run(As0, Ws, NRBF, ty, tx, acc);

    // hpre = rbf@W1_rbf + dot*w1_dot + b1, kept in registers
    float hs[8][4];
    {
        float4 wdot = *(const float4*)(w1 + 96 * HIDN + tx * 4);
        float wd[4] = {wdot.x, wdot.y, wdot.z, wdot.w};
        float4 b1v = *(const float4*)(b1 + tx * 4);
        float b1r[4] = {b1v.x, b1v.y, b1v.z, b1v.w};
#pragma unroll
        for (int pp = 0; pp < 4; pp++) {
            float2 dp = *(const float2*)(dots + ty * 8 + 2 * pp);
#pragma unroll
            for (int jj = 0; jj < 4; jj++) {
                float lo, hi;
                unpack2(acc[pp][jj], lo, hi);
                hs[2 * pp][jj] = lo + dp.x * wd[jj] + b1r[jj];
                hs[2 * pp + 1][jj] = hi + dp.y * wd[jj] + b1r[jj];
            }
        }
    }
    __syncthreads();
    // W2 -> Ws
    for (int idx = tid; idx < HIDN * HIDN / 4; idx += 512) {
        int r = idx >> 5, col = (idx & 31) * 4;
        *(float4*)(Ws + r * SW + col) = *(const float4*)(w2 + r * HIDN + col);
    }

    float4 b2v = *(const float4*)(b2 + tx * 4);
    float b2r[4] = {b2v.x, b2v.y, b2v.z, b2v.w};

    // build X1(h=0) into As0
    {
        float4 aq = __ldg((const float4*)(g_Aq + (long)(0 * EN + ig) * HIDN + tx * 4));
        float aqr[4] = {aq.x, aq.y, aq.z, aq.w};
        float xs[4][8];
#pragma unroll
        for (int ii = 0; ii < 8; ii++) {
            float4 ak = __ldg((const float4*)(g_Ak + (long)(0 * EN + bj * 8 + ii) * HIDN + tx * 4));
            float akr[4] = {ak.x, ak.y, ak.z, ak.w};
#pragma unroll
            for (int jj = 0; jj < 4; jj++)
                xs[jj][ii] = silu_fast(hs[ii][jj] + aqr[jj] + akr[jj]);
        }
#pragma unroll
        for (int jj = 0; jj < 4; jj++) {
            float* dst = As0 + (tx * 4 + jj) * SW + ty * 8;
            *(float4*)dst = make_float4(xs[jj][0], xs[jj][1], xs[jj][2], xs[jj][3]);
            *(float4*)(dst + 4) = make_float4(xs[jj][4], xs[jj][5], xs[jj][6], xs[jj][7]);
        }
    }
    __syncthreads();

    for (int h = 0; h < NHEAD; h++) {
        float* Ar = (h & 1) ? As1 : As0;
        float* Aw = (h & 1) ? As0 : As1;
#pragma unroll
        for (int pp = 0; pp < 4; pp++)
#pragma unroll
            for (int jj = 0; jj < 4; jj++) acc[pp][jj] = 0ull;
        gemm_run(Ar, Ws, HIDN, ty, tx, acc);

        // epilogue: exact silu + w3 column reduce across warp
        float w3r[4];
#pragma unroll
        for (int jj = 0; jj < 4; jj++) w3r[jj] = __ldg(w3 + (tx * 4 + jj) * NHEAD + h);
        float ps[8];
#pragma unroll
        for (int pp = 0; pp < 4; pp++) {
            float slo = 0.f, shi = 0.f;
#pragma unroll
            for (int jj = 0; jj < 4; jj++) {
                float lo, hi;
                unpack2(acc[pp][jj], lo, hi);
                slo += siluf(lo + b2r[jj]) * w3r[jj];
                shi += siluf(hi + b2r[jj]) * w3r[jj];
            }
            ps[2 * pp] = slo;
            ps[2 * pp + 1] = shi;
        }
#pragma unroll
        for (int off = 1; off < 32; off <<= 1) {
#pragma unroll
            for (int ii = 0; ii < 8; ii++)
                ps[ii] += __shfl_xor_sync(0xffffffffu, ps[ii], off);
        }
        if (tx == 0) {
            float bb = b3[h];
            const float* mrow = mask + (long)ig * EN + bj * 8;
            float* srow = g_scores + ((long)(h * EN + ig)) * EN + bj * 8;
            float4 m0 = __ldg((const float4*)mrow);
            float4 m1 = __ldg((const float4*)(mrow + 4));
            float4 o0, o1;
            o0.x = fminf(fmaxf(ps[0] + bb + m0.x, -1e9f), 1e9f);
            o0.y = fminf(fmaxf(ps[1] + bb + m0.y, -1e9f), 1e9f);
            o0.z = fminf(fmaxf(ps[2] + bb + m0.z, -1e9f), 1e9f);
            o0.w = fminf(fmaxf(ps[3] + bb + m0.w, -1e9f), 1e9f);
            o1.x = fminf(fmaxf(ps[4] + bb + m1.x, -1e9f), 1e9f);
            o1.y = fminf(fmaxf(ps[5] + bb + m1.y, -1e9f), 1e9f);
            o1.z = fminf(fmaxf(ps[6] + bb + m1.z, -1e9f), 1e9f);
            o1.w = fminf(fmaxf(ps[7] + bb + m1.w, -1e9f), 1e9f);
            *(float4*)srow = o0;
            *(float4*)(srow + 4) = o1;
        }

        // build X1(h+1) into the other buffer (fast silu)
        if (h < NHEAD - 1) {
            int hh = h + 1;
            float4 aq = __ldg((const float4*)(g_Aq + (long)(hh * EN + ig) * HIDN + tx * 4));
            float aqr[4] = {aq.x, aq.y, aq.z, aq.w};
            float xs[4][8];
#pragma unroll
            for (int ii = 0; ii < 8; ii++) {
                float4 ak = __ldg((const float4*)(g_Ak + (long)(hh * EN + bj * 8 + ii) * HIDN + tx * 4));
                float akr[4] = {ak.x, ak.y, ak.z, ak.w};
#pragma unroll
                for (int jj = 0; jj < 4; jj++)
                    xs[jj][ii] = silu_fast(hs[ii][jj] + aqr[jj] + akr[jj]);
            }
#pragma unroll
            for (int jj = 0; jj < 4; jj++) {
                float* dst = Aw + (tx * 4 + jj) * SW + ty * 8;
                *(float4*)dst = make_float4(xs[jj][0], xs[jj][1], xs[jj][2], xs[jj][3]);
                *(float4*)(dst + 4) = make_float4(xs[jj][4], xs[jj][5], xs[jj][6], xs[jj][7]);
            }
        }
        __syncthreads();
    }
}

// ---------------- K2: softmax + attn@V + coord delta ----------------
__global__ void k_softmax(const float* __restrict__ ec) {
    __shared__ float expv[EN];
    __shared__ float red[128];
    __shared__ float wred[4][20];
    __shared__ float fin[4];
    int i = blockIdx.x, h = blockIdx.y, t = threadIdx.x;
    const float* srow = &g_scores[(h * EN + i) * EN];

    float mx = -1e30f;
    for (int j = t; j < EN; j += 128) mx = fmaxf(mx, srow[j]);
    red[t] = mx;
    __syncthreads();
    for (int s = 64; s > 0; s >>= 1) {
        if (t < s) red[t] = fmaxf(red[t], red[t + s]);
        __syncthreads();
    }
    mx = red[0];
    __syncthreads();
    float sum = 0.f;
    for (int j = t; j < EN; j += 128) {
        float e = __expf(srow[j] - mx);
        expv[j] = e;
        sum += e;
    }
    red[t] = sum;
    __syncthreads();
    for (int s = 64; s > 0; s >>= 1) {
        if (t < s) red[t] += red[t + s];
        __syncthreads();
    }
    float inv = 1.0f / red[0];

    float vals[20];
#pragma unroll
    for (int q = 0; q < 20; q++) vals[q] = 0.f;
    for (int j = t; j < EN; j += 128) {
        float a = expv[j] * inv;
        const float* vr = &g_v[j * HIDN + h * DHEAD];
#pragma unroll
        for (int d = 0; d < DHEAD; d++) vals[d] += a * vr[d];
        vals[16] += a;
        vals[17] += a * ec[j * 3];
        vals[18] += a * ec[j * 3 + 1];
        vals[19] += a * ec[j * 3 + 2];
    }
#pragma unroll
    for (int off = 16; off > 0; off >>= 1)
#pragma unroll
        for (int q = 0; q < 20; q++)
            vals[q] += __shfl_xor_sync(0xffffffffu, vals[q], off);
    int lane = t & 31, warp = t >> 5;
    if (lane == 0)
#pragma unroll
        for (int q = 0; q < 20; q++) wred[warp][q] = vals[q];
    __syncthreads();
    if (t < 20) {
        float s = wred[0][t] + wred[1][t] + wred[2][t] + wred[3][t];
        if (t < 16) g_upd[i * HIDN + h * DHEAD + t] = s;
        else fin[t - 16] = s;
    }
    __syncthreads();
    if (t < 3) {
        float gate = g_gates[h * EN + i];
        g_delta[(h * EN + i) * 3 + t] = gate * (fin[0] * ec[i * 3 + t] - fin[1 + t]);
    }
}

// ---------------- K3: output projection + layernorm + coords ----------------
__global__ void k_out(const float* __restrict__ ef, const float* __restrict__ ec,
                      const float* __restrict__ wo, const float* __restrict__ bo,
                      const float* __restrict__ lg, const float* __restrict__ lb,
                      float* __restrict__ out) {
    __shared__ float u[HIDN];
    __shared__ float red[128];
    int i = blockIdx.x, n = threadIdx.x;
    u[n] = g_upd[i * HIDN + n];
    __syncthreads();
    float y = ef[i * HIDN + n] + bo[n];
#pragma unroll 8
    for (int c = 0; c < HIDN; c++) y += u[c] * wo[c * HIDN + n];
    red[n] = y;
    __syncthreads();
    for (int s = 64; s > 0; s >>= 1) {
        if (n < s) red[n] += red[n + s];
        __syncthreads();
    }
    float mean = red[0] * (1.0f / HIDN);
    __syncthreads();
    float dy = y - mean;
    red[n] = dy * dy;
    __syncthreads();
    for (int s = 64; s > 0; s >>= 1) {
        if (n < s) red[n] += red[n + s];
        __syncthreads();
    }
    float var = red[0] * (1.0f / HIDN);
    float rstd = rsqrtf(var + 1e-5f);
    out[i * HIDN + n] = dy * rstd * lg[n] + lb[n];
    if (n < 3) {
        float dsum = 0.f;
#pragma unroll
        for (int h = 0; h < NHEAD; h++) dsum += g_delta[(h * EN + i) * 3 + n];
        out[EN * HIDN + i * 3 + n] = ec[i * 3 + n] + dsum * 0.125f;
    }
}

// ---------------- launcher ----------------
extern "C" void kernel_launch(void* const* d_in, const int* in_sizes, int n_in,
                              void* d_out, int out_size) {
    const float* ef      = (const float*)d_in[0];
    const float* ec      = (const float*)d_in[1];
    const float* mask    = (const float*)d_in[2];
    const float* wq      = (const float*)d_in[3];
    const float* wk      = (const float*)d_in[4];
    const float* wv      = (const float*)d_in[5];
    const float* centers = (const float*)d_in[6];
    const float* widths  = (const float*)d_in[7];
    const float* a_w1    = (const float*)d_in[8];
    const float* a_b1    = (const float*)d_in[9];
    const float* a_w2    = (const float*)d_in[10];
    const float* a_b2    = (const float*)d_in[11];
    const float* a_w3    = (const float*)d_in[12];
    const float* a_b3    = (const float*)d_in[13];
    const float* g_w1    = (const float*)d_in[14];
    const float* g_b1    = (const float*)d_in[15];
    const float* g_w2    = (const float*)d_in[16];
    const float* g_b2    = (const float*)d_in[17];
    const float* wo      = (const float*)d_in[18];
    const float* bo      = (const float*)d_in[19];
    const float* ln_g    = (const float*)d_in[20];
    const float* ln_b    = (const float*)d_in[21];
    float* out = (float*)d_out;

    cudaFuncSetAttribute(k_scores, cudaFuncAttributeMaxDynamicSharedMemorySize,
                         SMEM_BYTES);

    k_qkv<<<dim3(EN, 3), HIDN>>>(ef, wq, wk, wv);
    k_aqak<<<dim3(EN, 2), HIDN>>>(a_w1);
    k_gates<<<dim3(EN, NHEAD), HIDN>>>(g_w1, g_b1, g_w2, g_b2);
    k_scores<<<dim3(EN / 16, EN / 8), 512, SMEM_BYTES>>>(
        ec, mask, centers, widths, a_w1, a_b1, a_w2, a_b2, a_w3, a_b3);
    k_softmax<<<dim3(EN, NHEAD), HIDN>>>(ec);
    k_out<<<EN, HIDN>>>(ef, ec, wo, bo, ln_g, ln_b, out);
}

// round 6
// speedup vs baseline: 3.0122x; 1.7650x over previous
#include <cuda_runtime.h>
#include <math.h>
#include <stdint.h>

#define EN 384
#define HIDN 128
#define NHEAD 8
#define DHEAD 16
#define NRBF 64

static constexpr int SW = 132;    // fp32 staging row stride (floats)
static constexpr int HS = 132;    // HPRE row stride (floats), 16B-aligned
static constexpr int XROW = 272;  // bf16 tile row stride (bytes): 128*2 + 16 pad

// ---- smem byte-offset map (dynamic smem, 1024-aligned base) ----
static constexpr int OFF_X1HI = 0;        // 128*272 = 34816   (rbf phase: rWs 33792)
static constexpr int OFF_X1LO = 34816;    // 34816            (rbf phase: rAs 33792)
static constexpr int OFF_W2HI = 69632;    // 34816
static constexpr int OFF_W2LO = 104448;   // 34816
static constexpr int OFF_HPRE = 139264;   // 128*132*4 = 67584 -> ends 206848
static constexpr int OFF_SRED = 206848;   // 4*128*4 = 2048
static constexpr int OFF_B2S  = 208896;   // 512
static constexpr int OFF_W3S  = 209408;   // 128*8*4 = 4096
static constexpr int OFF_DISTS= 213504;   // 512
static constexpr int OFF_DOTS = 214016;   // 512
static constexpr int SMEM_BYTES = 214528;

// ---------------- device scratch ----------------
__device__ float g_q[EN * HIDN];
__device__ float g_k[EN * HIDN];
__device__ float g_v[EN * HIDN];
__device__ float g_Aq[NHEAD * EN * HIDN];
__device__ float g_Ak[NHEAD * EN * HIDN];
__device__ float g_gates[NHEAD * EN];
__device__ float g_scores[NHEAD * EN * EN];
__device__ float g_upd[EN * HIDN];
__device__ float g_delta[NHEAD * EN * 3];

__device__ __forceinline__ float siluf(float x) {
    return __fdividef(x, 1.0f + __expf(-x));
}
__device__ __forceinline__ float silu_fast(float x) {
    float t;
    asm("tanh.approx.f32 %0, %1;" : "=f"(t) : "f"(x * 0.5f));
    return fmaf(x, 0.5f * t, 0.5f * x);
}
__device__ __forceinline__ unsigned long long pack2(float lo, float hi) {
    unsigned long long r;
    asm("mov.b64 %0, {%1, %2};" : "=l"(r) : "f"(lo), "f"(hi));
    return r;
}
__device__ __forceinline__ void unpack2(unsigned long long v, float& lo, float& hi) {
    asm("mov.b64 {%0, %1}, %2;" : "=f"(lo), "=f"(hi) : "l"(v));
}
__device__ __forceinline__ void ffma2(unsigned long long& d, unsigned long long a,
                                      unsigned long long b) {
    asm("fma.rn.f32x2 %0, %1, %2, %0;" : "+l"(d) : "l"(a), "l"(b));
}
// pack two fp32 -> bf16x2 (RN); second value -> high half
__device__ __forceinline__ uint32_t bf16pair(float x0, float x1) {
    uint32_t u;
    asm("cvt.rn.bf16x2.f32 %0, %1, %2;" : "=r"(u) : "f"(x1), "f"(x0));
    return u;
}
__device__ __forceinline__ float bf_lowf(uint32_t u) { return __uint_as_float(u << 16); }
__device__ __forceinline__ float bf_highf(uint32_t u) { return __uint_as_float(u & 0xFFFF0000u); }

__device__ __forceinline__ uint32_t smem_u32(const void* p) {
    uint32_t a;
    asm("{ .reg .u64 t; cvta.to.shared.u64 t, %1; cvt.u32.u64 %0, t; }" : "=r"(a) : "l"(p));
    return a;
}

// ---- HMMA path (compute_103-legal) ----
__device__ __forceinline__ void ldsm_x4(uint32_t* r, uint32_t addr) {
    asm volatile("ldmatrix.sync.aligned.m8n8.x4.shared.b16 {%0,%1,%2,%3}, [%4];"
                 : "=r"(r[0]), "=r"(r[1]), "=r"(r[2]), "=r"(r[3]) : "r"(addr));
}
__device__ __forceinline__ void ldsm_x4t(uint32_t* r, uint32_t addr) {
    asm volatile("ldmatrix.sync.aligned.m8n8.x4.trans.shared.b16 {%0,%1,%2,%3}, [%4];"
                 : "=r"(r[0]), "=r"(r[1]), "=r"(r[2]), "=r"(r[3]) : "r"(addr));
}
__device__ __forceinline__ void mma_bf16(float* d, const uint32_t* a, uint32_t b0, uint32_t b1) {
    asm volatile(
        "mma.sync.aligned.m16n8k16.row.col.f32.bf16.bf16.f32 "
        "{%0,%1,%2,%3}, {%4,%5,%6,%7}, {%8,%9}, {%0,%1,%2,%3};"
        : "+f"(d[0]), "+f"(d[1]), "+f"(d[2]), "+f"(d[3])
        : "r"(a[0]), "r"(a[1]), "r"(a[2]), "r"(a[3]), "r"(b0), "r"(b1));
}

// ---------------- K0: q,k,v projections ----------------
__global__ void k_qkv(const float* __restrict__ ef, const float* __restrict__ wq,
                      const float* __restrict__ wk, const float* __restrict__ wv) {
    __shared__ float row[HIDN];
    int i = blockIdx.x;
    int n = threadIdx.x;
    row[n] = ef[i * HIDN + n];
    __syncthreads();
    const float* W = (blockIdx.y == 0) ? wq : ((blockIdx.y == 1) ? wk : wv);
    float* O = (blockIdx.y == 0) ? g_q : ((blockIdx.y == 1) ? g_k : g_v);
    float acc = 0.f;
#pragma unroll 8
    for (int c = 0; c < HIDN; c++) acc += row[c] * W[c * HIDN + n];
    O[i * HIDN + n] = acc;
}

// ---------------- K0b: Aq/Ak precompute ----------------
__global__ void k_aqak(const float* __restrict__ w1) {
    __shared__ float row[HIDN];
    int i = blockIdx.x;
    int n = threadIdx.x;
    int sel = blockIdx.y;
    const float* src = sel ? g_k : g_q;
    float* dst = sel ? g_Ak : g_Aq;
    int roff = sel ? DHEAD : 0;
    row[n] = src[i * HIDN + n];
    __syncthreads();
    for (int h = 0; h < NHEAD; h++) {
        float acc = 0.f;
#pragma unroll
        for (int d = 0; d < DHEAD; d++)
            acc += row[h * DHEAD + d] * w1[(roff + d) * HIDN + n];
        dst[(h * EN + i) * HIDN + n] = acc;
    }
}

// ---------------- K0c: gates ----------------
__global__ void k_gates(const float* __restrict__ gw1, const float* __restrict__ gb1,
                        const float* __restrict__ gw2, const float* __restrict__ gb2) {
    __shared__ float vrow[DHEAD];
    __shared__ float red[HIDN];
    int j = blockIdx.x, h = blockIdx.y, n = threadIdx.x;
    if (n < DHEAD) vrow[n] = g_v[j * HIDN + h * DHEAD + n];
    __syncthreads();
    float acc = gb1[n];
#pragma unroll
    for (int d = 0; d < DHEAD; d++) acc += vrow[d] * gw1[d * HIDN + n];
    red[n] = siluf(acc) * gw2[n];
    __syncthreads();
    for (int s = 64; s > 0; s >>= 1) {
        if (n < s) red[n] += red[n + s];
        __syncthreads();
    }
    if (n == 0) g_gates[h * EN + j] = 1.0f / (1.0f + __expf(-(red[0] + gb2[0])));
}

// ---------------- FFMA2 register-tile GEMM (rbf layer only) ----------------
__device__ __forceinline__ void gemm_run(const float* __restrict__ A,
                                         const float* __restrict__ B, int K,
                                         int ty, int tx,
                                         unsigned long long acc[4][4]) {
    const float* ap = A + ty * 8;
    const float* bp = B + tx * 4;
#pragma unroll 2
    for (int c = 0; c < K; c++, ap += SW, bp += SW) {
        ulonglong2 a01 = *(const ulonglong2*)ap;
        ulonglong2 a23 = *(const ulonglong2*)(ap + 4);
        unsigned long long av[4] = {a01.x, a01.y, a23.x, a23.y};
        float4 w = *(const float4*)bp;
        unsigned long long bd[4] = {pack2(w.x, w.x), pack2(w.y, w.y),
                                    pack2(w.z, w.z), pack2(w.w, w.w)};
#pragma unroll
        for (int pp = 0; pp < 4; pp++)
#pragma unroll
            for (int jj = 0; jj < 4; jj++) ffma2(acc[pp][jj], av[pp], bd[jj]);
    }
}

// ---------------- K1: fused pair-MLP -> attention scores (HMMA W2 GEMM) ----------------
__global__ void __launch_bounds__(512, 1)
k_scores(const float* __restrict__ ec, const float* __restrict__ mask,
         const float* __restrict__ centers, const float* __restrict__ widths,
         const float* __restrict__ w1, const float* __restrict__ b1,
         const float* __restrict__ w2, const float* __restrict__ b2,
         const float* __restrict__ w3, const float* __restrict__ b3) {
    extern __shared__ float smem_f[];
    char* smem_c = (char*)smem_f;
    float* rWs   = (float*)(smem_c + OFF_X1HI);   // overlay: rbf weights (dead after hpre)
    float* rAs   = (float*)(smem_c + OFF_X1LO);   // overlay: rbf feats (dead after hpre)
    float* HPRE  = (float*)(smem_c + OFF_HPRE);
    float* SRED  = (float*)(smem_c + OFF_SRED);
    float* B2S   = (float*)(smem_c + OFF_B2S);
    float* W3S   = (float*)(smem_c + OFF_W3S);
    float* dists = (float*)(smem_c + OFF_DISTS);
    float* dots  = (float*)(smem_c + OFF_DOTS);

    uint32_t sbase = smem_u32(smem_c);

    int tid = threadIdx.x;
    int w = tid >> 5, lane = tid & 31;
    int tx = lane, ty = w;                 // rbf-gemm mapping
    int bi = blockIdx.x, bj = blockIdx.y;

    // build mapping: thread owns pair p, channel-interleave lq
    int p = tid >> 2;                      // 0..127
    int lq = tid & 3;
    int ig_p = bi * 16 + (p >> 3);
    int jg_p = bj * 8 + (p & 7);

    // ---- pair geometry ----
    if (tid < 128) {
        int pp = tid;
        int i = bi * 16 + (pp >> 3);
        int j = bj * 8 + (pp & 7);
        float ix = ec[i * 3], iy = ec[i * 3 + 1], iz = ec[i * 3 + 2];
        float jx = ec[j * 3], jy = ec[j * 3 + 1], jz = ec[j * 3 + 2];
        float dx = ix - jx, dy = iy - jy, dz = iz - jz;
        float d = sqrtf(dx * dx + dy * dy + dz * dz) + 1e-8f;
        d = fminf(fmaxf(d, 1e-8f), 1e8f);
        dists[pp] = d;
        float dt = ix * jx + iy * jy + iz * jz;
        dots[pp] = fminf(fmaxf(dt, -1e8f), 1e8f);
    }
    // ---- W1 rbf rows -> rWs ----
    for (int idx = tid; idx < NRBF * HIDN / 4; idx += 512) {
        int r = idx >> 5, col = (idx & 31) * 4;
        *(float4*)(rWs + r * SW + col) = *(const float4*)(w1 + (2 * DHEAD + r) * HIDN + col);
    }
    // ---- W2 -> bf16 hi/lo planes [c][n], row stride XROW ----
    for (int idx = tid; idx < HIDN * HIDN; idx += 512) {
        int c = idx >> 7;
        int n = idx & 127;
        float wv = w2[idx];
        uint32_t hb = bf16pair(wv, 0.0f) & 0xFFFFu;
        float rv = wv - __uint_as_float(hb << 16);
        uint32_t lb = bf16pair(rv, 0.0f) & 0xFFFFu;
        *(unsigned short*)(smem_c + OFF_W2HI + c * XROW + n * 2) = (unsigned short)hb;
        *(unsigned short*)(smem_c + OFF_W2LO + c * XROW + n * 2) = (unsigned short)lb;
    }
    // ---- b2, w3 ----
    if (tid < 128) B2S[tid] = b2[tid];
    for (int idx = tid; idx < HIDN * NHEAD; idx += 512) W3S[idx] = w3[idx];
    __syncthreads();

    // ---- rbf features [r][p] -> rAs ----
    for (int idx = tid; idx < NRBF * 128; idx += 512) {
        int pp = idx & 127, r = idx >> 7;
        float d = dists[pp];
        float t = d - centers[r];
        rAs[r * SW + pp] = (d <= 10.0f) ? __expf(-widths[r] * t * t) : 0.0f;
    }
    __syncthreads();

    // ---- hpre = rbf @ W1_rbf + dot*w1_dot + b1 -> HPRE[p][c] ----
    {
        unsigned long long acc[4][4];
#pragma unroll
        for (int pp2 = 0; pp2 < 4; pp2++)
#pragma unroll
            for (int jj = 0; jj < 4; jj++) acc[pp2][jj] = 0ull;
        gemm_run(rAs, rWs, NRBF, ty, tx, acc);
        float4 wdot = *(const float4*)(w1 + 96 * HIDN + tx * 4);
        float wd[4] = {wdot.x, wdot.y, wdot.z, wdot.w};
        float4 b1v = *(const float4*)(b1 + tx * 4);
        float b1r[4] = {b1v.x, b1v.y, b1v.z, b1v.w};
#pragma unroll
        for (int pp2 = 0; pp2 < 4; pp2++) {
            float2 dp = *(const float2*)(dots + ty * 8 + 2 * pp2);
#pragma unroll
            for (int jj = 0; jj < 4; jj++) {
                float lo, hi;
                unpack2(acc[pp2][jj], lo, hi);
                int c = tx * 4 + jj;
                HPRE[(ty * 8 + 2 * pp2) * HS + c] = lo + dp.x * wd[jj] + b1r[jj];
                HPRE[(ty * 8 + 2 * pp2 + 1) * HS + c] = hi + dp.y * wd[jj] + b1r[jj];
            }
        }
    }
    __syncthreads();   // HPRE done; rWs/rAs dead -> X1 planes may overwrite

    // ---- HMMA tiling constants ----
    int mb = w & 3, nb = w >> 2;
    int r16 = lane & 15, rh = lane >> 4;
    uint32_t aHi = sbase + OFF_X1HI + (uint32_t)(32 * mb + r16) * XROW + rh * 16;
    uint32_t aLo = sbase + OFF_X1LO + (uint32_t)(32 * mb + r16) * XROW + rh * 16;
    uint32_t bHi = sbase + OFF_W2HI + (uint32_t)r16 * XROW + 64 * nb + 16 * rh;
    uint32_t bLo = sbase + OFF_W2LO + (uint32_t)r16 * XROW + 64 * nb + 16 * rh;

    const float* hp = HPRE + p * HS;
    char* x1h = smem_c + OFF_X1HI + p * XROW;
    char* x1l = smem_c + OFF_X1LO + p * XROW;

    for (int h = 0; h < NHEAD; h++) {
        // ---- build X1(h): bf16 hi/lo planes ----
        {
            const float* aqp = g_Aq + ((long)(h * EN + ig_p)) * HIDN;
            const float* akp = g_Ak + ((long)(h * EN + jg_p)) * HIDN;
#pragma unroll
            for (int q = 0; q < 8; q++) {
                int c = lq * 4 + 16 * q;
                float4 hv = *(const float4*)(hp + c);
                float4 aq = __ldg((const float4*)(aqp + c));
                float4 ak = __ldg((const float4*)(akp + c));
                float x0 = silu_fast(hv.x + aq.x + ak.x);
                float x1 = silu_fast(hv.y + aq.y + ak.y);
                float x2 = silu_fast(hv.z + aq.z + ak.z);
                float x3 = silu_fast(hv.w + aq.w + ak.w);
                uint32_t u0 = bf16pair(x0, x1);
                uint32_t u1 = bf16pair(x2, x3);
                uint32_t l0 = bf16pair(x0 - bf_lowf(u0), x1 - bf_highf(u0));
                uint32_t l1 = bf16pair(x2 - bf_lowf(u1), x3 - bf_highf(u1));
                *(uint2*)(x1h + c * 2) = make_uint2(u0, u1);
                *(uint2*)(x1l + c * 2) = make_uint2(l0, l1);
            }
        }
        __syncthreads();   // X1 ready

        // ---- W2 GEMM via HMMA, 3-pass hi/lo ----
        float acc[2][4][4];
#pragma unroll
        for (int mi = 0; mi < 2; mi++)
#pragma unroll
            for (int ni = 0; ni < 4; ni++)
#pragma unroll
                for (int e = 0; e < 4; e++) acc[mi][ni][e] = 0.f;

#pragma unroll
        for (int kk = 0; kk < 8; kk++) {
            uint32_t kab = (uint32_t)kk * 32;          // A col bytes
            uint32_t kbb = (uint32_t)kk * 16 * XROW;   // B row bytes
            uint32_t ah[2][4], al[2][4], bh[2][4], bl[2][4];
            ldsm_x4(ah[0], aHi + kab);
            ldsm_x4(ah[1], aHi + 16 * XROW + kab);
            ldsm_x4(al[0], aLo + kab);
            ldsm_x4(al[1], aLo + 16 * XROW + kab);
            ldsm_x4t(bh[0], bHi + kbb);
            ldsm_x4t(bh[1], bHi + kbb + 32);
            ldsm_x4t(bl[0], bLo + kbb);
            ldsm_x4t(bl[1], bLo + kbb + 32);
#pragma unroll
            for (int mi = 0; mi < 2; mi++)
#pragma unroll
                for (int bx = 0; bx < 2; bx++)
#pragma unroll
                    for (int hf = 0; hf < 2; hf++) {
                        int ni = 2 * bx + hf;
                        mma_bf16(acc[mi][ni], ah[mi], bh[bx][2 * hf], bh[bx][2 * hf + 1]);
                        mma_bf16(acc[mi][ni], ah[mi], bl[bx][2 * hf], bl[bx][2 * hf + 1]);
                        mma_bf16(acc[mi][ni], al[mi], bh[bx][2 * hf], bh[bx][2 * hf + 1]);
                    }
        }

        // ---- epilogue: silu + w3 reduce ----
        {
            int colq = 2 * (lane & 3);
            float s[2][2];
            s[0][0] = s[0][1] = s[1][0] = s[1][1] = 0.f;
#pragma unroll
            for (int ni = 0; ni < 4; ni++) {
                int col = 32 * nb + 8 * ni + colq;
                float b2a = B2S[col], b2b = B2S[col + 1];
                float w3a = W3S[col * NHEAD + h], w3b = W3S[(col + 1) * NHEAD + h];
#pragma unroll
                for (int mi = 0; mi < 2; mi++) {
                    s[mi][0] += siluf(acc[mi][ni][0] + b2a) * w3a +
                                siluf(acc[mi][ni][1] + b2b) * w3b;
                    s[mi][1] += siluf(acc[mi][ni][2] + b2a) * w3a +
                                siluf(acc[mi][ni][3] + b2b) * w3b;
                }
            }
#pragma unroll
            for (int off = 1; off < 4; off <<= 1) {
#pragma unroll
                for (int mi = 0; mi < 2; mi++) {
                    s[mi][0] += __shfl_xor_sync(0xffffffffu, s[mi][0], off);
                    s[mi][1] += __shfl_xor_sync(0xffffffffu, s[mi][1], off);
                }
            }
            if ((lane & 3) == 0) {
                int r0 = 32 * mb + (lane >> 2);
#pragma unroll
                for (int mi = 0; mi < 2; mi++) {
                    SRED[nb * 128 + r0 + 16 * mi] = s[mi][0];
                    SRED[nb * 128 + r0 + 16 * mi + 8] = s[mi][1];
                }
            }
        }
        __syncthreads();   // SRED complete; gemm loads done -> X1 reusable

        if (tid < 128) {
            int p2 = tid;
            float tot = SRED[p2] + SRED[128 + p2] + SRED[256 + p2] + SRED[384 + p2];
            int igw = bi * 16 + (p2 >> 3), jgw = bj * 8 + (p2 & 7);
            float sc = tot + b3[h] + mask[(long)igw * EN + jgw];
            sc = fminf(fmaxf(sc, -1e9f), 1e9f);
            g_scores[((long)h * EN + igw) * EN + jgw] = sc;
        }
        // no sync needed: score-write reads SRED; next build writes X1 (disjoint);
        // SRED next written only after the next __syncthreads().
    }
}

// ---------------- K2: softmax + attn@V + coord delta ----------------
__global__ void k_softmax(const float* __restrict__ ec) {
    __shared__ float expv[EN];
    __shared__ float red[128];
    __shared__ float wred[4][20];
    __shared__ float fin[4];
    int i = blockIdx.x, h = blockIdx.y, t = threadIdx.x;
    const float* srow = &g_scores[(h * EN + i) * EN];

    float mx = -1e30f;
    for (int j = t; j < EN; j += 128) mx = fmaxf(mx, srow[j]);
    red[t] = mx;
    __syncthreads();
    for (int s = 64; s > 0; s >>= 1) {
        if (t < s) red[t] = fmaxf(red[t], red[t + s]);
        __syncthreads();
    }
    mx = red[0];
    __syncthreads();
    float sum = 0.f;
    for (int j = t; j < EN; j += 128) {
        float e = __expf(srow[j] - mx);
        expv[j] = e;
        sum += e;
    }
    red[t] = sum;
    __syncthreads();
    for (int s = 64; s > 0; s >>= 1) {
        if (t < s) red[t] += red[t + s];
        __syncthreads();
    }
    float inv = 1.0f / red[0];

    float vals[20];
#pragma unroll
    for (int q = 0; q < 20; q++) vals[q] = 0.f;
    for (int j = t; j < EN; j += 128) {
        float a = expv[j] * inv;
        const float* vr = &g_v[j * HIDN + h * DHEAD];
#pragma unroll
        for (int d = 0; d < DHEAD; d++) vals[d] += a * vr[d];
        vals[16] += a;
        vals[17] += a * ec[j * 3];
        vals[18] += a * ec[j * 3 + 1];
        vals[19] += a * ec[j * 3 + 2];
    }
#pragma unroll
    for (int off = 16; off > 0; off >>= 1)
#pragma unroll
        for (int q = 0; q < 20; q++)
            vals[q] += __shfl_xor_sync(0xffffffffu, vals[q], off);
    int lane = t & 31, warp = t >> 5;
    if (lane == 0)
#pragma unroll
        for (int q = 0; q < 20; q++) wred[warp][q] = vals[q];
    __syncthreads();
    if (t < 20) {
        float s = wred[0][t] + wred[1][t] + wred[2][t] + wred[3][t];
        if (t < 16) g_upd[i * HIDN + h * DHEAD + t] = s;
        else fin[t - 16] = s;
    }
    __syncthreads();
    if (t < 3) {
        float gate = g_gates[h * EN + i];
        g_delta[(h * EN + i) * 3 + t] = gate * (fin[0] * ec[i * 3 + t] - fin[1 + t]);
    }
}

// ---------------- K3: output projection + layernorm + coords ----------------
__global__ void k_out(const float* __restrict__ ef, const float* __restrict__ ec,
                      const float* __restrict__ wo, const float* __restrict__ bo,
                      const float* __restrict__ lg, const float* __restrict__ lb,
                      float* __restrict__ out) {
    __shared__ float u[HIDN];
    __shared__ float red[128];
    int i = blockIdx.x, n = threadIdx.x;
    u[n] = g_upd[i * HIDN + n];
    __syncthreads();
    float y = ef[i * HIDN + n] + bo[n];
#pragma unroll 8
    for (int c = 0; c < HIDN; c++) y += u[c] * wo[c * HIDN + n];
    red[n] = y;
    __syncthreads();
    for (int s = 64; s > 0; s >>= 1) {
        if (n < s) red[n] += red[n + s];
        __syncthreads();
    }
    float mean = red[0] * (1.0f / HIDN);
    __syncthreads();
    float dy = y - mean;
    red[n] = dy * dy;
    __syncthreads();
    for (int s = 64; s > 0; s >>= 1) {
        if (n < s) red[n] += red[n + s];
        __syncthreads();
    }
    float var = red[0] * (1.0f / HIDN);
    float rstd = rsqrtf(var + 1e-5f);
    out[i * HIDN + n] = dy * rstd * lg[n] + lb[n];
    if (n < 3) {
        float dsum = 0.f;
#pragma unroll
        for (int h = 0; h < NHEAD; h++) dsum += g_delta[(h * EN + i) * 3 + n];
        out[EN * HIDN + i * 3 + n] = ec[i * 3 + n] + dsum * 0.125f;
    }
}

// ---------------- launcher ----------------
extern "C" void kernel_launch(void* const* d_in, const int* in_sizes, int n_in,
                              void* d_out, int out_size) {
    const float* ef      = (const float*)d_in[0];
    const float* ec      = (const float*)d_in[1];
    const float* mask    = (const float*)d_in[2];
    const float* wq      = (const float*)d_in[3];
    const float* wk      = (const float*)d_in[4];
    const float* wv      = (const float*)d_in[5];
    const float* centers = (const float*)d_in[6];
    const float* widths  = (const float*)d_in[7];
    const float* a_w1    = (const float*)d_in[8];
    const float* a_b1    = (const float*)d_in[9];
    const float* a_w2    = (const float*)d_in[10];
    const float* a_b2    = (const float*)d_in[11];
    const float* a_w3    = (const float*)d_in[12];
    const float* a_b3    = (const float*)d_in[13];
    const float* g_w1    = (const float*)d_in[14];
    const float* g_b1    = (const float*)d_in[15];
    const float* g_w2    = (const float*)d_in[16];
    const float* g_b2    = (const float*)d_in[17];
    const float* wo      = (const float*)d_in[18];
    const float* bo      = (const float*)d_in[19];
    const float* ln_g    = (const float*)d_in[20];
    const float* ln_b    = (const float*)d_in[21];
    float* out = (float*)d_out;

    cudaFuncSetAttribute(k_scores, cudaFuncAttributeMaxDynamicSharedMemorySize,
                         SMEM_BYTES);

    k_qkv<<<dim3(EN, 3), HIDN>>>(ef, wq, wk, wv);
    k_aqak<<<dim3(EN, 2), HIDN>>>(a_w1);
    k_gates<<<dim3(EN, NHEAD), HIDN>>>(g_w1, g_b1, g_w2, g_b2);
    k_scores<<<dim3(EN / 16, EN / 8), 512, SMEM_BYTES>>>(
        ec, mask, centers, widths, a_w1, a_b1, a_w2, a_b2, a_w3, a_b3);
    k_softmax<<<dim3(EN, NHEAD), HIDN>>>(ec);
    k_out<<<EN, HIDN>>>(ef, ec, wo, bo, ln_g, ln_b, out);
}

// round 7
// speedup vs baseline: 3.8303x; 1.2716x over previous
#include <cuda_runtime.h>
#include <cuda_fp16.h>
#include <math.h>
#include <stdint.h>

#define EN 384
#define HIDN 128
#define NHEAD 8
#define DHEAD 16
#define NRBF 64

static constexpr int SW = 132;    // fp32 staging row stride (floats)
static constexpr int HS = 132;    // HPRE row stride (floats)
static constexpr int XROW = 272;  // fp16 tile row stride (bytes): 128*2 + 16 pad

// ---- smem byte-offset map (dynamic smem) ----
static constexpr int OFF_X1A  = 0;        // 128*272 = 34816  (rbf phase: rWs 33792)
static constexpr int OFF_X1B  = 34816;    // 34816            (rbf phase: rAs 33792)
static constexpr int OFF_W2HI = 69632;    // 34816
static constexpr int OFF_W2LO = 104448;   // 34816
static constexpr int OFF_HPRE = 139264;   // 128*132*4 = 67584 -> 206848
static constexpr int OFF_SRED = 206848;   // 2 * 512 floats = 4096
static constexpr int OFF_B2S  = 210944;   // 512
static constexpr int OFF_W3S  = 211456;   // 4096
static constexpr int OFF_DISTS= 215552;   // 512
static constexpr int OFF_DOTS = 216064;   // 512
static constexpr int SMEM_BYTES = 216576;

// ---------------- device scratch ----------------
__device__ float g_q[EN * HIDN];
__device__ float g_k[EN * HIDN];
__device__ float g_v[EN * HIDN];
__device__ float g_Aq[NHEAD * EN * HIDN];
__device__ float g_Ak[NHEAD * EN * HIDN];
__device__ float g_gates[NHEAD * EN];
__device__ float g_scores[NHEAD * EN * EN];
__device__ float g_upd[EN * HIDN];
__device__ float g_delta[NHEAD * EN * 3];

__device__ __forceinline__ float siluf(float x) {
    return __fdividef(x, 1.0f + __expf(-x));
}
__device__ __forceinline__ float silu_fast(float x) {
    float t;
    asm("tanh.approx.f32 %0, %1;" : "=f"(t) : "f"(x * 0.5f));
    return fmaf(x, 0.5f * t, 0.5f * x);
}
__device__ __forceinline__ unsigned long long pack2(float lo, float hi) {
    unsigned long long r;
    asm("mov.b64 %0, {%1, %2};" : "=l"(r) : "f"(lo), "f"(hi));
    return r;
}
__device__ __forceinline__ void unpack2(unsigned long long v, float& lo, float& hi) {
    asm("mov.b64 {%0, %1}, %2;" : "=f"(lo), "=f"(hi) : "l"(v));
}
__device__ __forceinline__ void ffma2(unsigned long long& d, unsigned long long a,
                                      unsigned long long b) {
    asm("fma.rn.f32x2 %0, %1, %2, %0;" : "+l"(d) : "l"(a), "l"(b));
}
// pack two fp32 -> f16x2; x0 -> low half, x1 -> high half
__device__ __forceinline__ uint32_t f16pair(float x0, float x1) {
    uint32_t u;
    asm("cvt.rn.f16x2.f32 %0, %1, %2;" : "=r"(u) : "f"(x1), "f"(x0));
    return u;
}
__device__ __forceinline__ uint32_t smem_u32(const void* p) {
    uint32_t a;
    asm("{ .reg .u64 t; cvta.to.shared.u64 t, %1; cvt.u32.u64 %0, t; }" : "=r"(a) : "l"(p));
    return a;
}

// ---- HMMA path (compute_103-legal) ----
__device__ __forceinline__ void ldsm_x4(uint32_t* r, uint32_t addr) {
    asm volatile("ldmatrix.sync.aligned.m8n8.x4.shared.b16 {%0,%1,%2,%3}, [%4];"
                 : "=r"(r[0]), "=r"(r[1]), "=r"(r[2]), "=r"(r[3]) : "r"(addr));
}
__device__ __forceinline__ void ldsm_x4t(uint32_t* r, uint32_t addr) {
    asm volatile("ldmatrix.sync.aligned.m8n8.x4.trans.shared.b16 {%0,%1,%2,%3}, [%4];"
                 : "=r"(r[0]), "=r"(r[1]), "=r"(r[2]), "=r"(r[3]) : "r"(addr));
}
__device__ __forceinline__ void mma_f16(float* d, const uint32_t* a, uint32_t b0, uint32_t b1) {
    asm volatile(
        "mma.sync.aligned.m16n8k16.row.col.f32.f16.f16.f32 "
        "{%0,%1,%2,%3}, {%4,%5,%6,%7}, {%8,%9}, {%0,%1,%2,%3};"
        : "+f"(d[0]), "+f"(d[1]), "+f"(d[2]), "+f"(d[3])
        : "r"(a[0]), "r"(a[1]), "r"(a[2]), "r"(a[3]), "r"(b0), "r"(b1));
}

// ---------------- K0: q,k,v projections ----------------
__global__ void k_qkv(const float* __restrict__ ef, const float* __restrict__ wq,
                      const float* __restrict__ wk, const float* __restrict__ wv) {
    __shared__ float row[HIDN];
    int i = blockIdx.x;
    int n = threadIdx.x;
    row[n] = ef[i * HIDN + n];
    __syncthreads();
    const float* W = (blockIdx.y == 0) ? wq : ((blockIdx.y == 1) ? wk : wv);
    float* O = (blockIdx.y == 0) ? g_q : ((blockIdx.y == 1) ? g_k : g_v);
    float acc = 0.f;
#pragma unroll 8
    for (int c = 0; c < HIDN; c++) acc += row[c] * W[c * HIDN + n];
    O[i * HIDN + n] = acc;
}

// ---------------- K0b: Aq/Ak precompute ----------------
__global__ void k_aqak(const float* __restrict__ w1) {
    __shared__ float row[HIDN];
    int i = blockIdx.x;
    int n = threadIdx.x;
    int sel = blockIdx.y;
    const float* src = sel ? g_k : g_q;
    float* dst = sel ? g_Ak : g_Aq;
    int roff = sel ? DHEAD : 0;
    row[n] = src[i * HIDN + n];
    __syncthreads();
    for (int h = 0; h < NHEAD; h++) {
        float acc = 0.f;
#pragma unroll
        for (int d = 0; d < DHEAD; d++)
            acc += row[h * DHEAD + d] * w1[(roff + d) * HIDN + n];
        dst[(h * EN + i) * HIDN + n] = acc;
    }
}

// ---------------- K0c: gates ----------------
__global__ void k_gates(const float* __restrict__ gw1, const float* __restrict__ gb1,
                        const float* __restrict__ gw2, const float* __restrict__ gb2) {
    __shared__ float vrow[DHEAD];
    __shared__ float red[HIDN];
    int j = blockIdx.x, h = blockIdx.y, n = threadIdx.x;
    if (n < DHEAD) vrow[n] = g_v[j * HIDN + h * DHEAD + n];
    __syncthreads();
    float acc = gb1[n];
#pragma unroll
    for (int d = 0; d < DHEAD; d++) acc += vrow[d] * gw1[d * HIDN + n];
    red[n] = siluf(acc) * gw2[n];
    __syncthreads();
    for (int s = 64; s > 0; s >>= 1) {
        if (n < s) red[n] += red[n + s];
        __syncthreads();
    }
    if (n == 0) g_gates[h * EN + j] = 1.0f / (1.0f + __expf(-(red[0] + gb2[0])));
}

// ---------------- FFMA2 register-tile GEMM (rbf layer only) ----------------
__device__ __forceinline__ void gemm_run(const float* __restrict__ A,
                                         const float* __restrict__ B, int K,
                                         int ty, int tx,
                                         unsigned long long acc[4][4]) {
    const float* ap = A + ty * 8;
    const float* bp = B + tx * 4;
#pragma unroll 2
    for (int c = 0; c < K; c++, ap += SW, bp += SW) {
        ulonglong2 a01 = *(const ulonglong2*)ap;
        ulonglong2 a23 = *(const ulonglong2*)(ap + 4);
        unsigned long long av[4] = {a01.x, a01.y, a23.x, a23.y};
        float4 w = *(const float4*)bp;
        unsigned long long bd[4] = {pack2(w.x, w.x), pack2(w.y, w.y),
                                    pack2(w.z, w.z), pack2(w.w, w.w)};
#pragma unroll
        for (int pp = 0; pp < 4; pp++)
#pragma unroll
            for (int jj = 0; jj < 4; jj++) ffma2(acc[pp][jj], av[pp], bd[jj]);
    }
}

// ---------------- K1: fused pair-MLP -> attention scores (fp16 HMMA, 2-pass) ----------------
__global__ void __launch_bounds__(512, 1)
k_scores(const float* __restrict__ ec, const float* __restrict__ mask,
         const float* __restrict__ centers, const float* __restrict__ widths,
         const float* __restrict__ w1, const float* __restrict__ b1,
         const float* __restrict__ w2, const float* __restrict__ b2,
         const float* __restrict__ w3, const float* __restrict__ b3) {
    extern __shared__ float smem_f[];
    char* smem_c = (char*)smem_f;
    float* rWs   = (float*)(smem_c + OFF_X1A);    // overlay (dead after hpre)
    float* rAs   = (float*)(smem_c + OFF_X1B);    // overlay (dead after hpre)
    float* HPRE  = (float*)(smem_c + OFF_HPRE);
    float* SRED  = (float*)(smem_c + OFF_SRED);   // [2][512]
    float* B2S   = (float*)(smem_c + OFF_B2S);
    float* W3S   = (float*)(smem_c + OFF_W3S);
    float* dists = (float*)(smem_c + OFF_DISTS);
    float* dots  = (float*)(smem_c + OFF_DOTS);

    uint32_t sbase = smem_u32(smem_c);

    int tid = threadIdx.x;
    int w = tid >> 5, lane = tid & 31;
    int tx = lane, ty = w;                 // rbf-gemm mapping
    int bi = blockIdx.x, bj = blockIdx.y;

    // build mapping: thread owns pair p, channel-interleave lq
    int p = tid >> 2;                      // 0..127
    int lq = tid & 3;
    int ig_p = bi * 16 + (p >> 3);
    int jg_p = bj * 8 + (p & 7);

    // ---- pair geometry ----
    if (tid < 128) {
        int pp = tid;
        int i = bi * 16 + (pp >> 3);
        int j = bj * 8 + (pp & 7);
        float ix = ec[i * 3], iy = ec[i * 3 + 1], iz = ec[i * 3 + 2];
        float jx = ec[j * 3], jy = ec[j * 3 + 1], jz = ec[j * 3 + 2];
        float dx = ix - jx, dy = iy - jy, dz = iz - jz;
        float d = sqrtf(dx * dx + dy * dy + dz * dz) + 1e-8f;
        d = fminf(fmaxf(d, 1e-8f), 1e8f);
        dists[pp] = d;
        float dt = ix * jx + iy * jy + iz * jz;
        dots[pp] = fminf(fmaxf(dt, -1e8f), 1e8f);
    }
    // ---- W1 rbf rows -> rWs ----
    for (int idx = tid; idx < NRBF * HIDN / 4; idx += 512) {
        int r = idx >> 5, col = (idx & 31) * 4;
        *(float4*)(rWs + r * SW + col) = *(const float4*)(w1 + (2 * DHEAD + r) * HIDN + col);
    }
    // ---- W2 -> fp16 hi/lo planes [c][n], row stride XROW ----
    for (int idx = tid; idx < HIDN * HIDN; idx += 512) {
        int c = idx >> 7;
        int n = idx & 127;
        float wv = w2[idx];
        __half hv = __float2half_rn(wv);
        float rv = wv - __half2float(hv);
        __half lv = __float2half_rn(rv);
        *(unsigned short*)(smem_c + OFF_W2HI + c * XROW + n * 2) = __half_as_ushort(hv);
        *(unsigned short*)(smem_c + OFF_W2LO + c * XROW + n * 2) = __half_as_ushort(lv);
    }
    // ---- b2, w3 ----
    if (tid < 128) B2S[tid] = b2[tid];
    for (int idx = tid; idx < HIDN * NHEAD; idx += 512) W3S[idx] = w3[idx];
    __syncthreads();

    // ---- rbf features [r][p] -> rAs ----
    for (int idx = tid; idx < NRBF * 128; idx += 512) {
        int pp = idx & 127, r = idx >> 7;
        float d = dists[pp];
        float t = d - centers[r];
        rAs[r * SW + pp] = (d <= 10.0f) ? __expf(-widths[r] * t * t) : 0.0f;
    }
    __syncthreads();

    // ---- hpre = rbf @ W1_rbf + dot*w1_dot + b1 -> HPRE[p][c] ----
    {
        unsigned long long acc[4][4];
#pragma unroll
        for (int pp2 = 0; pp2 < 4; pp2++)
#pragma unroll
            for (int jj = 0; jj < 4; jj++) acc[pp2][jj] = 0ull;
        gemm_run(rAs, rWs, NRBF, ty, tx, acc);
        float4 wdot = *(const float4*)(w1 + 96 * HIDN + tx * 4);
        float wd[4] = {wdot.x, wdot.y, wdot.z, wdot.w};
        float4 b1v = *(const float4*)(b1 + tx * 4);
        float b1r[4] = {b1v.x, b1v.y, b1v.z, b1v.w};
#pragma unroll
        for (int pp2 = 0; pp2 < 4; pp2++) {
            float2 dp = *(const float2*)(dots + ty * 8 + 2 * pp2);
#pragma unroll
            for (int jj = 0; jj < 4; jj++) {
                float lo, hi;
                unpack2(acc[pp2][jj], lo, hi);
                int c = tx * 4 + jj;
                HPRE[(ty * 8 + 2 * pp2) * HS + c] = lo + dp.x * wd[jj] + b1r[jj];
                HPRE[(ty * 8 + 2 * pp2 + 1) * HS + c] = hi + dp.y * wd[jj] + b1r[jj];
            }
        }
    }
    __syncthreads();   // HPRE done; overlays dead -> X1 buffers usable

    // ---- HMMA tiling constants ----
    int mb = w & 3, nb = w >> 2;
    int r16 = lane & 15, rh = lane >> 4;
    uint32_t aTile = (uint32_t)(32 * mb + r16) * XROW + rh * 16;
    uint32_t bHi = sbase + OFF_W2HI + (uint32_t)r16 * XROW + 64 * nb + 16 * rh;
    uint32_t bLo = sbase + OFF_W2LO + (uint32_t)r16 * XROW + 64 * nb + 16 * rh;

    const float* hp = HPRE + p * HS;

    // hoisted per-thread score-row data (addresses constant across heads)
    float mask_v = 0.f;
    int igw = 0, jgw = 0;
    if (tid < 128) {
        igw = bi * 16 + (tid >> 3);
        jgw = bj * 8 + (tid & 7);
        mask_v = __ldg(mask + (long)igw * EN + jgw);
    }

    // ---- X1 build (head h -> buffer sel) ----
    auto build_x1 = [&](int h, int sel) {
        char* dst = smem_c + (sel ? OFF_X1B : OFF_X1A) + p * XROW;
        const float* aqp = g_Aq + ((long)(h * EN + ig_p)) * HIDN;
        const float* akp = g_Ak + ((long)(h * EN + jg_p)) * HIDN;
#pragma unroll
        for (int q = 0; q < 8; q++) {
            int c = lq * 4 + 16 * q;
            float4 hv = *(const float4*)(hp + c);
            float4 aq = __ldg((const float4*)(aqp + c));
            float4 ak = __ldg((const float4*)(akp + c));
            float x0 = silu_fast(hv.x + aq.x + ak.x);
            float x1 = silu_fast(hv.y + aq.y + ak.y);
            float x2 = silu_fast(hv.z + aq.z + ak.z);
            float x3 = silu_fast(hv.w + aq.w + ak.w);
            *(uint2*)(dst + c * 2) = make_uint2(f16pair(x0, x1), f16pair(x2, x3));
        }
    };

    build_x1(0, 0);
    __syncthreads();

    for (int h = 0; h < NHEAD; h++) {
        int sel = h & 1;
        // ---- W2 GEMM via fp16 HMMA, 2-pass (A-hi x B-hi + A-hi x B-lo) ----
        uint32_t aBuf = sbase + (sel ? OFF_X1B : OFF_X1A) + aTile;
        float acc[2][4][4];
#pragma unroll
        for (int mi = 0; mi < 2; mi++)
#pragma unroll
            for (int ni = 0; ni < 4; ni++)
#pragma unroll
                for (int e = 0; e < 4; e++) acc[mi][ni][e] = 0.f;

#pragma unroll
        for (int kk = 0; kk < 8; kk++) {
            uint32_t kab = (uint32_t)kk * 32;
            uint32_t kbb = (uint32_t)kk * 16 * XROW;
            uint32_t ah[2][4], bh[2][4], bl[2][4];
            ldsm_x4(ah[0], aBuf + kab);
            ldsm_x4(ah[1], aBuf + 16 * XROW + kab);
            ldsm_x4t(bh[0], bHi + kbb);
            ldsm_x4t(bh[1], bHi + kbb + 32);
            ldsm_x4t(bl[0], bLo + kbb);
            ldsm_x4t(bl[1], bLo + kbb + 32);
#pragma unroll
            for (int mi = 0; mi < 2; mi++)
#pragma unroll
                for (int bx = 0; bx < 2; bx++)
#pragma unroll
                    for (int hf = 0; hf < 2; hf++) {
                        int ni = 2 * bx + hf;
                        mma_f16(acc[mi][ni], ah[mi], bh[bx][2 * hf], bh[bx][2 * hf + 1]);
                        mma_f16(acc[mi][ni], ah[mi], bl[bx][2 * hf], bl[bx][2 * hf + 1]);
                    }
        }

        // ---- epilogue: silu + w3 reduce -> SRED[sel] ----
        {
            float* SR = SRED + sel * 512;
            int colq = 2 * (lane & 3);
            float s[2][2];
            s[0][0] = s[0][1] = s[1][0] = s[1][1] = 0.f;
#pragma unroll
            for (int ni = 0; ni < 4; ni++) {
                int col = 32 * nb + 8 * ni + colq;
                float b2a = B2S[col], b2b = B2S[col + 1];
                float w3a = W3S[col * NHEAD + h], w3b = W3S[(col + 1) * NHEAD + h];
#pragma unroll
                for (int mi = 0; mi < 2; mi++) {
                    s[mi][0] += silu_fast(acc[mi][ni][0] + b2a) * w3a +
                                silu_fast(acc[mi][ni][1] + b2b) * w3b;
                    s[mi][1] += silu_fast(acc[mi][ni][2] + b2a) * w3a +
                                silu_fast(acc[mi][ni][3] + b2b) * w3b;
                }
            }
#pragma unroll
            for (int off = 1; off < 4; off <<= 1) {
#pragma unroll
                for (int mi = 0; mi < 2; mi++) {
                    s[mi][0] += __shfl_xor_sync(0xffffffffu, s[mi][0], off);
                    s[mi][1] += __shfl_xor_sync(0xffffffffu, s[mi][1], off);
                }
            }
            if ((lane & 3) == 0) {
                int r0 = 32 * mb + (lane >> 2);
#pragma unroll
                for (int mi = 0; mi < 2; mi++) {
                    SR[nb * 128 + r0 + 16 * mi] = s[mi][0];
                    SR[nb * 128 + r0 + 16 * mi + 8] = s[mi][1];
                }
            }
        }

        // ---- build next head into the other buffer ----
        if (h < NHEAD - 1) build_x1(h + 1, sel ^ 1);

        __syncthreads();   // SRED[sel] ready; X1[sel^1] ready; X1[sel] reads done

        // ---- score write (after sync; reads SRED[sel]) ----
        if (tid < 128) {
            float* SR = SRED + sel * 512;
            float tot = SR[tid] + SR[128 + tid] + SR[256 + tid] + SR[384 + tid];
            float sc = tot + b3[h] + mask_v;
            sc = fminf(fmaxf(sc, -1e9f), 1e9f);
            g_scores[((long)h * EN + igw) * EN + jgw] = sc;
        }
    }
}

// ---------------- K2: softmax + attn@V + coord delta ----------------
__global__ void k_softmax(const float* __restrict__ ec) {
    __shared__ float expv[EN];
    __shared__ float red[128];
    __shared__ float wred[4][20];
    __shared__ float fin[4];
    int i = blockIdx.x, h = blockIdx.y, t = threadIdx.x;
    const float* srow = &g_scores[(h * EN + i) * EN];

    float mx = -1e30f;
    for (int j = t; j < EN; j += 128) mx = fmaxf(mx, srow[j]);
    red[t] = mx;
    __syncthreads();
    for (int s = 64; s > 0; s >>= 1) {
        if (t < s) red[t] = fmaxf(red[t], red[t + s]);
        __syncthreads();
    }
    mx = red[0];
    __syncthreads();
    float sum = 0.f;
    for (int j = t; j < EN; j += 128) {
        float e = __expf(srow[j] - mx);
        expv[j] = e;
        sum += e;
    }
    red[t] = sum;
    __syncthreads();
    for (int s = 64; s > 0; s >>= 1) {
        if (t < s) red[t] += red[t + s];
        __syncthreads();
    }
    float inv = 1.0f / red[0];

    float vals[20];
#pragma unroll
    for (int q = 0; q < 20; q++) vals[q] = 0.f;
    for (int j = t; j < EN; j += 128) {
        float a = expv[j] * inv;
        const float* vr = &g_v[j * HIDN + h * DHEAD];
#pragma unroll
        for (int d = 0; d < DHEAD; d++) vals[d] += a * vr[d];
        vals[16] += a;
        vals[17] += a * ec[j * 3];
        vals[18] += a * ec[j * 3 + 1];
        vals[19] += a * ec[j * 3 + 2];
    }
#pragma unroll
    for (int off = 16; off > 0; off >>= 1)
#pragma unroll
        for (int q = 0; q < 20; q++)
            vals[q] += __shfl_xor_sync(0xffffffffu, vals[q], off);
    int lane = t & 31, warp = t >> 5;
    if (lane == 0)
#pragma unroll
        for (int q = 0; q < 20; q++) wred[warp][q] = vals[q];
    __syncthreads();
    if (t < 20) {
        float s = wred[0][t] + wred[1][t] + wred[2][t] + wred[3][t];
        if (t < 16) g_upd[i * HIDN + h * DHEAD + t] = s;
        else fin[t - 16] = s;
    }
    __syncthreads();
    if (t < 3) {
        float gate = g_gates[h * EN + i];
        g_delta[(h * EN + i) * 3 + t] = gate * (fin[0] * ec[i * 3 + t] - fin[1 + t]);
    }
}

// ---------------- K3: output projection + layernorm + coords ----------------
__global__ void k_out(const float* __restrict__ ef, const float* __restrict__ ec,
                      const float* __restrict__ wo, const float* __restrict__ bo,
                      const float* __restrict__ lg, const float* __restrict__ lb,
                      float* __restrict__ out) {
    __shared__ float u[HIDN];
    __shared__ float red[128];
    int i = blockIdx.x, n = threadIdx.x;
    u[n] = g_upd[i * HIDN + n];
    __syncthreads();
    float y = ef[i * HIDN + n] + bo[n];
#pragma unroll 8
    for (int c = 0; c < HIDN; c++) y += u[c] * wo[c * HIDN + n];
    red[n] = y;
    __syncthreads();
    for (int s = 64; s > 0; s >>= 1) {
        if (n < s) red[n] += red[n + s];
        __syncthreads();
    }
    float mean = red[0] * (1.0f / HIDN);
    __syncthreads();
    float dy = y - mean;
    red[n] = dy * dy;
    __syncthreads();
    for (int s = 64; s > 0; s >>= 1) {
        if (n < s) red[n] += red[n + s];
        __syncthreads();
    }
    float var = red[0] * (1.0f / HIDN);
    float rstd = rsqrtf(var + 1e-5f);
    out[i * HIDN + n] = dy * rstd * lg[n] + lb[n];
    if (n < 3) {
        float dsum = 0.f;
#pragma unroll
        for (int h = 0; h < NHEAD; h++) dsum += g_delta[(h * EN + i) * 3 + n];
        out[EN * HIDN + i * 3 + n] = ec[i * 3 + n] + dsum * 0.125f;
    }
}

// ---------------- launcher ----------------
extern "C" void kernel_launch(void* const* d_in, const int* in_sizes, int n_in,
                              void* d_out, int out_size) {
    const float* ef      = (const float*)d_in[0];
    const float* ec      = (const float*)d_in[1];
    const float* mask    = (const float*)d_in[2];
    const float* wq      = (const float*)d_in[3];
    const float* wk      = (const float*)d_in[4];
    const float* wv      = (const float*)d_in[5];
    const float* centers = (const float*)d_in[6];
    const float* widths  = (const float*)d_in[7];
    const float* a_w1    = (const float*)d_in[8];
    const float* a_b1    = (const float*)d_in[9];
    const float* a_w2    = (const float*)d_in[10];
    const float* a_b2    = (const float*)d_in[11];
    const float* a_w3    = (const float*)d_in[12];
    const float* a_b3    = (const float*)d_in[13];
    const float* g_w1    = (const float*)d_in[14];
    const float* g_b1    = (const float*)d_in[15];
    const float* g_w2    = (const float*)d_in[16];
    const float* g_b2    = (const float*)d_in[17];
    const float* wo      = (const float*)d_in[18];
    const float* bo      = (const float*)d_in[19];
    const float* ln_g    = (const float*)d_in[20];
    const float* ln_b    = (const float*)d_in[21];
    float* out = (float*)d_out;

    cudaFuncSetAttribute(k_scores, cudaFuncAttributeMaxDynamicSharedMemorySize,
                         SMEM_BYTES);

    k_qkv<<<dim3(EN, 3), HIDN>>>(ef, wq, wk, wv);
    k_aqak<<<dim3(EN, 2), HIDN>>>(a_w1);
    k_gates<<<dim3(EN, NHEAD), HIDN>>>(g_w1, g_b1, g_w2, g_b2);
    k_scores<<<dim3(EN / 16, EN / 8), 512, SMEM_BYTES>>>(
        ec, mask, centers, widths, a_w1, a_b1, a_w2, a_b2, a_w3, a_b3);
    k_softmax<<<dim3(EN, NHEAD), HIDN>>>(ec);
    k_out<<<EN, HIDN>>>(ef, ec, wo, bo, ln_g, ln_b, out);
}

// round 8
// speedup vs baseline: 4.3483x; 1.1352x over previous
#include <cuda_runtime.h>
#include <cuda_fp16.h>
#include <math.h>
#include <stdint.h>

#define EN 384
#define HIDN 128
#define NHEAD 8
#define DHEAD 16
#define NRBF 64

static constexpr int SW = 132;    // fp32 staging row stride (floats)
static constexpr int HS = 132;    // HPRE row stride (floats)
static constexpr int XROW = 272;  // fp16 tile row stride (bytes): 128*2 + 16 pad

// ---- smem byte-offset map (dynamic smem) ----
static constexpr int OFF_X1A  = 0;        // 128*272 = 34816  (rbf phase: rWs 33792)
static constexpr int OFF_X1B  = 34816;    // 34816            (rbf phase: rAs 33792)
static constexpr int OFF_W2HI = 69632;    // 34816
static constexpr int OFF_HPRE = 104448;   // 128*132*4 = 67584 -> 172032
static constexpr int OFF_SRED = 172032;   // 2 * 512 floats = 4096
static constexpr int OFF_B2S  = 176128;   // 512
static constexpr int OFF_W3S  = 176640;   // 4096
static constexpr int OFF_DISTS= 180736;   // 512
static constexpr int OFF_DOTS = 181248;   // 512
static constexpr int SMEM_BYTES = 181760;

// ---------------- device scratch ----------------
__device__ float g_q[EN * HIDN];
__device__ float g_k[EN * HIDN];
__device__ float g_v[EN * HIDN];
__device__ float g_Aq[NHEAD * EN * HIDN];
__device__ float g_Ak[NHEAD * EN * HIDN];
__device__ float g_gates[NHEAD * EN];
__device__ float g_scores[NHEAD * EN * EN];
__device__ float g_upd[EN * HIDN];
__device__ float g_delta[NHEAD * EN * 3];

__device__ __forceinline__ float siluf(float x) {
    return __fdividef(x, 1.0f + __expf(-x));
}
__device__ __forceinline__ float silu_fast(float x) {
    float t;
    asm("tanh.approx.f32 %0, %1;" : "=f"(t) : "f"(x * 0.5f));
    return fmaf(x, 0.5f * t, 0.5f * x);
}
__device__ __forceinline__ unsigned long long pack2(float lo, float hi) {
    unsigned long long r;
    asm("mov.b64 %0, {%1, %2};" : "=l"(r) : "f"(lo), "f"(hi));
    return r;
}
__device__ __forceinline__ void unpack2(unsigned long long v, float& lo, float& hi) {
    asm("mov.b64 {%0, %1}, %2;" : "=f"(lo), "=f"(hi) : "l"(v));
}
__device__ __forceinline__ void ffma2(unsigned long long& d, unsigned long long a,
                                      unsigned long long b) {
    asm("fma.rn.f32x2 %0, %1, %2, %0;" : "+l"(d) : "l"(a), "l"(b));
}
// pack two fp32 -> f16x2; x0 -> low half, x1 -> high half
__device__ __forceinline__ uint32_t f16pair(float x0, float x1) {
    uint32_t u;
    asm("cvt.rn.f16x2.f32 %0, %1, %2;" : "=r"(u) : "f"(x1), "f"(x0));
    return u;
}
__device__ __forceinline__ uint32_t smem_u32(const void* p) {
    uint32_t a;
    asm("{ .reg .u64 t; cvta.to.shared.u64 t, %1; cvt.u32.u64 %0, t; }" : "=r"(a) : "l"(p));
    return a;
}

// ---- HMMA path (compute_103-legal) ----
__device__ __forceinline__ void ldsm_x4(uint32_t* r, uint32_t addr) {
    asm volatile("ldmatrix.sync.aligned.m8n8.x4.shared.b16 {%0,%1,%2,%3}, [%4];"
                 : "=r"(r[0]), "=r"(r[1]), "=r"(r[2]), "=r"(r[3]) : "r"(addr));
}
__device__ __forceinline__ void ldsm_x4t(uint32_t* r, uint32_t addr) {
    asm volatile("ldmatrix.sync.aligned.m8n8.x4.trans.shared.b16 {%0,%1,%2,%3}, [%4];"
                 : "=r"(r[0]), "=r"(r[1]), "=r"(r[2]), "=r"(r[3]) : "r"(addr));
}
__device__ __forceinline__ void mma_f16(float* d, const uint32_t* a, uint32_t b0, uint32_t b1) {
    asm volatile(
        "mma.sync.aligned.m16n8k16.row.col.f32.f16.f16.f32 "
        "{%0,%1,%2,%3}, {%4,%5,%6,%7}, {%8,%9}, {%0,%1,%2,%3};"
        : "+f"(d[0]), "+f"(d[1]), "+f"(d[2]), "+f"(d[3])
        : "r"(a[0]), "r"(a[1]), "r"(a[2]), "r"(a[3]), "r"(b0), "r"(b1));
}

// ---------------- K0: q,k,v projections ----------------
__global__ void k_qkv(const float* __restrict__ ef, const float* __restrict__ wq,
                      const float* __restrict__ wk, const float* __restrict__ wv) {
    __shared__ float row[HIDN];
    int i = blockIdx.x;
    int n = threadIdx.x;
    row[n] = ef[i * HIDN + n];
    __syncthreads();
    const float* W = (blockIdx.y == 0) ? wq : ((blockIdx.y == 1) ? wk : wv);
    float* O = (blockIdx.y == 0) ? g_q : ((blockIdx.y == 1) ? g_k : g_v);
    float acc = 0.f;
#pragma unroll 8
    for (int c = 0; c < HIDN; c++) acc += row[c] * W[c * HIDN + n];
    O[i * HIDN + n] = acc;
}

// ---------------- K0b: Aq/Ak precompute ----------------
__global__ void k_aqak(const float* __restrict__ w1) {
    __shared__ float row[HIDN];
    int i = blockIdx.x;
    int n = threadIdx.x;
    int sel = blockIdx.y;
    const float* src = sel ? g_k : g_q;
    float* dst = sel ? g_Ak : g_Aq;
    int roff = sel ? DHEAD : 0;
    row[n] = src[i * HIDN + n];
    __syncthreads();
    for (int h = 0; h < NHEAD; h++) {
        float acc = 0.f;
#pragma unroll
        for (int d = 0; d < DHEAD; d++)
            acc += row[h * DHEAD + d] * w1[(roff + d) * HIDN + n];
        dst[(h * EN + i) * HIDN + n] = acc;
    }
}

// ---------------- K0c: gates ----------------
__global__ void k_gates(const float* __restrict__ gw1, const float* __restrict__ gb1,
                        const float* __restrict__ gw2, const float* __restrict__ gb2) {
    __shared__ float vrow[DHEAD];
    __shared__ float red[HIDN];
    int j = blockIdx.x, h = blockIdx.y, n = threadIdx.x;
    if (n < DHEAD) vrow[n] = g_v[j * HIDN + h * DHEAD + n];
    __syncthreads();
    float acc = gb1[n];
#pragma unroll
    for (int d = 0; d < DHEAD; d++) acc += vrow[d] * gw1[d * HIDN + n];
    red[n] = siluf(acc) * gw2[n];
    __syncthreads();
    for (int s = 64; s > 0; s >>= 1) {
        if (n < s) red[n] += red[n + s];
        __syncthreads();
    }
    if (n == 0) g_gates[h * EN + j] = 1.0f / (1.0f + __expf(-(red[0] + gb2[0])));
}

// ---------------- FFMA2 register-tile GEMM (rbf layer only) ----------------
__device__ __forceinline__ void gemm_run(const float* __restrict__ A,
                                         const float* __restrict__ B, int K,
                                         int ty, int tx,
                                         unsigned long long acc[4][4]) {
    const float* ap = A + ty * 8;
    const float* bp = B + tx * 4;
#pragma unroll 2
    for (int c = 0; c < K; c++, ap += SW, bp += SW) {
        ulonglong2 a01 = *(const ulonglong2*)ap;
        ulonglong2 a23 = *(const ulonglong2*)(ap + 4);
        unsigned long long av[4] = {a01.x, a01.y, a23.x, a23.y};
        float4 w = *(const float4*)bp;
        unsigned long long bd[4] = {pack2(w.x, w.x), pack2(w.y, w.y),
                                    pack2(w.z, w.z), pack2(w.w, w.w)};
#pragma unroll
        for (int pp = 0; pp < 4; pp++)
#pragma unroll
            for (int jj = 0; jj < 4; jj++) ffma2(acc[pp][jj], av[pp], bd[jj]);
    }
}

// ---------------- K1: fused pair-MLP -> attention scores ----------------
// 1024 threads, 32 warps. HMMA warp tile 16x32: mb=w&7 (row block), nb=w>>3 (col block).
__global__ void __launch_bounds__(1024, 1)
k_scores(const float* __restrict__ ec, const float* __restrict__ mask,
         const float* __restrict__ centers, const float* __restrict__ widths,
         const float* __restrict__ w1, const float* __restrict__ b1,
         const float* __restrict__ w2, const float* __restrict__ b2,
         const float* __restrict__ w3, const float* __restrict__ b3) {
    extern __shared__ float smem_f[];
    char* smem_c = (char*)smem_f;
    float* rWs   = (float*)(smem_c + OFF_X1A);    // overlay (dead after hpre)
    float* rAs   = (float*)(smem_c + OFF_X1B);    // overlay (dead after hpre)
    float* HPRE  = (float*)(smem_c + OFF_HPRE);
    float* SRED  = (float*)(smem_c + OFF_SRED);   // [2][512]
    float* B2S   = (float*)(smem_c + OFF_B2S);
    float* W3S   = (float*)(smem_c + OFF_W3S);
    float* dists = (float*)(smem_c + OFF_DISTS);
    float* dots  = (float*)(smem_c + OFF_DOTS);

    uint32_t sbase = smem_u32(smem_c);

    int tid = threadIdx.x;
    int w = tid >> 5, lane = tid & 31;
    int bi = blockIdx.x, bj = blockIdx.y;

    // build mapping: thread owns pair p, channel-interleave lq (16 channels/thread)
    int p = tid >> 3;                      // 0..127
    int lq = tid & 7;
    int ig_p = bi * 16 + (p >> 3);
    int jg_p = bj * 8 + (p & 7);

    // ---- pair geometry ----
    if (tid < 128) {
        int pp = tid;
        int i = bi * 16 + (pp >> 3);
        int j = bj * 8 + (pp & 7);
        float ix = ec[i * 3], iy = ec[i * 3 + 1], iz = ec[i * 3 + 2];
        float jx = ec[j * 3], jy = ec[j * 3 + 1], jz = ec[j * 3 + 2];
        float dx = ix - jx, dy = iy - jy, dz = iz - jz;
        float d = sqrtf(dx * dx + dy * dy + dz * dz) + 1e-8f;
        d = fminf(fmaxf(d, 1e-8f), 1e8f);
        dists[pp] = d;
        float dt = ix * jx + iy * jy + iz * jz;
        dots[pp] = fminf(fmaxf(dt, -1e8f), 1e8f);
    }
    // ---- W1 rbf rows -> rWs ----
    for (int idx = tid; idx < NRBF * HIDN / 4; idx += 1024) {
        int r = idx >> 5, col = (idx & 31) * 4;
        *(float4*)(rWs + r * SW + col) = *(const float4*)(w1 + (2 * DHEAD + r) * HIDN + col);
    }
    // ---- W2 -> fp16 plane [c][n], row stride XROW ----
    for (int idx = tid; idx < HIDN * HIDN; idx += 1024) {
        int c = idx >> 7;
        int n = idx & 127;
        __half hv = __float2half_rn(w2[idx]);
        *(unsigned short*)(smem_c + OFF_W2HI + c * XROW + n * 2) = __half_as_ushort(hv);
    }
    // ---- b2, w3 ----
    if (tid < 128) B2S[tid] = b2[tid];
    for (int idx = tid; idx < HIDN * NHEAD; idx += 1024) W3S[idx] = w3[idx];
    __syncthreads();

    // ---- rbf features [r][p] -> rAs ----
    for (int idx = tid; idx < NRBF * 128; idx += 1024) {
        int pp = idx & 127, r = idx >> 7;
        float d = dists[pp];
        float t = d - centers[r];
        rAs[r * SW + pp] = (d <= 10.0f) ? __expf(-widths[r] * t * t) : 0.0f;
    }
    __syncthreads();

    // ---- hpre = rbf @ W1_rbf + dot*w1_dot + b1 -> HPRE[p][c]  (first 16 warps) ----
    if (tid < 512) {
        int tx = lane, ty = w;
        unsigned long long acc[4][4];
#pragma unroll
        for (int pp2 = 0; pp2 < 4; pp2++)
#pragma unroll
            for (int jj = 0; jj < 4; jj++) acc[pp2][jj] = 0ull;
        gemm_run(rAs, rWs, NRBF, ty, tx, acc);
        float4 wdot = *(const float4*)(w1 + 96 * HIDN + tx * 4);
        float wd[4] = {wdot.x, wdot.y, wdot.z, wdot.w};
        float4 b1v = *(const float4*)(b1 + tx * 4);
        float b1r[4] = {b1v.x, b1v.y, b1v.z, b1v.w};
#pragma unroll
        for (int pp2 = 0; pp2 < 4; pp2++) {
            float2 dp = *(const float2*)(dots + ty * 8 + 2 * pp2);
#pragma unroll
            for (int jj = 0; jj < 4; jj++) {
                float lo, hi;
                unpack2(acc[pp2][jj], lo, hi);
                int c = tx * 4 + jj;
                HPRE[(ty * 8 + 2 * pp2) * HS + c] = lo + dp.x * wd[jj] + b1r[jj];
                HPRE[(ty * 8 + 2 * pp2 + 1) * HS + c] = hi + dp.y * wd[jj] + b1r[jj];
            }
        }
    }
    __syncthreads();   // HPRE done; overlays dead -> X1 buffers usable

    // ---- HMMA tiling constants (32 warps: 16x32 tile each) ----
    int mb = w & 7, nb = w >> 3;
    int r16 = lane & 15, rh = lane >> 4;
    uint32_t aTile = (uint32_t)(16 * mb + r16) * XROW + rh * 16;
    uint32_t bHi = sbase + OFF_W2HI + (uint32_t)r16 * XROW + 64 * nb + 16 * rh;

    const float* hp = HPRE + p * HS;

    // hoisted per-thread score-row data
    float mask_v = 0.f;
    int igw = 0, jgw = 0;
    if (tid < 128) {
        igw = bi * 16 + (tid >> 3);
        jgw = bj * 8 + (tid & 7);
        mask_v = __ldg(mask + (long)igw * EN + jgw);
    }

    // ---- X1 build (head h -> buffer sel); 16 channels per thread ----
    auto build_x1 = [&](int h, int sel) {
        char* dst = smem_c + (sel ? OFF_X1B : OFF_X1A) + p * XROW;
        const float* aqp = g_Aq + ((long)(h * EN + ig_p)) * HIDN;
        const float* akp = g_Ak + ((long)(h * EN + jg_p)) * HIDN;
#pragma unroll
        for (int q = 0; q < 4; q++) {
            int c = lq * 4 + 32 * q;
            float4 hv = *(const float4*)(hp + c);
            float4 aq = __ldg((const float4*)(aqp + c));
            float4 ak = __ldg((const float4*)(akp + c));
            float x0 = silu_fast(hv.x + aq.x + ak.x);
            float x1 = silu_fast(hv.y + aq.y + ak.y);
            float x2 = silu_fast(hv.z + aq.z + ak.z);
            float x3 = silu_fast(hv.w + aq.w + ak.w);
            *(uint2*)(dst + c * 2) = make_uint2(f16pair(x0, x1), f16pair(x2, x3));
        }
    };

    build_x1(0, 0);
    __syncthreads();

    for (int h = 0; h < NHEAD; h++) {
        int sel = h & 1;
        uint32_t aBuf = sbase + (sel ? OFF_X1B : OFF_X1A) + aTile;
        float acc[4][4];
#pragma unroll
        for (int ni = 0; ni < 4; ni++)
#pragma unroll
            for (int e = 0; e < 4; e++) acc[ni][e] = 0.f;

#pragma unroll
        for (int kk = 0; kk < 8; kk++) {
            uint32_t kab = (uint32_t)kk * 32;
            uint32_t kbb = (uint32_t)kk * 16 * XROW;
            uint32_t ah[4], bh[2][4];
            ldsm_x4(ah, aBuf + kab);
            ldsm_x4t(bh[0], bHi + kbb);
            ldsm_x4t(bh[1], bHi + kbb + 32);
#pragma unroll
            for (int bx = 0; bx < 2; bx++)
#pragma unroll
                for (int hf = 0; hf < 2; hf++) {
                    int ni = 2 * bx + hf;
                    mma_f16(acc[ni], ah, bh[bx][2 * hf], bh[bx][2 * hf + 1]);
                }
        }

        // ---- epilogue: silu + w3 reduce -> SRED[sel] ----
        {
            float* SR = SRED + sel * 512;
            int colq = 2 * (lane & 3);
            float s0 = 0.f, s1 = 0.f;
#pragma unroll
            for (int ni = 0; ni < 4; ni++) {
                int col = 32 * nb + 8 * ni + colq;
                float b2a = B2S[col], b2b = B2S[col + 1];
                float w3a = W3S[col * NHEAD + h], w3b = W3S[(col + 1) * NHEAD + h];
                s0 += silu_fast(acc[ni][0] + b2a) * w3a +
                      silu_fast(acc[ni][1] + b2b) * w3b;
                s1 += silu_fast(acc[ni][2] + b2a) * w3a +
                      silu_fast(acc[ni][3] + b2b) * w3b;
            }
#pragma unroll
            for (int off = 1; off < 4; off <<= 1) {
                s0 += __shfl_xor_sync(0xffffffffu, s0, off);
                s1 += __shfl_xor_sync(0xffffffffu, s1, off);
            }
            if ((lane & 3) == 0) {
                int r0 = 16 * mb + (lane >> 2);
                SR[nb * 128 + r0] = s0;
                SR[nb * 128 + r0 + 8] = s1;
            }
        }

        // ---- build next head into the other buffer ----
        if (h < NHEAD - 1) build_x1(h + 1, sel ^ 1);

        __syncthreads();   // SRED[sel] ready; X1[sel^1] ready; X1[sel] reads done

        // ---- score write ----
        if (tid < 128) {
            float* SR = SRED + sel * 512;
            float tot = SR[tid] + SR[128 + tid] + SR[256 + tid] + SR[384 + tid];
            float sc = tot + b3[h] + mask_v;
            sc = fminf(fmaxf(sc, -1e9f), 1e9f);
            g_scores[((long)h * EN + igw) * EN + jgw] = sc;
        }
    }
}

// ---------------- K2: softmax + attn@V + coord delta ----------------
__global__ void k_softmax(const float* __restrict__ ec) {
    __shared__ float expv[EN];
    __shared__ float red[128];
    __shared__ float wred[4][20];
    __shared__ float fin[4];
    int i = blockIdx.x, h = blockIdx.y, t = threadIdx.x;
    const float* srow = &g_scores[(h * EN + i) * EN];

    float mx = -1e30f;
    for (int j = t; j < EN; j += 128) mx = fmaxf(mx, srow[j]);
    red[t] = mx;
    __syncthreads();
    for (int s = 64; s > 0; s >>= 1) {
        if (t < s) red[t] = fmaxf(red[t], red[t + s]);
        __syncthreads();
    }
    mx = red[0];
    __syncthreads();
    float sum = 0.f;
    for (int j = t; j < EN; j += 128) {
        float e = __expf(srow[j] - mx);
        expv[j] = e;
        sum += e;
    }
    red[t] = sum;
    __syncthreads();
    for (int s = 64; s > 0; s >>= 1) {
        if (t < s) red[t] += red[t + s];
        __syncthreads();
    }
    float inv = 1.0f / red[0];

    float vals[20];
#pragma unroll
    for (int q = 0; q < 20; q++) vals[q] = 0.f;
    for (int j = t; j < EN; j += 128) {
        float a = expv[j] * inv;
        const float* vr = &g_v[j * HIDN + h * DHEAD];
#pragma unroll
        for (int d = 0; d < DHEAD; d++) vals[d] += a * vr[d];
        vals[16] += a;
        vals[17] += a * ec[j * 3];
        vals[18] += a * ec[j * 3 + 1];
        vals[19] += a * ec[j * 3 + 2];
    }
#pragma unroll
    for (int off = 16; off > 0; off >>= 1)
#pragma unroll
        for (int q = 0; q < 20; q++)
            vals[q] += __shfl_xor_sync(0xffffffffu, vals[q], off);
    int lane = t & 31, warp = t >> 5;
    if (lane == 0)
#pragma unroll
        for (int q = 0; q < 20; q++) wred[warp][q] = vals[q];
    __syncthreads();
    if (t < 20) {
        float s = wred[0][t] + wred[1][t] + wred[2][t] + wred[3][t];
        if (t < 16) g_upd[i * HIDN + h * DHEAD + t] = s;
        else fin[t - 16] = s;
    }
    __syncthreads();
    if (t < 3) {
        float gate = g_gates[h * EN + i];
        g_delta[(h * EN + i) * 3 + t] = gate * (fin[0] * ec[i * 3 + t] - fin[1 + t]);
    }
}

// ---------------- K3: output projection + layernorm + coords ----------------
__global__ void k_out(const float* __restrict__ ef, const float* __restrict__ ec,
                      const float* __restrict__ wo, const float* __restrict__ bo,
                      const float* __restrict__ lg, const float* __restrict__ lb,
                      float* __restrict__ out) {
    __shared__ float u[HIDN];
    __shared__ float red[128];
    int i = blockIdx.x, n = threadIdx.x;
    u[n] = g_upd[i * HIDN + n];
    __syncthreads();
    float y = ef[i * HIDN + n] + bo[n];
#pragma unroll 8
    for (int c = 0; c < HIDN; c++) y += u[c] * wo[c * HIDN + n];
    red[n] = y;
    __syncthreads();
    for (int s = 64; s > 0; s >>= 1) {
        if (n < s) red[n] += red[n + s];
        __syncthreads();
    }
    float mean = red[0] * (1.0f / HIDN);
    __syncthreads();
    float dy = y - mean;
    red[n] = dy * dy;
    __syncthreads();
    for (int s = 64; s > 0; s >>= 1) {
        if (n < s) red[n] += red[n + s];
        __syncthreads();
    }
    float var = red[0] * (1.0f / HIDN);
    float rstd = rsqrtf(var + 1e-5f);
    out[i * HIDN + n] = dy * rstd * lg[n] + lb[n];
    if (n < 3) {
        float dsum = 0.f;
#pragma unroll
        for (int h = 0; h < NHEAD; h++) dsum += g_delta[(h * EN + i) * 3 + n];
        out[EN * HIDN + i * 3 + n] = ec[i * 3 + n] + dsum * 0.125f;
    }
}

// ---------------- launcher ----------------
extern "C" void kernel_launch(void* const* d_in, const int* in_sizes, int n_in,
                              void* d_out, int out_size) {
    const float* ef      = (const float*)d_in[0];
    const float* ec      = (const float*)d_in[1];
    const float* mask    = (const float*)d_in[2];
    const float* wq      = (const float*)d_in[3];
    const float* wk      = (const float*)d_in[4];
    const float* wv      = (const float*)d_in[5];
    const float* centers = (const float*)d_in[6];
    const float* widths  = (const float*)d_in[7];
    const float* a_w1    = (const float*)d_in[8];
    const float* a_b1    = (const float*)d_in[9];
    const float* a_w2    = (const float*)d_in[10];
    const float* a_b2    = (const float*)d_in[11];
    const float* a_w3    = (const float*)d_in[12];
    const float* a_b3    = (const float*)d_in[13];
    const float* g_w1    = (const float*)d_in[14];
    const float* g_b1    = (const float*)d_in[15];
    const float* g_w2    = (const float*)d_in[16];
    const float* g_b2    = (const float*)d_in[17];
    const float* wo      = (const float*)d_in[18];
    const float* bo      = (const float*)d_in[19];
    const float* ln_g    = (const float*)d_in[20];
    const float* ln_b    = (const float*)d_in[21];
    float* out = (float*)d_out;

    cudaFuncSetAttribute(k_scores, cudaFuncAttributeMaxDynamicSharedMemorySize,
                         SMEM_BYTES);

    k_qkv<<<dim3(EN, 3), HIDN>>>(ef, wq, wk, wv);
    k_aqak<<<dim3(EN, 2), HIDN>>>(a_w1);
    k_gates<<<dim3(EN, NHEAD), HIDN>>>(g_w1, g_b1, g_w2, g_b2);
    k_scores<<<dim3(EN / 16, EN / 8), 1024, SMEM_BYTES>>>(
        ec, mask, centers, widths, a_w1, a_b1, a_w2, a_b2, a_w3, a_b3);
    k_softmax<<<dim3(EN, NHEAD), HIDN>>>(ec);
    k_out<<<EN, HIDN>>>(ef, ec, wo, bo, ln_g, ln_b, out);
}

// round 9
// speedup vs baseline: 4.5296x; 1.0417x over previous
#include <cuda_runtime.h>
#include <cuda_fp16.h>
#include <math.h>
#include <stdint.h>

#define EN 384
#define HIDN 128
#define NHEAD 8
#define DHEAD 16
#define NRBF 64

static constexpr int SW = 132;    // fp32 staging row stride (floats)
static constexpr int XROW = 272;  // fp16 X1/W2 tile row stride (bytes)
static constexpr int HROW = 320;  // fp16 HPRE row stride (bytes): 16-bank p-shift

// ---- smem byte-offset map (dynamic smem) ----
static constexpr int OFF_X1A  = 0;        // 34816  (rbf phase: rWs 33792)
static constexpr int OFF_X1B  = 34816;    // 34816  (rbf phase: rAs 33792)
static constexpr int OFF_W2H  = 69632;    // 34816
static constexpr int OFF_HPREH= 104448;   // 128*320 = 40960 -> 145408
static constexpr int OFF_SRED = 145408;   // 4096
static constexpr int OFF_B2S  = 149504;   // 512
static constexpr int OFF_W3S  = 150016;   // 4096
static constexpr int OFF_DISTS= 154112;   // 512
static constexpr int OFF_DOTS = 154624;   // 512
static constexpr int SMEM_BYTES = 155136;

// ---------------- device scratch ----------------
__device__ float g_q[EN * HIDN];
__device__ float g_k[EN * HIDN];
__device__ float g_v[EN * HIDN];
__device__ __half g_Aqh[NHEAD * EN * HIDN];
__device__ __half g_Akh[NHEAD * EN * HIDN];
__device__ float g_gates[NHEAD * EN];
__device__ float g_scores[NHEAD * EN * EN];
__device__ float g_upd[EN * HIDN];
__device__ float g_delta[NHEAD * EN * 3];

__device__ __forceinline__ float siluf(float x) {
    return __fdividef(x, 1.0f + __expf(-x));
}
__device__ __forceinline__ float silu_fast(float x) {
    float t;
    asm("tanh.approx.f32 %0, %1;" : "=f"(t) : "f"(x * 0.5f));
    return fmaf(x, 0.5f * t, 0.5f * x);
}
__device__ __forceinline__ unsigned long long pack2(float lo, float hi) {
    unsigned long long r;
    asm("mov.b64 %0, {%1, %2};" : "=l"(r) : "f"(lo), "f"(hi));
    return r;
}
__device__ __forceinline__ void unpack2(unsigned long long v, float& lo, float& hi) {
    asm("mov.b64 {%0, %1}, %2;" : "=f"(lo), "=f"(hi) : "l"(v));
}
__device__ __forceinline__ void ffma2(unsigned long long& d, unsigned long long a,
                                      unsigned long long b) {
    asm("fma.rn.f32x2 %0, %1, %2, %0;" : "+l"(d) : "l"(a), "l"(b));
}
// pack two fp32 -> f16x2; x0 -> low half, x1 -> high half
__device__ __forceinline__ uint32_t f16pair(float x0, float x1) {
    uint32_t u;
    asm("cvt.rn.f16x2.f32 %0, %1, %2;" : "=r"(u) : "f"(x1), "f"(x0));
    return u;
}
__device__ __forceinline__ uint32_t h2tanh(uint32_t y) {
    uint32_t r;
    asm("tanh.approx.f16x2 %0, %1;" : "=r"(r) : "r"(y));
    return r;
}
// packed-half2 silu on raw bits: o = y + y*tanh(y), y = 0.5*x
__device__ __forceinline__ uint32_t h2silu(uint32_t xb) {
    __half2 x = *(__half2*)&xb;
    __half2 y = __hmul2(x, __half2half2(__ushort_as_half(0x3800)));  // 0.5
    uint32_t yb = *(uint32_t*)&y;
    uint32_t tb = h2tanh(yb);
    __half2 t = *(__half2*)&tb;
    __half2 o = __hfma2(y, t, y);
    return *(uint32_t*)&o;
}
__device__ __forceinline__ uint32_t smem_u32(const void* p) {
    uint32_t a;
    asm("{ .reg .u64 t; cvta.to.shared.u64 t, %1; cvt.u32.u64 %0, t; }" : "=r"(a) : "l"(p));
    return a;
}

// ---- HMMA path (compute_103-legal) ----
__device__ __forceinline__ void ldsm_x4(uint32_t* r, uint32_t addr) {
    asm volatile("ldmatrix.sync.aligned.m8n8.x4.shared.b16 {%0,%1,%2,%3}, [%4];"
                 : "=r"(r[0]), "=r"(r[1]), "=r"(r[2]), "=r"(r[3]) : "r"(addr));
}
__device__ __forceinline__ void ldsm_x4t(uint32_t* r, uint32_t addr) {
    asm volatile("ldmatrix.sync.aligned.m8n8.x4.trans.shared.b16 {%0,%1,%2,%3}, [%4];"
                 : "=r"(r[0]), "=r"(r[1]), "=r"(r[2]), "=r"(r[3]) : "r"(addr));
}
__device__ __forceinline__ void mma_f16(float* d, const uint32_t* a, uint32_t b0, uint32_t b1) {
    asm volatile(
        "mma.sync.aligned.m16n8k16.row.col.f32.f16.f16.f32 "
        "{%0,%1,%2,%3}, {%4,%5,%6,%7}, {%8,%9}, {%0,%1,%2,%3};"
        : "+f"(d[0]), "+f"(d[1]), "+f"(d[2]), "+f"(d[3])
        : "r"(a[0]), "r"(a[1]), "r"(a[2]), "r"(a[3]), "r"(b0), "r"(b1));
}

// ---------------- K0: q,k,v projections ----------------
__global__ void k_qkv(const float* __restrict__ ef, const float* __restrict__ wq,
                      const float* __restrict__ wk, const float* __restrict__ wv) {
    __shared__ float row[HIDN];
    int i = blockIdx.x;
    int n = threadIdx.x;
    row[n] = ef[i * HIDN + n];
    __syncthreads();
    const float* W = (blockIdx.y == 0) ? wq : ((blockIdx.y == 1) ? wk : wv);
    float* O = (blockIdx.y == 0) ? g_q : ((blockIdx.y == 1) ? g_k : g_v);
    float acc = 0.f;
#pragma unroll 8
    for (int c = 0; c < HIDN; c++) acc += row[c] * W[c * HIDN + n];
    O[i * HIDN + n] = acc;
}

// ---------------- K0b: Aq/Ak precompute (fp16 output) ----------------
__global__ void k_aqak(const float* __restrict__ w1) {
    __shared__ float row[HIDN];
    int i = blockIdx.x;
    int n = threadIdx.x;
    int sel = blockIdx.y;
    const float* src = sel ? g_k : g_q;
    __half* dst = sel ? g_Akh : g_Aqh;
    int roff = sel ? DHEAD : 0;
    row[n] = src[i * HIDN + n];
    __syncthreads();
    for (int h = 0; h < NHEAD; h++) {
        float acc = 0.f;
#pragma unroll
        for (int d = 0; d < DHEAD; d++)
            acc += row[h * DHEAD + d] * w1[(roff + d) * HIDN + n];
        dst[(h * EN + i) * HIDN + n] = __float2half_rn(acc);
    }
}

// ---------------- K0c: gates ----------------
__global__ void k_gates(const float* __restrict__ gw1, const float* __restrict__ gb1,
                        const float* __restrict__ gw2, const float* __restrict__ gb2) {
    __shared__ float vrow[DHEAD];
    __shared__ float red[HIDN];
    int j = blockIdx.x, h = blockIdx.y, n = threadIdx.x;
    if (n < DHEAD) vrow[n] = g_v[j * HIDN + h * DHEAD + n];
    __syncthreads();
    float acc = gb1[n];
#pragma unroll
    for (int d = 0; d < DHEAD; d++) acc += vrow[d] * gw1[d * HIDN + n];
    red[n] = siluf(acc) * gw2[n];
    __syncthreads();
    for (int s = 64; s > 0; s >>= 1) {
        if (n < s) red[n] += red[n + s];
        __syncthreads();
    }
    if (n == 0) g_gates[h * EN + j] = 1.0f / (1.0f + __expf(-(red[0] + gb2[0])));
}

// ---------------- FFMA2 register-tile GEMM (rbf layer only) ----------------
__device__ __forceinline__ void gemm_run(const float* __restrict__ A,
                                         const float* __restrict__ B, int K,
                                         int ty, int tx,
                                         unsigned long long acc[4][4]) {
    const float* ap = A + ty * 8;
    const float* bp = B + tx * 4;
#pragma unroll 2
    for (int c = 0; c < K; c++, ap += SW, bp += SW) {
        ulonglong2 a01 = *(const ulonglong2*)ap;
        ulonglong2 a23 = *(const ulonglong2*)(ap + 4);
        unsigned long long av[4] = {a01.x, a01.y, a23.x, a23.y};
        float4 w = *(const float4*)bp;
        unsigned long long bd[4] = {pack2(w.x, w.x), pack2(w.y, w.y),
                                    pack2(w.z, w.z), pack2(w.w, w.w)};
#pragma unroll
        for (int pp = 0; pp < 4; pp++)
#pragma unroll
            for (int jj = 0; jj < 4; jj++) ffma2(acc[pp][jj], av[pp], bd[jj]);
    }
}

// ---------------- K1: fused pair-MLP -> attention scores ----------------
// 1024 threads, 32 warps. HMMA warp tile 16x32: mb=w&7, nb=w>>3.
__global__ void __launch_bounds__(1024, 1)
k_scores(const float* __restrict__ ec, const float* __restrict__ mask,
         const float* __restrict__ centers, const float* __restrict__ widths,
         const float* __restrict__ w1, const float* __restrict__ b1,
         const float* __restrict__ w2, const float* __restrict__ b2,
         const float* __restrict__ w3, const float* __restrict__ b3) {
    extern __shared__ float smem_f[];
    char* smem_c = (char*)smem_f;
    float* rWs   = (float*)(smem_c + OFF_X1A);    // overlay (dead after hpre)
    float* rAs   = (float*)(smem_c + OFF_X1B);    // overlay (dead after hpre)
    float* SRED  = (float*)(smem_c + OFF_SRED);   // [2][512]
    float* B2S   = (float*)(smem_c + OFF_B2S);
    float* W3S   = (float*)(smem_c + OFF_W3S);
    float* dists = (float*)(smem_c + OFF_DISTS);
    float* dots  = (float*)(smem_c + OFF_DOTS);

    uint32_t sbase = smem_u32(smem_c);

    int tid = threadIdx.x;
    int w = tid >> 5, lane = tid & 31;
    int bi = blockIdx.x, bj = blockIdx.y;

    // build mapping: thread owns pair p, channel-interleave lq (16 channels/thread)
    int p = tid >> 3;                      // 0..127
    int lq = tid & 7;
    int ig_p = bi * 16 + (p >> 3);
    int jg_p = bj * 8 + (p & 7);

    // ---- pair geometry ----
    if (tid < 128) {
        int pp = tid;
        int i = bi * 16 + (pp >> 3);
        int j = bj * 8 + (pp & 7);
        float ix = ec[i * 3], iy = ec[i * 3 + 1], iz = ec[i * 3 + 2];
        float jx = ec[j * 3], jy = ec[j * 3 + 1], jz = ec[j * 3 + 2];
        float dx = ix - jx, dy = iy - jy, dz = iz - jz;
        float d = sqrtf(dx * dx + dy * dy + dz * dz) + 1e-8f;
        d = fminf(fmaxf(d, 1e-8f), 1e8f);
        dists[pp] = d;
        float dt = ix * jx + iy * jy + iz * jz;
        dots[pp] = fminf(fmaxf(dt, -1e8f), 1e8f);
    }
    // ---- W1 rbf rows -> rWs ----
    for (int idx = tid; idx < NRBF * HIDN / 4; idx += 1024) {
        int r = idx >> 5, col = (idx & 31) * 4;
        *(float4*)(rWs + r * SW + col) = *(const float4*)(w1 + (2 * DHEAD + r) * HIDN + col);
    }
    // ---- W2 -> fp16 plane [c][n] ----
    for (int idx = tid; idx < HIDN * HIDN; idx += 1024) {
        int c = idx >> 7;
        int n = idx & 127;
        __half hv = __float2half_rn(w2[idx]);
        *(unsigned short*)(smem_c + OFF_W2H + c * XROW + n * 2) = __half_as_ushort(hv);
    }
    // ---- b2, w3 ----
    if (tid < 128) B2S[tid] = b2[tid];
    for (int idx = tid; idx < HIDN * NHEAD; idx += 1024) W3S[idx] = w3[idx];
    __syncthreads();

    // ---- rbf features [r][p] -> rAs ----
    for (int idx = tid; idx < NRBF * 128; idx += 1024) {
        int pp = idx & 127, r = idx >> 7;
        float d = dists[pp];
        float t = d - centers[r];
        rAs[r * SW + pp] = (d <= 10.0f) ? __expf(-widths[r] * t * t) : 0.0f;
    }
    __syncthreads();

    // ---- hpre = rbf @ W1_rbf + dot*w1_dot + b1 -> HPRE fp16 [p][c] (first 16 warps) ----
    if (tid < 512) {
        int tx = lane, ty = w;
        unsigned long long acc[4][4];
#pragma unroll
        for (int pp2 = 0; pp2 < 4; pp2++)
#pragma unroll
            for (int jj = 0; jj < 4; jj++) acc[pp2][jj] = 0ull;
        gemm_run(rAs, rWs, NRBF, ty, tx, acc);
        float4 wdot = *(const float4*)(w1 + 96 * HIDN + tx * 4);
        float wd[4] = {wdot.x, wdot.y, wdot.z, wdot.w};
        float4 b1v = *(const float4*)(b1 + tx * 4);
        float b1r[4] = {b1v.x, b1v.y, b1v.z, b1v.w};
#pragma unroll
        for (int pp2 = 0; pp2 < 4; pp2++) {
            int row0 = ty * 8 + 2 * pp2;
            float2 dp = *(const float2*)(dots + row0);
            float vl[4], vh[4];
#pragma unroll
            for (int jj = 0; jj < 4; jj++) {
                float lo, hi;
                unpack2(acc[pp2][jj], lo, hi);
                vl[jj] = lo + dp.x * wd[jj] + b1r[jj];
                vh[jj] = hi + dp.y * wd[jj] + b1r[jj];
            }
            uint32_t off = (uint32_t)row0 * HROW + tx * 8;
            *(uint2*)(smem_c + OFF_HPREH + off) =
                make_uint2(f16pair(vl[0], vl[1]), f16pair(vl[2], vl[3]));
            *(uint2*)(smem_c + OFF_HPREH + off + HROW) =
                make_uint2(f16pair(vh[0], vh[1]), f16pair(vh[2], vh[3]));
        }
    }
    __syncthreads();   // HPRE done; overlays dead -> X1 buffers usable

    // ---- HMMA tiling constants (32 warps: 16x32 tile each) ----
    int mb = w & 7, nb = w >> 3;
    int r16 = lane & 15, rh = lane >> 4;
    uint32_t aTile = (uint32_t)(16 * mb + r16) * XROW + rh * 16;
    uint32_t bHi = sbase + OFF_W2H + (uint32_t)r16 * XROW + 64 * nb + 16 * rh;

    // hoisted per-thread score-row data
    float mask_v = 0.f;
    int igw = 0, jgw = 0;
    if (tid < 128) {
        igw = bi * 16 + (tid >> 3);
        jgw = bj * 8 + (tid & 7);
        mask_v = __ldg(mask + (long)igw * EN + jgw);
    }

    // ---- X1 build in packed fp16: 16 channels (8 half2) per thread ----
    const char* hpb = smem_c + OFF_HPREH + p * HROW;
    auto build_x1 = [&](int h, int sel) {
        char* dst = smem_c + (sel ? OFF_X1B : OFF_X1A) + p * XROW;
        const __half* aqp = g_Aqh + ((long)(h * EN + ig_p)) * HIDN;
        const __half* akp = g_Akh + ((long)(h * EN + jg_p)) * HIDN;
#pragma unroll
        for (int q = 0; q < 4; q++) {
            int c = lq * 4 + 32 * q;                    // channel base (4 channels)
            uint2 av = __ldg((const uint2*)(aqp + c));
            uint2 kv = __ldg((const uint2*)(akp + c));
            uint2 hv = *(const uint2*)(hpb + c * 2);
            __half2 x0 = __hadd2(__hadd2(*(__half2*)&hv.x, *(__half2*)&av.x),
                                 *(__half2*)&kv.x);
            __half2 x1 = __hadd2(__hadd2(*(__half2*)&hv.y, *(__half2*)&av.y),
                                 *(__half2*)&kv.y);
            uint32_t o0 = h2silu(*(uint32_t*)&x0);
            uint32_t o1 = h2silu(*(uint32_t*)&x1);
            *(uint2*)(dst + c * 2) = make_uint2(o0, o1);
        }
    };

    build_x1(0, 0);
    __syncthreads();

    for (int h = 0; h < NHEAD; h++) {
        int sel = h & 1;
        uint32_t aBuf = sbase + (sel ? OFF_X1B : OFF_X1A) + aTile;
        float acc[4][4];
#pragma unroll
        for (int ni = 0; ni < 4; ni++)
#pragma unroll
            for (int e = 0; e < 4; e++) acc[ni][e] = 0.f;

#pragma unroll
        for (int kk = 0; kk < 8; kk++) {
            uint32_t kab = (uint32_t)kk * 32;
            uint32_t kbb = (uint32_t)kk * 16 * XROW;
            uint32_t ah[4], bh[2][4];
            ldsm_x4(ah, aBuf + kab);
            ldsm_x4t(bh[0], bHi + kbb);
            ldsm_x4t(bh[1], bHi + kbb + 32);
#pragma unroll
            for (int bx = 0; bx < 2; bx++)
#pragma unroll
                for (int hf = 0; hf < 2; hf++) {
                    int ni = 2 * bx + hf;
                    mma_f16(acc[ni], ah, bh[bx][2 * hf], bh[bx][2 * hf + 1]);
                }
        }

        // ---- epilogue: silu + w3 reduce -> SRED[sel] ----
        {
            float* SR = SRED + sel * 512;
            int colq = 2 * (lane & 3);
            float s0 = 0.f, s1 = 0.f;
#pragma unroll
            for (int ni = 0; ni < 4; ni++) {
                int col = 32 * nb + 8 * ni + colq;
                float b2a = B2S[col], b2b = B2S[col + 1];
                float w3a = W3S[col * NHEAD + h], w3b = W3S[(col + 1) * NHEAD + h];
                s0 += silu_fast(acc[ni][0] + b2a) * w3a +
                      silu_fast(acc[ni][1] + b2b) * w3b;
                s1 += silu_fast(acc[ni][2] + b2a) * w3a +
                      silu_fast(acc[ni][3] + b2b) * w3b;
            }
#pragma unroll
            for (int off = 1; off < 4; off <<= 1) {
                s0 += __shfl_xor_sync(0xffffffffu, s0, off);
                s1 += __shfl_xor_sync(0xffffffffu, s1, off);
            }
            if ((lane & 3) == 0) {
                int r0 = 16 * mb + (lane >> 2);
                SR[nb * 128 + r0] = s0;
                SR[nb * 128 + r0 + 8] = s1;
            }
        }

        // ---- build next head into the other buffer ----
        if (h < NHEAD - 1) build_x1(h + 1, sel ^ 1);

        __syncthreads();   // SRED[sel] ready; X1[sel^1] ready; X1[sel] reads done

        // ---- score write ----
        if (tid < 128) {
            float* SR = SRED + sel * 512;
            float tot = SR[tid] + SR[128 + tid] + SR[256 + tid] + SR[384 + tid];
            float sc = tot + b3[h] + mask_v;
            sc = fminf(fmaxf(sc, -1e9f), 1e9f);
            g_scores[((long)h * EN + igw) * EN + jgw] = sc;
        }
    }
}

// ---------------- K2: softmax + attn@V + coord delta ----------------
__global__ void k_softmax(const float* __restrict__ ec) {
    __shared__ float expv[EN];
    __shared__ float red[128];
    __shared__ float wred[4][20];
    __shared__ float fin[4];
    int i = blockIdx.x, h = blockIdx.y, t = threadIdx.x;
    const float* srow = &g_scores[(h * EN + i) * EN];

    float mx = -1e30f;
    for (int j = t; j < EN; j += 128) mx = fmaxf(mx, srow[j]);
    red[t] = mx;
    __syncthreads();
    for (int s = 64; s > 0; s >>= 1) {
        if (t < s) red[t] = fmaxf(red[t], red[t + s]);
        __syncthreads();
    }
    mx = red[0];
    __syncthreads();
    float sum = 0.f;
    for (int j = t; j < EN; j += 128) {
        float e = __expf(srow[j] - mx);
        expv[j] = e;
        sum += e;
    }
    red[t] = sum;
    __syncthreads();
    for (int s = 64; s > 0; s >>= 1) {
        if (t < s) red[t] += red[t + s];
        __syncthreads();
    }
    float inv = 1.0f / red[0];

    float vals[20];
#pragma unroll
    for (int q = 0; q < 20; q++) vals[q] = 0.f;
    for (int j = t; j < EN; j += 128) {
        float a = expv[j] * inv;
        const float* vr = &g_v[j * HIDN + h * DHEAD];
#pragma unroll
        for (int d = 0; d < DHEAD; d++) vals[d] += a * vr[d];
        vals[16] += a;
        vals[17] += a * ec[j * 3];
        vals[18] += a * ec[j * 3 + 1];
        vals[19] += a * ec[j * 3 + 2];
    }
#pragma unroll
    for (int off = 16; off > 0; off >>= 1)
#pragma unroll
        for (int q = 0; q < 20; q++)
            vals[q] += __shfl_xor_sync(0xffffffffu, vals[q], off);
    int lane = t & 31, warp = t >> 5;
    if (lane == 0)
#pragma unroll
        for (int q = 0; q < 20; q++) wred[warp][q] = vals[q];
    __syncthreads();
    if (t < 20) {
        float s = wred[0][t] + wred[1][t] + wred[2][t] + wred[3][t];
        if (t < 16) g_upd[i * HIDN + h * DHEAD + t] = s;
        else fin[t - 16] = s;
    }
    __syncthreads();
    if (t < 3) {
        float gate = g_gates[h * EN + i];
        g_delta[(h * EN + i) * 3 + t] = gate * (fin[0] * ec[i * 3 + t] - fin[1 + t]);
    }
}

// ---------------- K3: output projection + layernorm + coords ----------------
__global__ void k_out(const float* __restrict__ ef, const float* __restrict__ ec,
                      const float* __restrict__ wo, const float* __restrict__ bo,
                      const float* __restrict__ lg, const float* __restrict__ lb,
                      float* __restrict__ out) {
    __shared__ float u[HIDN];
    __shared__ float red[128];
    int i = blockIdx.x, n = threadIdx.x;
    u[n] = g_upd[i * HIDN + n];
    __syncthreads();
    float y = ef[i * HIDN + n] + bo[n];
#pragma unroll 8
    for (int c = 0; c < HIDN; c++) y += u[c] * wo[c * HIDN + n];
    red[n] = y;
    __syncthreads();
    for (int s = 64; s > 0; s >>= 1) {
        if (n < s) red[n] += red[n + s];
        __syncthreads();
    }
    float mean = red[0] * (1.0f / HIDN);
    __syncthreads();
    float dy = y - mean;
    red[n] = dy * dy;
    __syncthreads();
    for (int s = 64; s > 0; s >>= 1) {
        if (n < s) red[n] += red[n + s];
        __syncthreads();
    }
    float var = red[0] * (1.0f / HIDN);
    float rstd = rsqrtf(var + 1e-5f);
    out[i * HIDN + n] = dy * rstd * lg[n] + lb[n];
    if (n < 3) {
        float dsum = 0.f;
#pragma unroll
        for (int h = 0; h < NHEAD; h++) dsum += g_delta[(h * EN + i) * 3 + n];
        out[EN * HIDN + i * 3 + n] = ec[i * 3 + n] + dsum * 0.125f;
    }
}

// ---------------- launcher ----------------
extern "C" void kernel_launch(void* const* d_in, const int* in_sizes, int n_in,
                              void* d_out, int out_size) {
    const float* ef      = (const float*)d_in[0];
    const float* ec      = (const float*)d_in[1];
    const float* mask    = (const float*)d_in[2];
    const float* wq      = (const float*)d_in[3];
    const float* wk      = (const float*)d_in[4];
    const float* wv      = (const float*)d_in[5];
    const float* centers = (const float*)d_in[6];
    const float* widths  = (const float*)d_in[7];
    const float* a_w1    = (const float*)d_in[8];
    const float* a_b1    = (const float*)d_in[9];
    const float* a_w2    = (const float*)d_in[10];
    const float* a_b2    = (const float*)d_in[11];
    const float* a_w3    = (const float*)d_in[12];
    const float* a_b3    = (const float*)d_in[13];
    const float* g_w1    = (const float*)d_in[14];
    const float* g_b1    = (const float*)d_in[15];
    const float* g_w2    = (const float*)d_in[16];
    const float* g_b2    = (const float*)d_in[17];
    const float* wo      = (const float*)d_in[18];
    const float* bo      = (const float*)d_in[19];
    const float* ln_g    = (const float*)d_in[20];
    const float* ln_b    = (const float*)d_in[21];
    float* out = (float*)d_out;

    cudaFuncSetAttribute(k_scores, cudaFuncAttributeMaxDynamicSharedMemorySize,
                         SMEM_BYTES);

    k_qkv<<<dim3(EN, 3), HIDN>>>(ef, wq, wk, wv);
    k_aqak<<<dim3(EN, 2), HIDN>>>(a_w1);
    k_gates<<<dim3(EN, NHEAD), HIDN>>>(g_w1, g_b1, g_w2, g_b2);
    k_scores<<<dim3(EN / 16, EN / 8), 1024, SMEM_BYTES>>>(
        ec, mask, centers, widths, a_w1, a_b1, a_w2, a_b2, a_w3, a_b3);
    k_softmax<<<dim3(EN, NHEAD), HIDN>>>(ec);
    k_out<<<EN, HIDN>>>(ef, ec, wo, bo, ln_g, ln_b, out);
}

// round 10
// speedup vs baseline: 4.9224x; 1.0867x over previous
#include <cuda_runtime.h>
#include <cuda_fp16.h>
#include <math.h>
#include <stdint.h>

#define EN 384
#define HIDN 128
#define NHEAD 8
#define DHEAD 16
#define NRBF 64

static constexpr int SW = 132;    // fp32 staging row stride (floats)
static constexpr int XROW = 272;  // fp16 X1/W2 tile row stride (bytes)
static constexpr int HROW = 320;  // fp16 HPRE row stride (bytes)

// ---- smem byte-offset map (dynamic smem) ----
static constexpr int OFF_X1A  = 0;        // 34816  (rbf phase: rWs 33792)
static constexpr int OFF_X1B  = 34816;    // 34816  (rbf phase: rAs 33792)
static constexpr int OFF_W2H  = 69632;    // 34816
static constexpr int OFF_HPREH= 104448;   // 128*320 = 40960 -> 145408
static constexpr int OFF_SRED = 145408;   // 4096
static constexpr int OFF_B2S  = 149504;   // 512
static constexpr int OFF_W3S  = 150016;   // 4096
static constexpr int OFF_DISTS= 154112;   // 512
static constexpr int OFF_DOTS = 154624;   // 512
static constexpr int SMEM_BYTES = 155136;

// ---------------- device scratch ----------------
__device__ float g_v[EN * HIDN];
__device__ __half g_Aqh[NHEAD * EN * HIDN];
__device__ __half g_Akh[NHEAD * EN * HIDN];
__device__ float g_gates[NHEAD * EN];
__device__ float g_scores[NHEAD * EN * EN];

__device__ __forceinline__ float siluf(float x) {
    return __fdividef(x, 1.0f + __expf(-x));
}
__device__ __forceinline__ unsigned long long pack2(float lo, float hi) {
    unsigned long long r;
    asm("mov.b64 %0, {%1, %2};" : "=l"(r) : "f"(lo), "f"(hi));
    return r;
}
__device__ __forceinline__ void unpack2(unsigned long long v, float& lo, float& hi) {
    asm("mov.b64 {%0, %1}, %2;" : "=f"(lo), "=f"(hi) : "l"(v));
}
__device__ __forceinline__ void ffma2(unsigned long long& d, unsigned long long a,
                                      unsigned long long b) {
    asm("fma.rn.f32x2 %0, %1, %2, %0;" : "+l"(d) : "l"(a), "l"(b));
}
// pack two fp32 -> f16x2; x0 -> low half, x1 -> high half
__device__ __forceinline__ uint32_t f16pair(float x0, float x1) {
    uint32_t u;
    asm("cvt.rn.f16x2.f32 %0, %1, %2;" : "=r"(u) : "f"(x1), "f"(x0));
    return u;
}
__device__ __forceinline__ uint32_t h2tanh(uint32_t y) {
    uint32_t r;
    asm("tanh.approx.f16x2 %0, %1;" : "=r"(r) : "r"(y));
    return r;
}
// packed-half2 silu on raw bits: o = y + y*tanh(y), y = 0.5*x
__device__ __forceinline__ uint32_t h2silu(uint32_t xb) {
    __half2 x = *(__half2*)&xb;
    __half2 y = __hmul2(x, __half2half2(__ushort_as_half(0x3800)));  // 0.5
    uint32_t yb = *(uint32_t*)&y;
    uint32_t tb = h2tanh(yb);
    __half2 t = *(__half2*)&tb;
    __half2 o = __hfma2(y, t, y);
    return *(uint32_t*)&o;
}
__device__ __forceinline__ uint32_t smem_u32(const void* p) {
    uint32_t a;
    asm("{ .reg .u64 t; cvta.to.shared.u64 t, %1; cvt.u32.u64 %0, t; }" : "=r"(a) : "l"(p));
    return a;
}

// ---- HMMA path (compute_103-legal) ----
__device__ __forceinline__ void ldsm_x4(uint32_t* r, uint32_t addr) {
    asm volatile("ldmatrix.sync.aligned.m8n8.x4.shared.b16 {%0,%1,%2,%3}, [%4];"
                 : "=r"(r[0]), "=r"(r[1]), "=r"(r[2]), "=r"(r[3]) : "r"(addr));
}
__device__ __forceinline__ void ldsm_x4t(uint32_t* r, uint32_t addr) {
    asm volatile("ldmatrix.sync.aligned.m8n8.x4.trans.shared.b16 {%0,%1,%2,%3}, [%4];"
                 : "=r"(r[0]), "=r"(r[1]), "=r"(r[2]), "=r"(r[3]) : "r"(addr));
}
__device__ __forceinline__ void mma_f16(float* d, const uint32_t* a, uint32_t b0, uint32_t b1) {
    asm volatile(
        "mma.sync.aligned.m16n8k16.row.col.f32.f16.f16.f32 "
        "{%0,%1,%2,%3}, {%4,%5,%6,%7}, {%8,%9}, {%0,%1,%2,%3};"
        : "+f"(d[0]), "+f"(d[1]), "+f"(d[2]), "+f"(d[3])
        : "r"(a[0]), "r"(a[1]), "r"(a[2]), "r"(a[3]), "r"(b0), "r"(b1));
}

// ---------------- K_pre: qkv + Aq/Ak + gates, one block per edge ----------------
__global__ void k_pre(const float* __restrict__ ef, const float* __restrict__ wq,
                      const float* __restrict__ wk, const float* __restrict__ wv,
                      const float* __restrict__ w1,
                      const float* __restrict__ gw1, const float* __restrict__ gb1,
                      const float* __restrict__ gw2, const float* __restrict__ gb2) {
    __shared__ float row[HIDN], qrow[HIDN], krow[HIDN], vrow[HIDN];
    __shared__ float wpart[4][NHEAD];
    int i = blockIdx.x, n = threadIdx.x;
    int lane = n & 31, warp = n >> 5;
    row[n] = ef[i * HIDN + n];
    __syncthreads();
    float qa = 0.f, ka = 0.f, va = 0.f;
#pragma unroll 4
    for (int c = 0; c < HIDN; c++) {
        float r = row[c];
        qa = fmaf(r, wq[c * HIDN + n], qa);
        ka = fmaf(r, wk[c * HIDN + n], ka);
        va = fmaf(r, wv[c * HIDN + n], va);
    }
    qrow[n] = qa; krow[n] = ka; vrow[n] = va;
    g_v[i * HIDN + n] = va;
    __syncthreads();
#pragma unroll 1
    for (int h = 0; h < NHEAD; h++) {
        float aq = 0.f, ak = 0.f;
#pragma unroll
        for (int d = 0; d < DHEAD; d++) {
            aq = fmaf(qrow[h * DHEAD + d], w1[d * HIDN + n], aq);
            ak = fmaf(krow[h * DHEAD + d], w1[(DHEAD + d) * HIDN + n], ak);
        }
        g_Aqh[((long)h * EN + i) * HIDN + n] = __float2half_rn(aq);
        g_Akh[((long)h * EN + i) * HIDN + n] = __float2half_rn(ak);
    }
    // gates
#pragma unroll 1
    for (int h = 0; h < NHEAD; h++) {
        float acc = gb1[n];
#pragma unroll
        for (int d = 0; d < DHEAD; d++)
            acc = fmaf(vrow[h * DHEAD + d], gw1[d * HIDN + n], acc);
        float val = siluf(acc) * gw2[n];
#pragma unroll
        for (int off = 16; off > 0; off >>= 1)
            val += __shfl_xor_sync(0xffffffffu, val, off);
        if (lane == 0) wpart[warp][h] = val;
    }
    __syncthreads();
    if (n < NHEAD) {
        float s = wpart[0][n] + wpart[1][n] + wpart[2][n] + wpart[3][n];
        g_gates[n * EN + i] = 1.0f / (1.0f + __expf(-(s + gb2[0])));
    }
}

// ---------------- FFMA2 register-tile GEMM (rbf layer only) ----------------
__device__ __forceinline__ void gemm_run(const float* __restrict__ A,
                                         const float* __restrict__ B, int K,
                                         int ty, int tx,
                                         unsigned long long acc[4][4]) {
    const float* ap = A + ty * 8;
    const float* bp = B + tx * 4;
#pragma unroll 2
    for (int c = 0; c < K; c++, ap += SW, bp += SW) {
        ulonglong2 a01 = *(const ulonglong2*)ap;
        ulonglong2 a23 = *(const ulonglong2*)(ap + 4);
        unsigned long long av[4] = {a01.x, a01.y, a23.x, a23.y};
        float4 w = *(const float4*)bp;
        unsigned long long bd[4] = {pack2(w.x, w.x), pack2(w.y, w.y),
                                    pack2(w.z, w.z), pack2(w.w, w.w)};
#pragma unroll
        for (int pp = 0; pp < 4; pp++)
#pragma unroll
            for (int jj = 0; jj < 4; jj++) ffma2(acc[pp][jj], av[pp], bd[jj]);
    }
}

// ---------------- K1: fused pair-MLP -> attention scores ----------------
__global__ void __launch_bounds__(1024, 1)
k_scores(const float* __restrict__ ec, const float* __restrict__ mask,
         const float* __restrict__ centers, const float* __restrict__ widths,
         const float* __restrict__ w1, const float* __restrict__ b1,
         const float* __restrict__ w2, const float* __restrict__ b2,
         const float* __restrict__ w3, const float* __restrict__ b3) {
    extern __shared__ float smem_f[];
    char* smem_c = (char*)smem_f;
    float* rWs   = (float*)(smem_c + OFF_X1A);
    float* rAs   = (float*)(smem_c + OFF_X1B);
    float* SRED  = (float*)(smem_c + OFF_SRED);
    float* B2S   = (float*)(smem_c + OFF_B2S);
    float* W3S   = (float*)(smem_c + OFF_W3S);
    float* dists = (float*)(smem_c + OFF_DISTS);
    float* dots  = (float*)(smem_c + OFF_DOTS);

    uint32_t sbase = smem_u32(smem_c);

    int tid = threadIdx.x;
    int w = tid >> 5, lane = tid & 31;
    int bi = blockIdx.x, bj = blockIdx.y;

    int p = tid >> 3;
    int lq = tid & 7;
    int ig_p = bi * 16 + (p >> 3);
    int jg_p = bj * 8 + (p & 7);

    if (tid < 128) {
        int pp = tid;
        int i = bi * 16 + (pp >> 3);
        int j = bj * 8 + (pp & 7);
        float ix = ec[i * 3], iy = ec[i * 3 + 1], iz = ec[i * 3 + 2];
        float jx = ec[j * 3], jy = ec[j * 3 + 1], jz = ec[j * 3 + 2];
        float dx = ix - jx, dy = iy - jy, dz = iz - jz;
        float d = sqrtf(dx * dx + dy * dy + dz * dz) + 1e-8f;
        d = fminf(fmaxf(d, 1e-8f), 1e8f);
        dists[pp] = d;
        float dt = ix * jx + iy * jy + iz * jz;
        dots[pp] = fminf(fmaxf(dt, -1e8f), 1e8f);
    }
    for (int idx = tid; idx < NRBF * HIDN / 4; idx += 1024) {
        int r = idx >> 5, col = (idx & 31) * 4;
        *(float4*)(rWs + r * SW + col) = *(const float4*)(w1 + (2 * DHEAD + r) * HIDN + col);
    }
    for (int idx = tid; idx < HIDN * HIDN; idx += 1024) {
        int c = idx >> 7;
        int n = idx & 127;
        __half hv = __float2half_rn(w2[idx]);
        *(unsigned short*)(smem_c + OFF_W2H + c * XROW + n * 2) = __half_as_ushort(hv);
    }
    if (tid < 128) B2S[tid] = b2[tid];
    for (int idx = tid; idx < HIDN * NHEAD; idx += 1024) W3S[idx] = w3[idx];
    __syncthreads();

    for (int idx = tid; idx < NRBF * 128; idx += 1024) {
        int pp = idx & 127, r = idx >> 7;
        float d = dists[pp];
        float t = d - centers[r];
        rAs[r * SW + pp] = (d <= 10.0f) ? __expf(-widths[r] * t * t) : 0.0f;
    }
    __syncthreads();

    if (tid < 512) {
        int tx = lane, ty = w;
        unsigned long long acc[4][4];
#pragma unroll
        for (int pp2 = 0; pp2 < 4; pp2++)
#pragma unroll
            for (int jj = 0; jj < 4; jj++) acc[pp2][jj] = 0ull;
        gemm_run(rAs, rWs, NRBF, ty, tx, acc);
        float4 wdot = *(const float4*)(w1 + 96 * HIDN + tx * 4);
        float wd[4] = {wdot.x, wdot.y, wdot.z, wdot.w};
        float4 b1v = *(const float4*)(b1 + tx * 4);
        float b1r[4] = {b1v.x, b1v.y, b1v.z, b1v.w};
#pragma unroll
        for (int pp2 = 0; pp2 < 4; pp2++) {
            int row0 = ty * 8 + 2 * pp2;
            float2 dp = *(const float2*)(dots + row0);
            float vl[4], vh[4];
#pragma unroll
            for (int jj = 0; jj < 4; jj++) {
                float lo, hi;
                unpack2(acc[pp2][jj], lo, hi);
                vl[jj] = lo + dp.x * wd[jj] + b1r[jj];
                vh[jj] = hi + dp.y * wd[jj] + b1r[jj];
            }
            uint32_t off = (uint32_t)row0 * HROW + tx * 8;
            *(uint2*)(smem_c + OFF_HPREH + off) =
                make_uint2(f16pair(vl[0], vl[1]), f16pair(vl[2], vl[3]));
            *(uint2*)(smem_c + OFF_HPREH + off + HROW) =
                make_uint2(f16pair(vh[0], vh[1]), f16pair(vh[2], vh[3]));
        }
    }
    __syncthreads();

    int mb = w & 7, nb = w >> 3;
    int r16 = lane & 15, rh = lane >> 4;
    uint32_t aTile = (uint32_t)(16 * mb + r16) * XROW + rh * 16;
    uint32_t bHi = sbase + OFF_W2H + (uint32_t)r16 * XROW + 64 * nb + 16 * rh;

    float mask_v = 0.f;
    int igw = 0, jgw = 0;
    if (tid < 128) {
        igw = bi * 16 + (tid >> 3);
        jgw = bj * 8 + (tid & 7);
        mask_v = __ldg(mask + (long)igw * EN + jgw);
    }

    const char* hpb = smem_c + OFF_HPREH + p * HROW;
    auto build_x1 = [&](int h, int sel) {
        char* dst = smem_c + (sel ? OFF_X1B : OFF_X1A) + p * XROW;
        const __half* aqp = g_Aqh + ((long)(h * EN + ig_p)) * HIDN;
        const __half* akp = g_Akh + ((long)(h * EN + jg_p)) * HIDN;
#pragma unroll
        for (int q = 0; q < 4; q++) {
            int c = lq * 4 + 32 * q;
            uint2 av = __ldg((const uint2*)(aqp + c));
            uint2 kv = __ldg((const uint2*)(akp + c));
            uint2 hv = *(const uint2*)(hpb + c * 2);
            __half2 x0 = __hadd2(__hadd2(*(__half2*)&hv.x, *(__half2*)&av.x),
                                 *(__half2*)&kv.x);
            __half2 x1 = __hadd2(__hadd2(*(__half2*)&hv.y, *(__half2*)&av.y),
                                 *(__half2*)&kv.y);
            uint32_t o0 = h2silu(*(uint32_t*)&x0);
            uint32_t o1 = h2silu(*(uint32_t*)&x1);
            *(uint2*)(dst + c * 2) = make_uint2(o0, o1);
        }
    };

    build_x1(0, 0);
    __syncthreads();

    for (int h = 0; h < NHEAD; h++) {
        int sel = h & 1;
        uint32_t aBuf = sbase + (sel ? OFF_X1B : OFF_X1A) + aTile;
        float acc[4][4];
#pragma unroll
        for (int ni = 0; ni < 4; ni++)
#pragma unroll
            for (int e = 0; e < 4; e++) acc[ni][e] = 0.f;

#pragma unroll
        for (int kk = 0; kk < 8; kk++) {
            uint32_t kab = (uint32_t)kk * 32;
            uint32_t kbb = (uint32_t)kk * 16 * XROW;
            uint32_t ah[4], bh[2][4];
            ldsm_x4(ah, aBuf + kab);
            ldsm_x4t(bh[0], bHi + kbb);
            ldsm_x4t(bh[1], bHi + kbb + 32);
#pragma unroll
            for (int bx = 0; bx < 2; bx++)
#pragma unroll
                for (int hf = 0; hf < 2; hf++) {
                    int ni = 2 * bx + hf;
                    mma_f16(acc[ni], ah, bh[bx][2 * hf], bh[bx][2 * hf + 1]);
                }
        }

        // ---- epilogue: packed fp16 silu + w3 reduce -> SRED[sel] ----
        {
            float* SR = SRED + sel * 512;
            int colq = 2 * (lane & 3);
            float s0 = 0.f, s1 = 0.f;
#pragma unroll
            for (int ni = 0; ni < 4; ni++) {
                int col = 32 * nb + 8 * ni + colq;
                float b2a = B2S[col], b2b = B2S[col + 1];
                float w3a = W3S[col * NHEAD + h], w3b = W3S[(col + 1) * NHEAD + h];
                uint32_t u0 = h2silu(f16pair(acc[ni][0] + b2a, acc[ni][1] + b2b));
                float2 f0 = __half22float2(*(__half2*)&u0);
                s0 += f0.x * w3a + f0.y * w3b;
                uint32_t u1 = h2silu(f16pair(acc[ni][2] + b2a, acc[ni][3] + b2b));
                float2 f1 = __half22float2(*(__half2*)&u1);
                s1 += f1.x * w3a + f1.y * w3b;
            }
#pragma unroll
            for (int off = 1; off < 4; off <<= 1) {
                s0 += __shfl_xor_sync(0xffffffffu, s0, off);
                s1 += __shfl_xor_sync(0xffffffffu, s1, off);
            }
            if ((lane & 3) == 0) {
                int r0 = 16 * mb + (lane >> 2);
                SR[nb * 128 + r0] = s0;
                SR[nb * 128 + r0 + 8] = s1;
            }
        }

        if (h < NHEAD - 1) build_x1(h + 1, sel ^ 1);

        __syncthreads();

        if (tid < 128) {
            float* SR = SRED + sel * 512;
            float tot = SR[tid] + SR[128 + tid] + SR[256 + tid] + SR[384 + tid];
            float sc = tot + b3[h] + mask_v;
            sc = fminf(fmaxf(sc, -1e9f), 1e9f);
            g_scores[((long)h * EN + igw) * EN + jgw] = sc;
        }
    }
}

// ---------------- K_post: softmax + attn@V + coords + out-proj + layernorm ----------------
// One block per edge i, 384 threads (one per key j).
__global__ void __launch_bounds__(EN, 1)
k_post(const float* __restrict__ ec, const float* __restrict__ ef,
       const float* __restrict__ wo, const float* __restrict__ bo,
       const float* __restrict__ lg, const float* __restrict__ lb,
       float* __restrict__ out) {
    __shared__ float att[EN];
    __shared__ float part[12];
    __shared__ float upd[HIDN];
    __shared__ float fin[4];
    __shared__ float dacc[3];
    __shared__ float red[128];

    int i = blockIdx.x, t = threadIdx.x;
    int lane = t & 31, warp = t >> 5;
    if (t < 3) dacc[t] = 0.f;

    for (int h = 0; h < NHEAD; h++) {
        float s = g_scores[((long)h * EN + i) * EN + t];
        // block max
        float m = s;
#pragma unroll
        for (int off = 16; off > 0; off >>= 1)
            m = fmaxf(m, __shfl_xor_sync(0xffffffffu, m, off));
        if (lane == 0) part[warp] = m;
        __syncthreads();
        float mx = part[0];
#pragma unroll
        for (int k = 1; k < 12; k++) mx = fmaxf(mx, part[k]);
        float e = __expf(s - mx);
        __syncthreads();   // part reuse
        float ss = e;
#pragma unroll
        for (int off = 16; off > 0; off >>= 1)
            ss += __shfl_xor_sync(0xffffffffu, ss, off);
        if (lane == 0) part[warp] = ss;
        __syncthreads();
        float tot = 0.f;
#pragma unroll
        for (int k = 0; k < 12; k++) tot += part[k];
        att[t] = e * (1.0f / tot);
        __syncthreads();

        // regrouped A@V + coord sums: 20 outputs x 16 sub-threads
        if (t < 320) {
            int o = t >> 4, sub = t & 15;
            float a2 = 0.f;
            if (o < 16) {
                const float* vp = g_v + h * DHEAD + o;
#pragma unroll 4
                for (int j = sub; j < EN; j += 16) a2 += att[j] * vp[j * HIDN];
            } else if (o == 16) {
#pragma unroll 4
                for (int j = sub; j < EN; j += 16) a2 += att[j];
            } else {
                const float* cp = ec + (o - 17);
#pragma unroll 4
                for (int j = sub; j < EN; j += 16) a2 += att[j] * cp[j * 3];
            }
#pragma unroll
            for (int off = 8; off > 0; off >>= 1)
                a2 += __shfl_xor_sync(0xffffffffu, a2, off);
            if (sub == 0) {
                if (o < 16) upd[h * DHEAD + o] = a2;
                else fin[o - 16] = a2;
            }
        }
        __syncthreads();
        if (t < 3)
            dacc[t] += g_gates[h * EN + i] * (fin[0] * ec[i * 3 + t] - fin[1 + t]);
        __syncthreads();
    }

    // ---- output projection + layernorm (threads 0..127) ----
    float y = 0.f;
    if (t < 128) {
        y = ef[i * HIDN + t] + bo[t];
#pragma unroll 8
        for (int c = 0; c < HIDN; c++) y = fmaf(upd[c], wo[c * HIDN + t], y);
        red[t] = y;
    }
    __syncthreads();
    for (int s2 = 64; s2 > 0; s2 >>= 1) {
        if (t < s2) red[t] += red[t + s2];
        __syncthreads();
    }
    float mean = red[0] * (1.0f / HIDN);
    __syncthreads();
    float dy = y - mean;
    if (t < 128) red[t] = dy * dy;
    __syncthreads();
    for (int s2 = 64; s2 > 0; s2 >>= 1) {
        if (t < s2) red[t] += red[t + s2];
        __syncthreads();
    }
    float var = red[0] * (1.0f / HIDN);
    float rstd = rsqrtf(var + 1e-5f);
    if (t < 128) out[i * HIDN + t] = dy * rstd * lg[t] + lb[t];
    if (t < 3) out[EN * HIDN + i * 3 + t] = ec[i * 3 + t] + dacc[t] * 0.125f;
}

// ---------------- launcher ----------------
extern "C" void kernel_launch(void* const* d_in, const int* in_sizes, int n_in,
                              void* d_out, int out_size) {
    const float* ef      = (const float*)d_in[0];
    const float* ec      = (const float*)d_in[1];
    const float* mask    = (const float*)d_in[2];
    const float* wq      = (const float*)d_in[3];
    const float* wk      = (const float*)d_in[4];
    const float* wv      = (const float*)d_in[5];
    const float* centers = (const float*)d_in[6];
    const float* widths  = (const float*)d_in[7];
    const float* a_w1    = (const float*)d_in[8];
    const float* a_b1    = (const float*)d_in[9];
    const float* a_w2    = (const float*)d_in[10];
    const float* a_b2    = (const float*)d_in[11];
    const float* a_w3    = (const float*)d_in[12];
    const float* a_b3    = (const float*)d_in[13];
    const float* g_w1    = (const float*)d_in[14];
    const float* g_b1    = (const float*)d_in[15];
    const float* g_w2    = (const float*)d_in[16];
    const float* g_b2    = (const float*)d_in[17];
    const float* wo      = (const float*)d_in[18];
    const float* bo      = (const float*)d_in[19];
    const float* ln_g    = (const float*)d_in[20];
    const float* ln_b    = (const float*)d_in[21];
    float* out = (float*)d_out;

    cudaFuncSetAttribute(k_scores, cudaFuncAttributeMaxDynamicSharedMemorySize,
                         SMEM_BYTES);

    k_pre<<<EN, HIDN>>>(ef, wq, wk, wv, a_w1, g_w1, g_b1, g_w2, g_b2);
    k_scores<<<dim3(EN / 16, EN / 8), 1024, SMEM_BYTES>>>(
        ec, mask, centers, widths, a_w1, a_b1, a_w2, a_b2, a_w3, a_b3);
    k_post<<<EN, EN>>>(ec, ef, wo, bo, ln_g, ln_b, out);
}

// round 11
// speedup vs baseline: 5.3317x; 1.0831x over previous
#include <cuda_runtime.h>
#include <cuda_fp16.h>
#include <math.h>
#include <stdint.h>

#define EN 384
#define HIDN 128
#define NHEAD 8
#define DHEAD 16
#define NRBF 64

static constexpr int SW = 132;    // fp32 staging row stride (floats)
static constexpr int XROW = 272;  // fp16 X1/W2 tile row stride (bytes)
static constexpr int HROW = 320;  // fp16 HPRE row stride (bytes)

// ---- smem byte-offset map (dynamic smem) ----
static constexpr int OFF_X1A  = 0;
static constexpr int OFF_X1B  = 34816;
static constexpr int OFF_W2H  = 69632;
static constexpr int OFF_HPREH= 104448;
static constexpr int OFF_SRED = 145408;
static constexpr int OFF_B2S  = 149504;
static constexpr int OFF_W3S  = 150016;
static constexpr int OFF_DISTS= 154112;
static constexpr int OFF_DOTS = 154624;
static constexpr int SMEM_BYTES = 155136;

// ---------------- device scratch ----------------
__device__ float g_v[EN * HIDN];
__device__ __half g_Aqh[NHEAD * EN * HIDN];
__device__ __half g_Akh[NHEAD * EN * HIDN];
__device__ float g_gates[NHEAD * EN];
__device__ float g_scores[NHEAD * EN * EN];

__device__ __forceinline__ float siluf(float x) {
    return __fdividef(x, 1.0f + __expf(-x));
}
__device__ __forceinline__ unsigned long long pack2(float lo, float hi) {
    unsigned long long r;
    asm("mov.b64 %0, {%1, %2};" : "=l"(r) : "f"(lo), "f"(hi));
    return r;
}
__device__ __forceinline__ void unpack2(unsigned long long v, float& lo, float& hi) {
    asm("mov.b64 {%0, %1}, %2;" : "=f"(lo), "=f"(hi) : "l"(v));
}
__device__ __forceinline__ void ffma2(unsigned long long& d, unsigned long long a,
                                      unsigned long long b) {
    asm("fma.rn.f32x2 %0, %1, %2, %0;" : "+l"(d) : "l"(a), "l"(b));
}
__device__ __forceinline__ uint32_t f16pair(float x0, float x1) {
    uint32_t u;
    asm("cvt.rn.f16x2.f32 %0, %1, %2;" : "=r"(u) : "f"(x1), "f"(x0));
    return u;
}
__device__ __forceinline__ uint32_t h2tanh(uint32_t y) {
    uint32_t r;
    asm("tanh.approx.f16x2 %0, %1;" : "=r"(r) : "r"(y));
    return r;
}
__device__ __forceinline__ uint32_t h2silu(uint32_t xb) {
    __half2 x = *(__half2*)&xb;
    __half2 y = __hmul2(x, __half2half2(__ushort_as_half(0x3800)));  // 0.5
    uint32_t yb = *(uint32_t*)&y;
    uint32_t tb = h2tanh(yb);
    __half2 t = *(__half2*)&tb;
    __half2 o = __hfma2(y, t, y);
    return *(uint32_t*)&o;
}
__device__ __forceinline__ uint32_t smem_u32(const void* p) {
    uint32_t a;
    asm("{ .reg .u64 t; cvta.to.shared.u64 t, %1; cvt.u32.u64 %0, t; }" : "=r"(a) : "l"(p));
    return a;
}

// ---- HMMA path ----
__device__ __forceinline__ void ldsm_x4(uint32_t* r, uint32_t addr) {
    asm volatile("ldmatrix.sync.aligned.m8n8.x4.shared.b16 {%0,%1,%2,%3}, [%4];"
                 : "=r"(r[0]), "=r"(r[1]), "=r"(r[2]), "=r"(r[3]) : "r"(addr));
}
__device__ __forceinline__ void ldsm_x4t(uint32_t* r, uint32_t addr) {
    asm volatile("ldmatrix.sync.aligned.m8n8.x4.trans.shared.b16 {%0,%1,%2,%3}, [%4];"
                 : "=r"(r[0]), "=r"(r[1]), "=r"(r[2]), "=r"(r[3]) : "r"(addr));
}
__device__ __forceinline__ void mma_f16(float* d, const uint32_t* a, uint32_t b0, uint32_t b1) {
    asm volatile(
        "mma.sync.aligned.m16n8k16.row.col.f32.f16.f16.f32 "
        "{%0,%1,%2,%3}, {%4,%5,%6,%7}, {%8,%9}, {%0,%1,%2,%3};"
        : "+f"(d[0]), "+f"(d[1]), "+f"(d[2]), "+f"(d[3])
        : "r"(a[0]), "r"(a[1]), "r"(a[2]), "r"(a[3]), "r"(b0), "r"(b1));
}

// ---------------- K_pre: qkv + Aq/Ak + gates, one block per edge, 256 threads ----------------
__global__ void __launch_bounds__(256, 4)
k_pre(const float* __restrict__ ef, const float* __restrict__ wq,
      const float* __restrict__ wk, const float* __restrict__ wv,
      const float* __restrict__ w1,
      const float* __restrict__ gw1, const float* __restrict__ gb1,
      const float* __restrict__ gw2, const float* __restrict__ gb2) {
    __shared__ float row[HIDN], qrow[HIDN], krow[HIDN], vrow[HIDN];
    __shared__ float wpart[4][NHEAD];
    int i = blockIdx.x, tid = threadIdx.x;
    int n = tid & 127, half = tid >> 7;
    int lane = tid & 31;
    if (tid < 128) row[tid] = ef[i * HIDN + tid];
    __syncthreads();

    if (half == 0) {
        float qa = 0.f, va = 0.f;
#pragma unroll 4
        for (int c = 0; c < HIDN; c++) {
            float r = row[c];
            qa = fmaf(r, wq[c * HIDN + n], qa);
            va = fmaf(r, wv[c * HIDN + n], va);
        }
        qrow[n] = qa; vrow[n] = va;
        g_v[i * HIDN + n] = va;
    } else {
        float ka = 0.f;
#pragma unroll 4
        for (int c = 0; c < HIDN; c++)
            ka = fmaf(row[c], wk[c * HIDN + n], ka);
        krow[n] = ka;
    }
    __syncthreads();

    if (half == 0) {
#pragma unroll 1
        for (int h = 0; h < NHEAD; h++) {
            float aq = 0.f;
#pragma unroll
            for (int d = 0; d < DHEAD; d++)
                aq = fmaf(qrow[h * DHEAD + d], w1[d * HIDN + n], aq);
            g_Aqh[((long)h * EN + i) * HIDN + n] = __float2half_rn(aq);
        }
    } else {
#pragma unroll 1
        for (int h = 0; h < NHEAD; h++) {
            float ak = 0.f;
#pragma unroll
            for (int d = 0; d < DHEAD; d++)
                ak = fmaf(krow[h * DHEAD + d], w1[(DHEAD + d) * HIDN + n], ak);
            g_Akh[((long)h * EN + i) * HIDN + n] = __float2half_rn(ak);
        }
        // gates (warps 4..7 -> local warp index (tid>>5)-4)
#pragma unroll 1
        for (int h = 0; h < NHEAD; h++) {
            float acc = gb1[n];
#pragma unroll
            for (int d = 0; d < DHEAD; d++)
                acc = fmaf(vrow[h * DHEAD + d], gw1[d * HIDN + n], acc);
            float val = siluf(acc) * gw2[n];
#pragma unroll
            for (int off = 16; off > 0; off >>= 1)
                val += __shfl_xor_sync(0xffffffffu, val, off);
            if (lane == 0) wpart[(tid >> 5) - 4][h] = val;
        }
    }
    __syncthreads();
    if (tid < NHEAD) {
        float s = wpart[0][tid] + wpart[1][tid] + wpart[2][tid] + wpart[3][tid];
        g_gates[tid * EN + i] = 1.0f / (1.0f + __expf(-(s + gb2[0])));
    }
}

// ---------------- FFMA2 register-tile GEMM (rbf layer only) ----------------
__device__ __forceinline__ void gemm_run(const float* __restrict__ A,
                                         const float* __restrict__ B, int K,
                                         int ty, int tx,
                                         unsigned long long acc[4][4]) {
    const float* ap = A + ty * 8;
    const float* bp = B + tx * 4;
#pragma unroll 2
    for (int c = 0; c < K; c++, ap += SW, bp += SW) {
        ulonglong2 a01 = *(const ulonglong2*)ap;
        ulonglong2 a23 = *(const ulonglong2*)(ap + 4);
        unsigned long long av[4] = {a01.x, a01.y, a23.x, a23.y};
        float4 w = *(const float4*)bp;
        unsigned long long bd[4] = {pack2(w.x, w.x), pack2(w.y, w.y),
                                    pack2(w.z, w.z), pack2(w.w, w.w)};
#pragma unroll
        for (int pp = 0; pp < 4; pp++)
#pragma unroll
            for (int jj = 0; jj < 4; jj++) ffma2(acc[pp][jj], av[pp], bd[jj]);
    }
}

// ---------------- K1: fused pair-MLP -> attention scores (unchanged core) ----------------
__global__ void __launch_bounds__(1024, 1)
k_scores(const float* __restrict__ ec, const float* __restrict__ mask,
         const float* __restrict__ centers, const float* __restrict__ widths,
         const float* __restrict__ w1, const float* __restrict__ b1,
         const float* __restrict__ w2, const float* __restrict__ b2,
         const float* __restrict__ w3, const float* __restrict__ b3) {
    extern __shared__ float smem_f[];
    char* smem_c = (char*)smem_f;
    float* rWs   = (float*)(smem_c + OFF_X1A);
    float* rAs   = (float*)(smem_c + OFF_X1B);
    float* SRED  = (float*)(smem_c + OFF_SRED);
    float* B2S   = (float*)(smem_c + OFF_B2S);
    float* W3S   = (float*)(smem_c + OFF_W3S);
    float* dists = (float*)(smem_c + OFF_DISTS);
    float* dots  = (float*)(smem_c + OFF_DOTS);

    uint32_t sbase = smem_u32(smem_c);

    int tid = threadIdx.x;
    int w = tid >> 5, lane = tid & 31;
    int bi = blockIdx.x, bj = blockIdx.y;

    int p = tid >> 3;
    int lq = tid & 7;
    int ig_p = bi * 16 + (p >> 3);
    int jg_p = bj * 8 + (p & 7);

    if (tid < 128) {
        int pp = tid;
        int i = bi * 16 + (pp >> 3);
        int j = bj * 8 + (pp & 7);
        float ix = ec[i * 3], iy = ec[i * 3 + 1], iz = ec[i * 3 + 2];
        float jx = ec[j * 3], jy = ec[j * 3 + 1], jz = ec[j * 3 + 2];
        float dx = ix - jx, dy = iy - jy, dz = iz - jz;
        float d = sqrtf(dx * dx + dy * dy + dz * dz) + 1e-8f;
        d = fminf(fmaxf(d, 1e-8f), 1e8f);
        dists[pp] = d;
        float dt = ix * jx + iy * jy + iz * jz;
        dots[pp] = fminf(fmaxf(dt, -1e8f), 1e8f);
    }
    for (int idx = tid; idx < NRBF * HIDN / 4; idx += 1024) {
        int r = idx >> 5, col = (idx & 31) * 4;
        *(float4*)(rWs + r * SW + col) = *(const float4*)(w1 + (2 * DHEAD + r) * HIDN + col);
    }
    for (int idx = tid; idx < HIDN * HIDN; idx += 1024) {
        int c = idx >> 7;
        int n = idx & 127;
        __half hv = __float2half_rn(w2[idx]);
        *(unsigned short*)(smem_c + OFF_W2H + c * XROW + n * 2) = __half_as_ushort(hv);
    }
    if (tid < 128) B2S[tid] = b2[tid];
    for (int idx = tid; idx < HIDN * NHEAD; idx += 1024) W3S[idx] = w3[idx];
    __syncthreads();

    for (int idx = tid; idx < NRBF * 128; idx += 1024) {
        int pp = idx & 127, r = idx >> 7;
        float d = dists[pp];
        float t = d - centers[r];
        rAs[r * SW + pp] = (d <= 10.0f) ? __expf(-widths[r] * t * t) : 0.0f;
    }
    __syncthreads();

    if (tid < 512) {
        int tx = lane, ty = w;
        unsigned long long acc[4][4];
#pragma unroll
        for (int pp2 = 0; pp2 < 4; pp2++)
#pragma unroll
            for (int jj = 0; jj < 4; jj++) acc[pp2][jj] = 0ull;
        gemm_run(rAs, rWs, NRBF, ty, tx, acc);
        float4 wdot = *(const float4*)(w1 + 96 * HIDN + tx * 4);
        float wd[4] = {wdot.x, wdot.y, wdot.z, wdot.w};
        float4 b1v = *(const float4*)(b1 + tx * 4);
        float b1r[4] = {b1v.x, b1v.y, b1v.z, b1v.w};
#pragma unroll
        for (int pp2 = 0; pp2 < 4; pp2++) {
            int row0 = ty * 8 + 2 * pp2;
            float2 dp = *(const float2*)(dots + row0);
            float vl[4], vh[4];
#pragma unroll
            for (int jj = 0; jj < 4; jj++) {
                float lo, hi;
                unpack2(acc[pp2][jj], lo, hi);
                vl[jj] = lo + dp.x * wd[jj] + b1r[jj];
                vh[jj] = hi + dp.y * wd[jj] + b1r[jj];
            }
            uint32_t off = (uint32_t)row0 * HROW + tx * 8;
            *(uint2*)(smem_c + OFF_HPREH + off) =
                make_uint2(f16pair(vl[0], vl[1]), f16pair(vl[2], vl[3]));
            *(uint2*)(smem_c + OFF_HPREH + off + HROW) =
                make_uint2(f16pair(vh[0], vh[1]), f16pair(vh[2], vh[3]));
        }
    }
    __syncthreads();

    int mb = w & 7, nb = w >> 3;
    int r16 = lane & 15, rh = lane >> 4;
    uint32_t aTile = (uint32_t)(16 * mb + r16) * XROW + rh * 16;
    uint32_t bHi = sbase + OFF_W2H + (uint32_t)r16 * XROW + 64 * nb + 16 * rh;

    float mask_v = 0.f;
    int igw = 0, jgw = 0;
    if (tid < 128) {
        igw = bi * 16 + (tid >> 3);
        jgw = bj * 8 + (tid & 7);
        mask_v = __ldg(mask + (long)igw * EN + jgw);
    }

    const char* hpb = smem_c + OFF_HPREH + p * HROW;
    auto build_x1 = [&](int h, int sel) {
        char* dst = smem_c + (sel ? OFF_X1B : OFF_X1A) + p * XROW;
        const __half* aqp = g_Aqh + ((long)(h * EN + ig_p)) * HIDN;
        const __half* akp = g_Akh + ((long)(h * EN + jg_p)) * HIDN;
#pragma unroll
        for (int q = 0; q < 4; q++) {
            int c = lq * 4 + 32 * q;
            uint2 av = __ldg((const uint2*)(aqp + c));
            uint2 kv = __ldg((const uint2*)(akp + c));
            uint2 hv = *(const uint2*)(hpb + c * 2);
            __half2 x0 = __hadd2(__hadd2(*(__half2*)&hv.x, *(__half2*)&av.x),
                                 *(__half2*)&kv.x);
            __half2 x1 = __hadd2(__hadd2(*(__half2*)&hv.y, *(__half2*)&av.y),
                                 *(__half2*)&kv.y);
            uint32_t o0 = h2silu(*(uint32_t*)&x0);
            uint32_t o1 = h2silu(*(uint32_t*)&x1);
            *(uint2*)(dst + c * 2) = make_uint2(o0, o1);
        }
    };

    build_x1(0, 0);
    __syncthreads();

    for (int h = 0; h < NHEAD; h++) {
        int sel = h & 1;
        uint32_t aBuf = sbase + (sel ? OFF_X1B : OFF_X1A) + aTile;
        float acc[4][4];
#pragma unroll
        for (int ni = 0; ni < 4; ni++)
#pragma unroll
            for (int e = 0; e < 4; e++) acc[ni][e] = 0.f;

#pragma unroll
        for (int kk = 0; kk < 8; kk++) {
            uint32_t kab = (uint32_t)kk * 32;
            uint32_t kbb = (uint32_t)kk * 16 * XROW;
            uint32_t ah[4], bh[2][4];
            ldsm_x4(ah, aBuf + kab);
            ldsm_x4t(bh[0], bHi + kbb);
            ldsm_x4t(bh[1], bHi + kbb + 32);
#pragma unroll
            for (int bx = 0; bx < 2; bx++)
#pragma unroll
                for (int hf = 0; hf < 2; hf++) {
                    int ni = 2 * bx + hf;
                    mma_f16(acc[ni], ah, bh[bx][2 * hf], bh[bx][2 * hf + 1]);
                }
        }

        {
            float* SR = SRED + sel * 512;
            int colq = 2 * (lane & 3);
            float s0 = 0.f, s1 = 0.f;
#pragma unroll
            for (int ni = 0; ni < 4; ni++) {
                int col = 32 * nb + 8 * ni + colq;
                float b2a = B2S[col], b2b = B2S[col + 1];
                float w3a = W3S[col * NHEAD + h], w3b = W3S[(col + 1) * NHEAD + h];
                uint32_t u0 = h2silu(f16pair(acc[ni][0] + b2a, acc[ni][1] + b2b));
                float2 f0 = __half22float2(*(__half2*)&u0);
                s0 += f0.x * w3a + f0.y * w3b;
                uint32_t u1 = h2silu(f16pair(acc[ni][2] + b2a, acc[ni][3] + b2b));
                float2 f1 = __half22float2(*(__half2*)&u1);
                s1 += f1.x * w3a + f1.y * w3b;
            }
#pragma unroll
            for (int off = 1; off < 4; off <<= 1) {
                s0 += __shfl_xor_sync(0xffffffffu, s0, off);
                s1 += __shfl_xor_sync(0xffffffffu, s1, off);
            }
            if ((lane & 3) == 0) {
                int r0 = 16 * mb + (lane >> 2);
                SR[nb * 128 + r0] = s0;
                SR[nb * 128 + r0 + 8] = s1;
            }
        }

        if (h < NHEAD - 1) build_x1(h + 1, sel ^ 1);

        __syncthreads();

        if (tid < 128) {
            float* SR = SRED + sel * 512;
            float tot = SR[tid] + SR[128 + tid] + SR[256 + tid] + SR[384 + tid];
            float sc = tot + b3[h] + mask_v;
            sc = fminf(fmaxf(sc, -1e9f), 1e9f);
            g_scores[((long)h * EN + igw) * EN + jgw] = sc;
        }
    }
}

// ---------------- K_post: warp-local softmax + coalesced A@V + out-proj + LN ----------------
// One block per edge i, 384 threads. Warps 0-7: full softmax for head w (in-warp only).
__global__ void __launch_bounds__(EN, 2)
k_post(const float* __restrict__ ec, const float* __restrict__ ef,
       const float* __restrict__ wo, const float* __restrict__ bo,
       const float* __restrict__ lg, const float* __restrict__ lb,
       float* __restrict__ out) {
    __shared__ float att[NHEAD][EN];   // 12 KB
    __shared__ float upd[HIDN];
    __shared__ float hsum[NHEAD][4];   // attn-sum, cx, cy, cz
    __shared__ float dacc[3];
    __shared__ float red[128];

    int i = blockIdx.x, t = threadIdx.x;
    int lane = t & 31, w = t >> 5;

    // ---- phase 1: warp-local softmax (heads 0..7 on warps 0..7) ----
    if (w < NHEAD) {
        const float* srow = g_scores + ((long)w * EN + i) * EN;
        float s[12];
#pragma unroll
        for (int k = 0; k < 12; k++) s[k] = srow[lane + 32 * k];
        float m = s[0];
#pragma unroll
        for (int k = 1; k < 12; k++) m = fmaxf(m, s[k]);
#pragma unroll
        for (int off = 16; off > 0; off >>= 1)
            m = fmaxf(m, __shfl_xor_sync(0xffffffffu, m, off));
        float tot = 0.f;
#pragma unroll
        for (int k = 0; k < 12; k++) {
            s[k] = __expf(s[k] - m);
            tot += s[k];
        }
#pragma unroll
        for (int off = 16; off > 0; off >>= 1)
            tot += __shfl_xor_sync(0xffffffffu, tot, off);
        float inv = 1.0f / tot;
#pragma unroll
        for (int k = 0; k < 12; k++) att[w][lane + 32 * k] = s[k] * inv;
    }
    __syncthreads();

    // ---- phase 2: A@V (threads 0..127, coalesced over c) + coord sums (128..159) ----
    if (t < 128) {
        int h = t >> 4;
        const float* ar = att[h];
        float acc = 0.f;
#pragma unroll 4
        for (int j = 0; j < EN; j++) acc = fmaf(ar[j], g_v[j * HIDN + t], acc);
        upd[t] = acc;
    } else if (t < 160) {
        int o = t - 128;
        int h = o >> 2, q = o & 3;
        const float* ar = att[h];
        float s2 = 0.f;
        if (q == 0) {
#pragma unroll 4
            for (int j = 0; j < EN; j++) s2 += ar[j];
        } else {
            const float* cp = ec + (q - 1);
#pragma unroll 4
            for (int j = 0; j < EN; j++) s2 = fmaf(ar[j], cp[j * 3], s2);
        }
        hsum[h][q] = s2;
    }
    __syncthreads();

    // ---- phase 3: coord delta ----
    if (t < 3) {
        float d = 0.f;
#pragma unroll
        for (int h = 0; h < NHEAD; h++)
            d += g_gates[h * EN + i] * (hsum[h][0] * ec[i * 3 + t] - hsum[h][1 + t]);
        dacc[t] = d;
    }

    // ---- phase 4: output projection + layernorm ----
    float y = 0.f;
    if (t < 128) {
        y = ef[i * HIDN + t] + bo[t];
#pragma unroll 8
        for (int c = 0; c < HIDN; c++) y = fmaf(upd[c], wo[c * HIDN + t], y);
        red[t] = y;
    }
    __syncthreads();
    for (int s2 = 64; s2 > 0; s2 >>= 1) {
        if (t < s2) red[t] += red[t + s2];
        __syncthreads();
    }
    float mean = red[0] * (1.0f / HIDN);
    __syncthreads();
    float dy = y - mean;
    if (t < 128) red[t] = dy * dy;
    __syncthreads();
    for (int s2 = 64; s2 > 0; s2 >>= 1) {
        if (t < s2) red[t] += red[t + s2];
        __syncthreads();
    }
    float var = red[0] * (1.0f / HIDN);
    float rstd = rsqrtf(var + 1e-5f);
    if (t < 128) out[i * HIDN + t] = dy * rstd * lg[t] + lb[t];
    if (t < 3) out[EN * HIDN + i * 3 + t] = ec[i * 3 + t] + dacc[t] * 0.125f;
}

// ---------------- launcher ----------------
extern "C" void kernel_launch(void* const* d_in, const int* in_sizes, int n_in,
                              void* d_out, int out_size) {
    const float* ef      = (const float*)d_in[0];
    const float* ec      = (const float*)d_in[1];
    const float* mask    = (const float*)d_in[2];
    const float* wq      = (const float*)d_in[3];
    const float* wk      = (const float*)d_in[4];
    const float* wv      = (const float*)d_in[5];
    const float* centers = (const float*)d_in[6];
    const float* widths  = (const float*)d_in[7];
    const float* a_w1    = (const float*)d_in[8];
    const float* a_b1    = (const float*)d_in[9];
    const float* a_w2    = (const float*)d_in[10];
    const float* a_b2    = (const float*)d_in[11];
    const float* a_w3    = (const float*)d_in[12];
    const float* a_b3    = (const float*)d_in[13];
    const float* g_w1    = (const float*)d_in[14];
    const float* g_b1    = (const float*)d_in[15];
    const float* g_w2    = (const float*)d_in[16];
    const float* g_b2    = (const float*)d_in[17];
    const float* wo      = (const float*)d_in[18];
    const float* bo      = (const float*)d_in[19];
    const float* ln_g    = (const float*)d_in[20];
    const float* ln_b    = (const float*)d_in[21];
    float* out = (float*)d_out;

    cudaFuncSetAttribute(k_scores, cudaFuncAttributeMaxDynamicSharedMemorySize,
                         SMEM_BYTES);

    k_pre<<<EN, 256>>>(ef, wq, wk, wv, a_w1, g_w1, g_b1, g_w2, g_b2);
    k_scores<<<dim3(EN / 16, EN / 8), 1024, SMEM_BYTES>>>(
        ec, mask, centers, widths, a_w1, a_b1, a_w2, a_b2, a_w3, a_b3);
    k_post<<<EN, EN>>>(ec, ef, wo, bo, ln_g, ln_b, out);
}

// round 12
// speedup vs baseline: 6.3109x; 1.1837x over previous
#include <cuda_runtime.h>
#include <cuda_fp16.h>
#include <math.h>
#include <stdint.h>

#define EN 384
#define HIDN 128
#define NHEAD 8
#define DHEAD 16
#define NRBF 64

static constexpr int XROW = 272;  // fp16 tile row stride (bytes)
static constexpr int HROW = 320;  // fp16 HPRE row stride (bytes)

// ---- smem byte-offset map (dynamic smem) ----
static constexpr int OFF_X1A  = 0;        // X1 buf A / rbf feats [p][r] fp16
static constexpr int OFF_X1B  = 34816;    // X1 buf B / W1rbf fp16 [r][n]
static constexpr int OFF_W2H  = 69632;    // W2 fp16 [c][n]
static constexpr int OFF_HPREH= 104448;   // HPRE fp16 [p][c], HROW stride
static constexpr int OFF_SRED = 145408;   // [2][512] fp32
static constexpr int OFF_B2S  = 149504;
static constexpr int OFF_W3S  = 150016;
static constexpr int OFF_DISTS= 154112;
static constexpr int OFF_DOTS = 154624;
static constexpr int SMEM_BYTES = 155136;

// ---------------- device scratch ----------------
__device__ float g_v[EN * HIDN];
__device__ __half g_Aqh[NHEAD * EN * HIDN];
__device__ __half g_Akh[NHEAD * EN * HIDN];
__device__ __half g_W2h[HIDN * HIDN];
__device__ float g_gates[NHEAD * EN];
__device__ float g_scores[NHEAD * EN * EN];

__device__ __forceinline__ float siluf(float x) {
    return __fdividef(x, 1.0f + __expf(-x));
}
__device__ __forceinline__ uint32_t f16pair(float x0, float x1) {
    uint32_t u;
    asm("cvt.rn.f16x2.f32 %0, %1, %2;" : "=r"(u) : "f"(x1), "f"(x0));
    return u;
}
__device__ __forceinline__ uint32_t h2tanh(uint32_t y) {
    uint32_t r;
    asm("tanh.approx.f16x2 %0, %1;" : "=r"(r) : "r"(y));
    return r;
}
__device__ __forceinline__ uint32_t h2silu(uint32_t xb) {
    __half2 x = *(__half2*)&xb;
    __half2 y = __hmul2(x, __half2half2(__ushort_as_half(0x3800)));  // 0.5
    uint32_t yb = *(uint32_t*)&y;
    uint32_t tb = h2tanh(yb);
    __half2 t = *(__half2*)&tb;
    __half2 o = __hfma2(y, t, y);
    return *(uint32_t*)&o;
}
__device__ __forceinline__ uint32_t smem_u32(const void* p) {
    uint32_t a;
    asm("{ .reg .u64 t; cvta.to.shared.u64 t, %1; cvt.u32.u64 %0, t; }" : "=r"(a) : "l"(p));
    return a;
}

// ---- HMMA path ----
__device__ __forceinline__ void ldsm_x4(uint32_t* r, uint32_t addr) {
    asm volatile("ldmatrix.sync.aligned.m8n8.x4.shared.b16 {%0,%1,%2,%3}, [%4];"
                 : "=r"(r[0]), "=r"(r[1]), "=r"(r[2]), "=r"(r[3]) : "r"(addr));
}
__device__ __forceinline__ void ldsm_x4t(uint32_t* r, uint32_t addr) {
    asm volatile("ldmatrix.sync.aligned.m8n8.x4.trans.shared.b16 {%0,%1,%2,%3}, [%4];"
                 : "=r"(r[0]), "=r"(r[1]), "=r"(r[2]), "=r"(r[3]) : "r"(addr));
}
__device__ __forceinline__ void mma_f16(float* d, const uint32_t* a, uint32_t b0, uint32_t b1) {
    asm volatile(
        "mma.sync.aligned.m16n8k16.row.col.f32.f16.f16.f32 "
        "{%0,%1,%2,%3}, {%4,%5,%6,%7}, {%8,%9}, {%0,%1,%2,%3};"
        : "+f"(d[0]), "+f"(d[1]), "+f"(d[2]), "+f"(d[3])
        : "r"(a[0]), "r"(a[1]), "r"(a[2]), "r"(a[3]), "r"(b0), "r"(b1));
}

// ---------------- K_pre: qkv + Aq/Ak + gates (+ W2 fp16 convert in extra block) ----------------
__global__ void __launch_bounds__(256, 4)
k_pre(const float* __restrict__ ef, const float* __restrict__ wq,
      const float* __restrict__ wk, const float* __restrict__ wv,
      const float* __restrict__ w1, const float* __restrict__ w2,
      const float* __restrict__ gw1, const float* __restrict__ gb1,
      const float* __restrict__ gw2, const float* __restrict__ gb2) {
    int i = blockIdx.x;
    if (i == EN) {   // W2 fp32 -> fp16 global, once
        for (int idx = threadIdx.x; idx < HIDN * HIDN; idx += 256)
            g_W2h[idx] = __float2half_rn(w2[idx]);
        return;
    }
    __shared__ float row[HIDN], qrow[HIDN], krow[HIDN], vrow[HIDN];
    __shared__ float wpart[4][NHEAD];
    int tid = threadIdx.x;
    int n = tid & 127, half = tid >> 7;
    int lane = tid & 31;
    if (tid < 128) row[tid] = ef[i * HIDN + tid];
    __syncthreads();

    if (half == 0) {
        float qa0 = 0.f, qa1 = 0.f, va0 = 0.f, va1 = 0.f;
#pragma unroll 4
        for (int c = 0; c < HIDN; c += 2) {
            float r0 = row[c], r1 = row[c + 1];
            qa0 = fmaf(r0, wq[c * HIDN + n], qa0);
            qa1 = fmaf(r1, wq[(c + 1) * HIDN + n], qa1);
            va0 = fmaf(r0, wv[c * HIDN + n], va0);
            va1 = fmaf(r1, wv[(c + 1) * HIDN + n], va1);
        }
        float qa = qa0 + qa1, va = va0 + va1;
        qrow[n] = qa; vrow[n] = va;
        g_v[i * HIDN + n] = va;
    } else {
        float ka0 = 0.f, ka1 = 0.f;
#pragma unroll 4
        for (int c = 0; c < HIDN; c += 2) {
            ka0 = fmaf(row[c], wk[c * HIDN + n], ka0);
            ka1 = fmaf(row[c + 1], wk[(c + 1) * HIDN + n], ka1);
        }
        krow[n] = ka0 + ka1;
    }
    __syncthreads();

    if (half == 0) {
#pragma unroll 1
        for (int h = 0; h < NHEAD; h++) {
            float aq = 0.f;
#pragma unroll
            for (int d = 0; d < DHEAD; d++)
                aq = fmaf(qrow[h * DHEAD + d], w1[d * HIDN + n], aq);
            g_Aqh[((long)h * EN + i) * HIDN + n] = __float2half_rn(aq);
        }
    } else {
#pragma unroll 1
        for (int h = 0; h < NHEAD; h++) {
            float ak = 0.f;
#pragma unroll
            for (int d = 0; d < DHEAD; d++)
                ak = fmaf(krow[h * DHEAD + d], w1[(DHEAD + d) * HIDN + n], ak);
            g_Akh[((long)h * EN + i) * HIDN + n] = __float2half_rn(ak);
        }
#pragma unroll 1
        for (int h = 0; h < NHEAD; h++) {
            float acc = gb1[n];
#pragma unroll
            for (int d = 0; d < DHEAD; d++)
                acc = fmaf(vrow[h * DHEAD + d], gw1[d * HIDN + n], acc);
            float val = siluf(acc) * gw2[n];
#pragma unroll
            for (int off = 16; off > 0; off >>= 1)
                val += __shfl_xor_sync(0xffffffffu, val, off);
            if (lane == 0) wpart[(tid >> 5) - 4][h] = val;
        }
    }
    __syncthreads();
    if (tid < NHEAD) {
        float s = wpart[0][tid] + wpart[1][tid] + wpart[2][tid] + wpart[3][tid];
        g_gates[tid * EN + i] = 1.0f / (1.0f + __expf(-(s + gb2[0])));
    }
}

// ---------------- K1: fused pair-MLP -> attention scores ----------------
// 1024 threads, 32 warps. Warp tile 16x32: mb=w&7 (pair rows), nb=w>>3 (channel cols).
__global__ void __launch_bounds__(1024, 1)
k_scores(const float* __restrict__ ec, const float* __restrict__ mask,
         const float* __restrict__ centers, const float* __restrict__ widths,
         const float* __restrict__ w1, const float* __restrict__ b1,
         const float* __restrict__ b2,
         const float* __restrict__ w3, const float* __restrict__ b3) {
    extern __shared__ float smem_f[];
    char* smem_c = (char*)smem_f;
    float* SRED  = (float*)(smem_c + OFF_SRED);
    float* B2S   = (float*)(smem_c + OFF_B2S);
    float* W3S   = (float*)(smem_c + OFF_W3S);
    float* dists = (float*)(smem_c + OFF_DISTS);
    float* dots  = (float*)(smem_c + OFF_DOTS);

    uint32_t sbase = smem_u32(smem_c);

    int tid = threadIdx.x;
    int w = tid >> 5, lane = tid & 31;
    int bi = blockIdx.x, bj = blockIdx.y;

    int p = tid >> 3;
    int lq = tid & 7;
    int ig_p = bi * 16 + (p >> 3);
    int jg_p = bj * 8 + (p & 7);

    // ---- pair geometry ----
    if (tid < 128) {
        int pp = tid;
        int i = bi * 16 + (pp >> 3);
        int j = bj * 8 + (pp & 7);
        float ix = ec[i * 3], iy = ec[i * 3 + 1], iz = ec[i * 3 + 2];
        float jx = ec[j * 3], jy = ec[j * 3 + 1], jz = ec[j * 3 + 2];
        float dx = ix - jx, dy = iy - jy, dz = iz - jz;
        float d = sqrtf(dx * dx + dy * dy + dz * dz) + 1e-8f;
        d = fminf(fmaxf(d, 1e-8f), 1e8f);
        dists[pp] = d;
        float dt = ix * jx + iy * jy + iz * jz;
        dots[pp] = fminf(fmaxf(dt, -1e8f), 1e8f);
    }
    // ---- W2 fp16 from global (vectorized; 2 uint4/thread) ----
    for (int idx = tid; idx < HIDN * HIDN / 8; idx += 1024) {
        int c = idx >> 4, col16 = idx & 15;
        *(uint4*)(smem_c + OFF_W2H + c * XROW + col16 * 16) =
            *(const uint4*)((const char*)g_W2h + idx * 16);
    }
    // ---- W1rbf -> fp16 [r][n] in X1B overlay ----
    for (int idx = tid; idx < NRBF * HIDN; idx += 1024) {
        int r = idx >> 7, n = idx & 127;
        __half hv = __float2half_rn(w1[(2 * DHEAD + r) * HIDN + n]);
        *(unsigned short*)(smem_c + OFF_X1B + r * XROW + n * 2) = __half_as_ushort(hv);
    }
    // ---- b2, w3 ----
    if (tid < 128) B2S[tid] = b2[tid];
    for (int idx = tid; idx < HIDN * NHEAD; idx += 1024) W3S[idx] = w3[idx];
    __syncthreads();

    // ---- rbf features fp16 [p][r] in X1A overlay ----
    for (int idx = tid; idx < 128 * (NRBF / 2); idx += 1024) {
        int pp = idx >> 5, rp = idx & 31;
        int r = 2 * rp;
        float d = dists[pp];
        float t0 = d - centers[r], t1 = d - centers[r + 1];
        float e0 = 0.f, e1 = 0.f;
        if (d <= 10.0f) {
            e0 = __expf(-widths[r] * t0 * t0);
            e1 = __expf(-widths[r + 1] * t1 * t1);
        }
        *(uint32_t*)(smem_c + OFF_X1A + pp * XROW + r * 2) = f16pair(e0, e1);
    }
    __syncthreads();

    // ---- HMMA tiling constants ----
    int mb = w & 7, nb = w >> 3;
    int r16 = lane & 15, rh = lane >> 4;
    uint32_t aTile = (uint32_t)(16 * mb + r16) * XROW + rh * 16;
    uint32_t bW1 = sbase + OFF_X1B + (uint32_t)r16 * XROW + 64 * nb + 16 * rh;
    uint32_t bHi = sbase + OFF_W2H + (uint32_t)r16 * XROW + 64 * nb + 16 * rh;

    // ---- rbf -> hpre via HMMA (K = 64, 4 k-steps) ----
    {
        uint32_t aRbf = sbase + OFF_X1A + aTile;
        float acc[4][4];
#pragma unroll
        for (int ni = 0; ni < 4; ni++)
#pragma unroll
            for (int e = 0; e < 4; e++) acc[ni][e] = 0.f;
#pragma unroll
        for (int kk = 0; kk < 4; kk++) {
            uint32_t ah[4], bh[2][4];
            ldsm_x4(ah, aRbf + kk * 32);
            ldsm_x4t(bh[0], bW1 + kk * 16 * XROW);
            ldsm_x4t(bh[1], bW1 + kk * 16 * XROW + 32);
#pragma unroll
            for (int bx = 0; bx < 2; bx++)
#pragma unroll
                for (int hf = 0; hf < 2; hf++) {
                    int ni = 2 * bx + hf;
                    mma_f16(acc[ni], ah, bh[bx][2 * hf], bh[bx][2 * hf + 1]);
                }
        }
        // epilogue: + dot*w1_dot + b1, pack fp16 -> HPREH
        int r0 = 16 * mb + (lane >> 2);
        float dp0 = dots[r0], dp1 = dots[r0 + 8];
#pragma unroll
        for (int ni = 0; ni < 4; ni++) {
            int c0 = 32 * nb + 8 * ni + 2 * (lane & 3);
            float wd0 = __ldg(w1 + 96 * HIDN + c0), wd1 = __ldg(w1 + 96 * HIDN + c0 + 1);
            float b10 = __ldg(b1 + c0), b11 = __ldg(b1 + c0 + 1);
            float v00 = acc[ni][0] + dp0 * wd0 + b10;
            float v01 = acc[ni][1] + dp0 * wd1 + b11;
            float v10 = acc[ni][2] + dp1 * wd0 + b10;
            float v11 = acc[ni][3] + dp1 * wd1 + b11;
            *(uint32_t*)(smem_c + OFF_HPREH + r0 * HROW + c0 * 2) = f16pair(v00, v01);
            *(uint32_t*)(smem_c + OFF_HPREH + (r0 + 8) * HROW + c0 * 2) = f16pair(v10, v11);
        }
    }
    __syncthreads();   // HPREH done; X1A/X1B overlays dead -> X1 buffers usable

    uint32_t aTileX = aTile;   // same geometry for X1
    float mask_v = 0.f;
    int igw = 0, jgw = 0;
    if (tid < 128) {
        igw = bi * 16 + (tid >> 3);
        jgw = bj * 8 + (tid & 7);
        mask_v = __ldg(mask + (long)igw * EN + jgw);
    }

    const char* hpb = smem_c + OFF_HPREH + p * HROW;
    auto build_x1 = [&](int h, int sel) {
        char* dst = smem_c + (sel ? OFF_X1B : OFF_X1A) + p * XROW;
        const __half* aqp = g_Aqh + ((long)(h * EN + ig_p)) * HIDN;
        const __half* akp = g_Akh + ((long)(h * EN + jg_p)) * HIDN;
#pragma unroll
        for (int q = 0; q < 4; q++) {
            int c = lq * 4 + 32 * q;
            uint2 av = __ldg((const uint2*)(aqp + c));
            uint2 kv = __ldg((const uint2*)(akp + c));
            uint2 hv = *(const uint2*)(hpb + c * 2);
            __half2 x0 = __hadd2(__hadd2(*(__half2*)&hv.x, *(__half2*)&av.x),
                                 *(__half2*)&kv.x);
            __half2 x1 = __hadd2(__hadd2(*(__half2*)&hv.y, *(__half2*)&av.y),
                                 *(__half2*)&kv.y);
            uint32_t o0 = h2silu(*(uint32_t*)&x0);
            uint32_t o1 = h2silu(*(uint32_t*)&x1);
            *(uint2*)(dst + c * 2) = make_uint2(o0, o1);
        }
    };

    build_x1(0, 0);
    __syncthreads();

    for (int h = 0; h < NHEAD; h++) {
        int sel = h & 1;
        uint32_t aBuf = sbase + (sel ? OFF_X1B : OFF_X1A) + aTileX;
        float acc[4][4];
#pragma unroll
        for (int ni = 0; ni < 4; ni++)
#pragma unroll
            for (int e = 0; e < 4; e++) acc[ni][e] = 0.f;

#pragma unroll
        for (int kk = 0; kk < 8; kk++) {
            uint32_t kab = (uint32_t)kk * 32;
            uint32_t kbb = (uint32_t)kk * 16 * XROW;
            uint32_t ah[4], bh[2][4];
            ldsm_x4(ah, aBuf + kab);
            ldsm_x4t(bh[0], bHi + kbb);
            ldsm_x4t(bh[1], bHi + kbb + 32);
#pragma unroll
            for (int bx = 0; bx < 2; bx++)
#pragma unroll
                for (int hf = 0; hf < 2; hf++) {
                    int ni = 2 * bx + hf;
                    mma_f16(acc[ni], ah, bh[bx][2 * hf], bh[bx][2 * hf + 1]);
                }
        }

        // ---- epilogue: packed fp16 silu + w3 reduce -> SRED[sel] ----
        {
            float* SR = SRED + sel * 512;
            int colq = 2 * (lane & 3);
            float s0 = 0.f, s1 = 0.f;
#pragma unroll
            for (int ni = 0; ni < 4; ni++) {
                int col = 32 * nb + 8 * ni + colq;
                float b2a = B2S[col], b2b = B2S[col + 1];
                float w3a = W3S[col * NHEAD + h], w3b = W3S[(col + 1) * NHEAD + h];
                uint32_t u0 = h2silu(f16pair(acc[ni][0] + b2a, acc[ni][1] + b2b));
                float2 f0 = __half22float2(*(__half2*)&u0);
                s0 += f0.x * w3a + f0.y * w3b;
                uint32_t u1 = h2silu(f16pair(acc[ni][2] + b2a, acc[ni][3] + b2b));
                float2 f1 = __half22float2(*(__half2*)&u1);
                s1 += f1.x * w3a + f1.y * w3b;
            }
#pragma unroll
            for (int off = 1; off < 4; off <<= 1) {
                s0 += __shfl_xor_sync(0xffffffffu, s0, off);
                s1 += __shfl_xor_sync(0xffffffffu, s1, off);
            }
            if ((lane & 3) == 0) {
                int r0 = 16 * mb + (lane >> 2);
                SR[nb * 128 + r0] = s0;
                SR[nb * 128 + r0 + 8] = s1;
            }
        }

        if (h < NHEAD - 1) build_x1(h + 1, sel ^ 1);

        __syncthreads();

        if (tid < 128) {
            float* SR = SRED + sel * 512;
            float tot = SR[tid] + SR[128 + tid] + SR[256 + tid] + SR[384 + tid];
            float sc = tot + b3[h] + mask_v;
            sc = fminf(fmaxf(sc, -1e9f), 1e9f);
            g_scores[((long)h * EN + igw) * EN + jgw] = sc;
        }
    }
}

// ---------------- K_post: warp-local softmax + coalesced A@V + out-proj + LN ----------------
__global__ void __launch_bounds__(EN, 2)
k_post(const float* __restrict__ ec, const float* __restrict__ ef,
       const float* __restrict__ wo, const float* __restrict__ bo,
       const float* __restrict__ lg, const float* __restrict__ lb,
       float* __restrict__ out) {
    __shared__ float att[NHEAD][EN];
    __shared__ float upd[HIDN];
    __shared__ float hsum[NHEAD][4];
    __shared__ float dacc[3];
    __shared__ float red[128];

    int i = blockIdx.x, t = threadIdx.x;
    int lane = t & 31, w = t >> 5;

    if (w < NHEAD) {
        const float* srow = g_scores + ((long)w * EN + i) * EN;
        float s[12];
#pragma unroll
        for (int k = 0; k < 12; k++) s[k] = srow[lane + 32 * k];
        float m = s[0];
#pragma unroll
        for (int k = 1; k < 12; k++) m = fmaxf(m, s[k]);
#pragma unroll
        for (int off = 16; off > 0; off >>= 1)
            m = fmaxf(m, __shfl_xor_sync(0xffffffffu, m, off));
        float tot = 0.f;
#pragma unroll
        for (int k = 0; k < 12; k++) {
            s[k] = __expf(s[k] - m);
            tot += s[k];
        }
#pragma unroll
        for (int off = 16; off > 0; off >>= 1)
            tot += __shfl_xor_sync(0xffffffffu, tot, off);
        float inv = 1.0f / tot;
#pragma unroll
        for (int k = 0; k < 12; k++) att[w][lane + 32 * k] = s[k] * inv;
    }
    __syncthreads();

    if (t < 128) {
        int h = t >> 4;
        const float* ar = att[h];
        float acc = 0.f;
#pragma unroll 4
        for (int j = 0; j < EN; j++) acc = fmaf(ar[j], g_v[j * HIDN + t], acc);
        upd[t] = acc;
    } else if (t < 160) {
        int o = t - 128;
        int h = o >> 2, q = o & 3;
        const float* ar = att[h];
        float s2 = 0.f;
        if (q == 0) {
#pragma unroll 4
            for (int j = 0; j < EN; j++) s2 += ar[j];
        } else {
            const float* cp = ec + (q - 1);
#pragma unroll 4
            for (int j = 0; j < EN; j++) s2 = fmaf(ar[j], cp[j * 3], s2);
        }
        hsum[h][q] = s2;
    }
    __syncthreads();

    if (t < 3) {
        float d = 0.f;
#pragma unroll
        for (int h = 0; h < NHEAD; h++)
            d += g_gates[h * EN + i] * (hsum[h][0] * ec[i * 3 + t] - hsum[h][1 + t]);
        dacc[t] = d;
    }

    float y = 0.f;
    if (t < 128) {
        y = ef[i * HIDN + t] + bo[t];
#pragma unroll 8
        for (int c = 0; c < HIDN; c++) y = fmaf(upd[c], wo[c * HIDN + t], y);
        red[t] = y;
    }
    __syncthreads();
    for (int s2 = 64; s2 > 0; s2 >>= 1) {
        if (t < s2) red[t] += red[t + s2];
        __syncthreads();
    }
    float mean = red[0] * (1.0f / HIDN);
    __syncthreads();
    float dy = y - mean;
    if (t < 128) red[t] = dy * dy;
    __syncthreads();
    for (int s2 = 64; s2 > 0; s2 >>= 1) {
        if (t < s2) red[t] += red[t + s2];
        __syncthreads();
    }
    float var = red[0] * (1.0f / HIDN);
    float rstd = rsqrtf(var + 1e-5f);
    if (t < 128) out[i * HIDN + t] = dy * rstd * lg[t] + lb[t];
    if (t < 3) out[EN * HIDN + i * 3 + t] = ec[i * 3 + t] + dacc[t] * 0.125f;
}

// ---------------- launcher ----------------
extern "C" void kernel_launch(void* const* d_in, const int* in_sizes, int n_in,
                              void* d_out, int out_size) {
    const float* ef      = (const float*)d_in[0];
    const float* ec      = (const float*)d_in[1];
    const float* mask    = (const float*)d_in[2];
    const float* wq      = (const float*)d_in[3];
    const float* wk      = (const float*)d_in[4];
    const float* wv      = (const float*)d_in[5];
    const float* centers = (const float*)d_in[6];
    const float* widths  = (const float*)d_in[7];
    const float* a_w1    = (const float*)d_in[8];
    const float* a_b1    = (const float*)d_in[9];
    const float* a_w2    = (const float*)d_in[10];
    const float* a_b2    = (const float*)d_in[11];
    const float* a_w3    = (const float*)d_in[12];
    const float* a_b3    = (const float*)d_in[13];
    const float* g_w1    = (const float*)d_in[14];
    const float* g_b1    = (const float*)d_in[15];
    const float* g_w2    = (const float*)d_in[16];
    const float* g_b2    = (const float*)d_in[17];
    const float* wo      = (const float*)d_in[18];
    const float* bo      = (const float*)d_in[19];
    const float* ln_g    = (const float*)d_in[20];
    const float* ln_b    = (const float*)d_in[21];
    float* out = (float*)d_out;

    cudaFuncSetAttribute(k_scores, cudaFuncAttributeMaxDynamicSharedMemorySize,
                         SMEM_BYTES);

    k_pre<<<EN + 1, 256>>>(ef, wq, wk, wv, a_w1, a_w2, g_w1, g_b1, g_w2, g_b2);
    k_scores<<<dim3(EN / 16, EN / 8), 1024, SMEM_BYTES>>>(
        ec, mask, centers, widths, a_w1, a_b1, a_b2, a_w3, a_b3);
    k_post<<<EN, EN>>>(ec, ef, wo, bo, ln_g, ln_b, out);
}